// round 6
// baseline (speedup 1.0000x reference)
#include <cuda_runtime.h>
#include <cuda_bf16.h>
#include <cstdint>

// ---------------- problem constants ----------------
#define NA 500000
static const int H_DEG_CNT[7] = {20000, 80000, 150000, 150000, 75000, 20000, 5000};
static const int H_DEG_OFF[8] = {0, 20000, 100000, 250000, 400000, 475000, 495000, 500000};

// ---------------- scratch (device globals; no allocation allowed) ----------------
__device__ float    g_h1[(size_t)NA * 64];
__device__ float    g_h2[(size_t)NA * 64];
__device__ float    g_gsum[1024 * 128];
__device__ unsigned g_gmax[1024 * 128];

// ---------------- helpers ----------------
__device__ __forceinline__ unsigned enc_f(float f) {
    unsigned u = __float_as_uint(f);
    return (u >> 31) ? ~u : (u | 0x80000000u);
}
__device__ __forceinline__ float dec_f(unsigned u) {
    return (u >> 31) ? __uint_as_float(u & 0x7FFFFFFFu) : __uint_as_float(~u);
}
__device__ __forceinline__ float tanh_fast(float x) {
    float y;
    asm("tanh.approx.f32 %0, %1;" : "=f"(y) : "f"(x));
    return y;
}
#define COMP(v, i) ((i) == 0 ? (v).x : (i) == 1 ? (v).y : (i) == 2 ? (v).z : (v).w)

// bf16x2 pack from two floats (round-to-nearest)
__device__ __forceinline__ uint32_t bf2_hi(float a, float b, float& ra, float& rb) {
    __nv_bfloat16 ha = __float2bfloat16_rn(a);
    __nv_bfloat16 hb = __float2bfloat16_rn(b);
    ra = a - __bfloat162float(ha);
    rb = b - __bfloat162float(hb);
    __nv_bfloat162 p = __halves2bfloat162(ha, hb);
    return *(uint32_t*)&p;
}
__device__ __forceinline__ uint32_t bf2(float a, float b) {
    __nv_bfloat162 p = __halves2bfloat162(__float2bfloat16_rn(a), __float2bfloat16_rn(b));
    return *(uint32_t*)&p;
}

// mma.sync m16n8k16 bf16 -> f32 (sm_80+ baseline PTX; HMMA on sm_103)
#define MMA_BF16(c0,c1,c2,c3,a0,a1,a2,a3,b0,b1) \
    asm volatile("mma.sync.aligned.m16n8k16.row.col.f32.bf16.bf16.f32 " \
        "{%0,%1,%2,%3}, {%4,%5,%6,%7}, {%8,%9}, {%0,%1,%2,%3};" \
        : "+f"(c0), "+f"(c1), "+f"(c2), "+f"(c3) \
        : "r"(a0), "r"(a1), "r"(a2), "r"(a3), "r"(b0), "r"(b1))

// shared host/device smem-size formula for the gc MMA kernel
__host__ __device__ constexpr int gc_kp(int F) { return (F == 75) ? 80 : 64; }
__host__ __device__ constexpr int gc_kt(int F, int D) { return (D > 0 ? 2 : 1) * gc_kp(F); }
__host__ __device__ constexpr int gc_rsw(int F, int D) { return gc_kt(F, D) / 2 + 4; }
__host__ __device__ constexpr int gc_smem_bytes(int F, int D) {
    int sz = 64 * gc_rsw(F, D) * 4;           // one bf16 tile (64 rows x KT, padded)
    int dd = (D > 0) ? D : 1;
    return 4 * sz + 64 * dd * 4 + 2 * 64 * 4; // Wh,Wl,Xh,Xl + adj + sc,sh
}

// ================= graph conv via mma.sync bf16 hi/lo (+bias +tanh +bn1) =============
// Block = 64 atoms, 128 threads (4 warps x 16 rows x 64 cols).
// X = [self | neighbor-sum] bf16 hi/lo in SMEM; W^T bf16 hi/lo in SMEM.
// acc = Xh@Wh + Xh@Wl + Xl@Wh (3-term split ~ fp32 accuracy).
template <int F, int D>
__global__ __launch_bounds__(128) void gc_mma_kernel(
    const float* __restrict__ feat,
    const int* __restrict__ adj,
    const float* __restrict__ Ws,   // [F][64] slice for this degree
    const float* __restrict__ Wn,   // [F][64] slice (unused if D==0)
    const float* __restrict__ bias, // [64]
    const float* __restrict__ bn_g, const float* __restrict__ bn_b,
    const float* __restrict__ bn_m, const float* __restrict__ bn_v,
    float* __restrict__ out,
    int atom0, int cnt)
{
    constexpr int KP  = gc_kp(F);
    constexpr int KT  = gc_kt(F, D);
    constexpr int RSW = gc_rsw(F, D);   // 32-bit words per row (bank-safe stride)
    constexpr int RS2 = 2 * RSW;        // bf16 elems per row
    constexpr int DD  = (D > 0) ? D : 1;
    constexpr int SZ  = 64 * RSW * 4;   // bytes per tile

    extern __shared__ char smem[];
    __nv_bfloat16* s_wh = (__nv_bfloat16*)(smem);
    __nv_bfloat16* s_wl = (__nv_bfloat16*)(smem + SZ);
    __nv_bfloat16* s_xh = (__nv_bfloat16*)(smem + 2 * SZ);
    __nv_bfloat16* s_xl = (__nv_bfloat16*)(smem + 3 * SZ);
    int*   s_adj = (int*)(smem + 4 * SZ);
    float* s_sc  = (float*)(smem + 4 * SZ + 64 * DD * 4);
    float* s_sh  = s_sc + 64;

    const int t = threadIdx.x;
    const int lane = t & 31;
    const int warp = t >> 5;
    const int abase = blockIdx.x * 64;
    const int nat = min(64, cnt - abase);

    // ---- bn scale/shift ----
    if (t < 64) {
        float sc = bn_g[t] * rsqrtf(bn_v[t] + 1e-3f);
        s_sc[t] = sc;
        s_sh[t] = bn_b[t] - bn_m[t] * sc;
    }

    // ---- stage W^T (bf16 hi/lo): s_w[n][k] = W[k][n] ----
    for (int e = t; e < 64 * KT; e += 128) {
        int n = e & 63, k = e >> 6;
        float w = 0.f;
        if (k < KP) { if (k < F) w = Ws[k * 64 + n]; }
        else        { int kk = k - KP; if (kk < F) w = Wn[kk * 64 + n]; }
        __nv_bfloat16 h = __float2bfloat16_rn(w);
        s_wh[n * RS2 + k] = h;
        s_wl[n * RS2 + k] = __float2bfloat16_rn(w - __bfloat162float(h));
    }

    // ---- adjacency ----
    if (D > 0)
        for (int u = t; u < nat * D; u += 128)
            s_adj[u] = adj[abase * D + u];
    __syncthreads();

    // ---- gather X = [self | neighbor-sum] (bf16 hi/lo) ----
    for (int u = t; u < nat * KT; u += 128) {
        int a = u / KT, k = u - a * KT;
        float v = 0.f;
        if (k < KP) {
            if (k < F) v = feat[(size_t)(atom0 + abase + a) * F + k];
        } else {
            int kk = k - KP;
            if (kk < F) {
                #pragma unroll
                for (int m = 0; m < DD; m++)
                    v += feat[(size_t)s_adj[a * D + m] * F + kk];
            }
        }
        __nv_bfloat16 h = __float2bfloat16_rn(v);
        s_xh[a * RS2 + k] = h;
        s_xl[a * RS2 + k] = __float2bfloat16_rn(v - __bfloat162float(h));
    }
    __syncthreads();

    // ---- compute: warp handles rows [16*warp, 16*warp+16), all 64 cols ----
    const int g   = lane >> 2;   // 0..7
    const int tIG = lane & 3;    // 0..3
    const int row0 = warp * 16 + g;
    const int row1 = row0 + 8;

    const uint32_t* xh32 = (const uint32_t*)s_xh;
    const uint32_t* xl32 = (const uint32_t*)s_xl;
    const uint32_t* wh32 = (const uint32_t*)s_wh;
    const uint32_t* wl32 = (const uint32_t*)s_wl;

    float c[8][4];
    #pragma unroll
    for (int nt = 0; nt < 8; nt++) {
        float2 bb = *(const float2*)(bias + nt * 8 + tIG * 2);
        c[nt][0] = bb.x; c[nt][1] = bb.y; c[nt][2] = bb.x; c[nt][3] = bb.y;
    }

    #pragma unroll 1
    for (int ks = 0; ks < KT / 16; ks++) {
        const int koff = ks * 8 + tIG;
        uint32_t a0h = xh32[row0 * RSW + koff];
        uint32_t a1h = xh32[row1 * RSW + koff];
        uint32_t a2h = xh32[row0 * RSW + koff + 4];
        uint32_t a3h = xh32[row1 * RSW + koff + 4];
        uint32_t a0l = xl32[row0 * RSW + koff];
        uint32_t a1l = xl32[row1 * RSW + koff];
        uint32_t a2l = xl32[row0 * RSW + koff + 4];
        uint32_t a3l = xl32[row1 * RSW + koff + 4];
        #pragma unroll
        for (int nt = 0; nt < 8; nt++) {
            const int nrow = nt * 8 + g;
            uint32_t b0h = wh32[nrow * RSW + koff];
            uint32_t b1h = wh32[nrow * RSW + koff + 4];
            uint32_t b0l = wl32[nrow * RSW + koff];
            uint32_t b1l = wl32[nrow * RSW + koff + 4];
            MMA_BF16(c[nt][0], c[nt][1], c[nt][2], c[nt][3],
                     a0h, a1h, a2h, a3h, b0h, b1h);
            MMA_BF16(c[nt][0], c[nt][1], c[nt][2], c[nt][3],
                     a0h, a1h, a2h, a3h, b0l, b1l);
            MMA_BF16(c[nt][0], c[nt][1], c[nt][2], c[nt][3],
                     a0l, a1l, a2l, a3l, b0h, b1h);
        }
    }

    // ---- epilogue: tanh + bn + store ----
    #pragma unroll
    for (int nt = 0; nt < 8; nt++) {
        const int n = nt * 8 + tIG * 2;
        float2 sc2 = *(const float2*)(s_sc + n);
        float2 sh2 = *(const float2*)(s_sh + n);
        if (row0 < nat) {
            float2 o;
            o.x = sc2.x * tanh_fast(c[nt][0]) + sh2.x;
            o.y = sc2.y * tanh_fast(c[nt][1]) + sh2.y;
            *(float2*)(out + (size_t)(atom0 + abase + row0) * 64 + n) = o;
        }
        if (row1 < nat) {
            float2 o;
            o.x = sc2.x * tanh_fast(c[nt][2]) + sh2.x;
            o.y = sc2.y * tanh_fast(c[nt][3]) + sh2.y;
            *(float2*)(out + (size_t)(atom0 + abase + row1) * 64 + n) = o;
        }
    }
}

// ================= graph pool (float4) =================
__global__ __launch_bounds__(256) void pool_kernel(
    const float4* __restrict__ in, float4* __restrict__ out,
    const int* __restrict__ a1, const int* __restrict__ a2,
    const int* __restrict__ a3, const int* __restrict__ a4,
    const int* __restrict__ a5, const int* __restrict__ a6)
{
    int idx  = blockIdx.x * 256 + threadIdx.x;  // NA*16 total
    int atom = idx >> 4;
    int q    = idx & 15;
    float4 v = in[idx];

    if (atom >= 20000) {
        const int* ap; int d, li;
        if      (atom < 100000) { d = 1; ap = a1; li = atom - 20000;  }
        else if (atom < 250000) { d = 2; ap = a2; li = atom - 100000; }
        else if (atom < 400000) { d = 3; ap = a3; li = atom - 250000; }
        else if (atom < 475000) { d = 4; ap = a4; li = atom - 400000; }
        else if (atom < 495000) { d = 5; ap = a5; li = atom - 475000; }
        else                    { d = 6; ap = a6; li = atom - 495000; }
        for (int m = 0; m < d; m++) {
            int nb = ap[li * d + m];
            float4 u = in[nb * 16 + q];
            v.x = fmaxf(v.x, u.x); v.y = fmaxf(v.y, u.y);
            v.z = fmaxf(v.z, u.z); v.w = fmaxf(v.w, u.w);
        }
    }
    out[idx] = v;
}

// ================= dense1 [64]->[128] + tanh + bn3, fused segment gather ==============
__global__ __launch_bounds__(256) void dense1_gather_kernel(
    const float* __restrict__ in,
    const int* __restrict__ membership,
    const float* __restrict__ W,   // [64][128]
    const float* __restrict__ b,   // [128]
    const float* __restrict__ bn_g, const float* __restrict__ bn_b,
    const float* __restrict__ bn_m, const float* __restrict__ bn_v,
    float* __restrict__ gsum, unsigned* __restrict__ gmax,
    int cnt)
{
    __shared__ float s_in[64][68];
    __shared__ int   s_mem[64];

    const int t    = threadIdx.x;
    const int ablk = blockIdx.x * 64;
    const int nat  = min(64, cnt - ablk);

    for (int idx = t; idx < nat * 16; idx += 256) {
        int a = idx >> 4, q = idx & 15;
        *(float4*)&s_in[a][q * 4] = *(const float4*)(in + (size_t)(ablk + a) * 64 + q * 4);
    }
    if (t < nat) s_mem[t] = membership[ablk + t];
    __syncthreads();

    const int j   = (t & 31) * 4;
    const int grp = t >> 5;

    float acc[8][4];
    {
        float4 b4 = *(const float4*)(b + j);
        #pragma unroll
        for (int r = 0; r < 8; r++) {
            acc[r][0] = b4.x; acc[r][1] = b4.y; acc[r][2] = b4.z; acc[r][3] = b4.w;
        }
    }

    for (int k0 = 0; k0 < 64; k0 += 4) {
        float4 w[4];
        #pragma unroll
        for (int kk = 0; kk < 4; kk++)
            w[kk] = *(const float4*)(W + (k0 + kk) * 128 + j);
        #pragma unroll
        for (int r = 0; r < 8; r++) {
            float4 xv = *(const float4*)&s_in[grp * 8 + r][k0];
            #pragma unroll
            for (int kk = 0; kk < 4; kk++) {
                float x = COMP(xv, kk);
                acc[r][0] = fmaf(x, w[kk].x, acc[r][0]);
                acc[r][1] = fmaf(x, w[kk].y, acc[r][1]);
                acc[r][2] = fmaf(x, w[kk].z, acc[r][2]);
                acc[r][3] = fmaf(x, w[kk].w, acc[r][3]);
            }
        }
    }

    float4 g4 = *(const float4*)(bn_g + j);
    float4 v4 = *(const float4*)(bn_v + j);
    float4 bb4 = *(const float4*)(bn_b + j);
    float4 m4 = *(const float4*)(bn_m + j);
    float sc[4], sh[4];
    #pragma unroll
    for (int c = 0; c < 4; c++) {
        sc[c] = COMP(g4, c) * rsqrtf(COMP(v4, c) + 1e-3f);
        sh[c] = COMP(bb4, c) - COMP(m4, c) * sc[c];
    }

    #pragma unroll
    for (int r = 0; r < 8; r++) {
        int a = grp * 8 + r;
        if (a < nat) {
            int m = s_mem[a];
            #pragma unroll
            for (int c = 0; c < 4; c++) {
                float v = sc[c] * tanh_fast(acc[r][c]) + sh[c];
                atomicAdd(&gsum[m * 128 + j + c], v);
                atomicMax(&gmax[m * 128 + j + c], enc_f(v));
            }
        }
    }
}

// ================= head =================
__global__ void head_kernel(const float* __restrict__ gsum, const unsigned* __restrict__ gmax,
                            const float* __restrict__ d2W, const float* __restrict__ d2b,
                            const float* __restrict__ d3W, const float* __restrict__ d3b,
                            float* __restrict__ out)
{
    __shared__ float sg[256];
    __shared__ float sred[64];
    const int row = blockIdx.x;
    const int t   = threadIdx.x;  // 64 threads

    for (int k = t; k < 256; k += 64) {
        float v = (k < 128) ? gsum[row * 128 + k] : dec_f(gmax[row * 128 + (k - 128)]);
        sg[k] = tanh_fast(v);
    }
    __syncthreads();

    float acc = d2b[t];
    for (int k = 0; k < 256; k++)
        acc = fmaf(sg[k], d2W[k * 64 + t], acc);
    float s = 1.f / (1.f + expf(-acc));

    sred[t] = s * d3W[t];
    __syncthreads();
    if (t < 32) {
        float x = sred[t] + sred[t + 32];
        #pragma unroll
        for (int off = 16; off; off >>= 1)
            x += __shfl_down_sync(0xffffffffu, x, off);
        if (t == 0) out[row] = x + d3b[0];
    }
}

// ================= dispatch helpers =================
template <int F, int D>
static void gc_launch_one(const float* feat, const int* adj, const float* Ws,
                          const float* Wn, const float* b, const float* bg,
                          const float* bb, const float* bm, const float* bv,
                          float* out, int atom0, int cnt)
{
    constexpr int SZ = gc_smem_bytes(F, D);
    static bool attr_set = false;
    if (!attr_set) {
        cudaFuncSetAttribute(gc_mma_kernel<F, D>,
                             cudaFuncAttributeMaxDynamicSharedMemorySize, SZ);
        attr_set = true;
    }
    gc_mma_kernel<F, D><<<(cnt + 63) / 64, 128, SZ>>>(
        feat, adj, Ws, Wn, b, bg, bb, bm, bv, out, atom0, cnt);
}

template <int F>
static void launch_gc(int d, const float* feat, const int* adj,
                      const float* Ws, const float* Wn, const float* bias,
                      const float* bg, const float* bb, const float* bm, const float* bv,
                      float* out, int atom0, int cnt)
{
    switch (d) {
    case 0: gc_launch_one<F,0>(feat,adj,Ws,Wn,bias,bg,bb,bm,bv,out,atom0,cnt); break;
    case 1: gc_launch_one<F,1>(feat,adj,Ws,Wn,bias,bg,bb,bm,bv,out,atom0,cnt); break;
    case 2: gc_launch_one<F,2>(feat,adj,Ws,Wn,bias,bg,bb,bm,bv,out,atom0,cnt); break;
    case 3: gc_launch_one<F,3>(feat,adj,Ws,Wn,bias,bg,bb,bm,bv,out,atom0,cnt); break;
    case 4: gc_launch_one<F,4>(feat,adj,Ws,Wn,bias,bg,bb,bm,bv,out,atom0,cnt); break;
    case 5: gc_launch_one<F,5>(feat,adj,Ws,Wn,bias,bg,bb,bm,bv,out,atom0,cnt); break;
    case 6: gc_launch_one<F,6>(feat,adj,Ws,Wn,bias,bg,bb,bm,bv,out,atom0,cnt); break;
    }
}

// ================= launch =================
extern "C" void kernel_launch(void* const* d_in, const int* in_sizes, int n_in,
                              void* d_out, int out_size)
{
    const float* feat       = (const float*)d_in[0];
    const int*   membership = (const int*)d_in[1];
    const int*   adj[6]     = {(const int*)d_in[2], (const int*)d_in[3], (const int*)d_in[4],
                               (const int*)d_in[5], (const int*)d_in[6], (const int*)d_in[7]};
    const float* gc1_Wn = (const float*)d_in[8];
    const float* gc1_Ws = (const float*)d_in[9];
    const float* gc1_b  = (const float*)d_in[10];
    const float* gc2_Wn = (const float*)d_in[11];
    const float* gc2_Ws = (const float*)d_in[12];
    const float* gc2_b  = (const float*)d_in[13];
    const float* bn1g = (const float*)d_in[14];
    const float* bn1b = (const float*)d_in[15];
    const float* bn1m = (const float*)d_in[16];
    const float* bn1v = (const float*)d_in[17];
    const float* bn3g = (const float*)d_in[18];
    const float* bn3b = (const float*)d_in[19];
    const float* bn3m = (const float*)d_in[20];
    const float* bn3v = (const float*)d_in[21];
    const float* d1W = (const float*)d_in[22];
    const float* d1b = (const float*)d_in[23];
    const float* d2W = (const float*)d_in[24];
    const float* d2b = (const float*)d_in[25];
    const float* d3W = (const float*)d_in[26];
    const float* d3b = (const float*)d_in[27];

    float *h1, *h2, *gsum; unsigned* gmax;
    cudaGetSymbolAddress((void**)&h1, g_h1);
    cudaGetSymbolAddress((void**)&h2, g_h2);
    cudaGetSymbolAddress((void**)&gsum, g_gsum);
    cudaGetSymbolAddress((void**)&gmax, g_gmax);

    // ---- gc1 (+tanh +bn1): feat[NA,75] -> h1[NA,64]
    for (int d = 0; d <= 6; d++) {
        launch_gc<75>(d, feat, d ? adj[d - 1] : nullptr,
                      gc1_Ws + d * 75 * 64, d ? gc1_Wn + (d - 1) * 75 * 64 : nullptr,
                      gc1_b + d * 64, bn1g, bn1b, bn1m, bn1v,
                      h1, H_DEG_OFF[d], H_DEG_CNT[d]);
    }

    // ---- pool1: h1 -> h2
    pool_kernel<<<NA * 16 / 256, 256>>>((const float4*)h1, (float4*)h2,
                                        adj[0], adj[1], adj[2], adj[3], adj[4], adj[5]);

    // ---- gc2 (+tanh +bn1): h2[NA,64] -> h1[NA,64]
    for (int d = 0; d <= 6; d++) {
        launch_gc<64>(d, h2, d ? adj[d - 1] : nullptr,
                      gc2_Ws + d * 64 * 64, d ? gc2_Wn + (d - 1) * 64 * 64 : nullptr,
                      gc2_b + d * 64, bn1g, bn1b, bn1m, bn1v,
                      h1, H_DEG_OFF[d], H_DEG_CNT[d]);
    }

    // ---- pool2: h1 -> h2
    pool_kernel<<<NA * 16 / 256, 256>>>((const float4*)h1, (float4*)h2,
                                        adj[0], adj[1], adj[2], adj[3], adj[4], adj[5]);

    // ---- zero gather accumulators, then fused dense1 + segment gather
    cudaMemsetAsync(gsum, 0, 1024 * 128 * sizeof(float));
    cudaMemsetAsync(gmax, 0, 1024 * 128 * sizeof(unsigned));
    dense1_gather_kernel<<<(NA + 63) / 64, 256>>>(h2, membership, d1W, d1b,
                                                  bn3g, bn3b, bn3m, bn3v,
                                                  gsum, gmax, NA);

    // ---- head
    head_kernel<<<1024, 64>>>(gsum, gmax, d2W, d2b, d3W, d3b, (float*)d_out);
}

// round 7
// speedup vs baseline: 2.0590x; 2.0590x over previous
#include <cuda_runtime.h>
#include <cuda_bf16.h>
#include <cstdint>

// ---------------- problem constants ----------------
#define NA 500000
static const int H_DEG_CNT[7] = {20000, 80000, 150000, 150000, 75000, 20000, 5000};
static const int H_DEG_OFF[8] = {0, 20000, 100000, 250000, 400000, 475000, 495000, 500000};

// ---------------- scratch (device globals; no allocation allowed) ----------------
__device__ float    g_h1[(size_t)NA * 64];
__device__ float    g_h2[(size_t)NA * 64];
__device__ float    g_gsum[1024 * 128];
__device__ unsigned g_gmax[1024 * 128];

// ---------------- helpers ----------------
__device__ __forceinline__ unsigned enc_f(float f) {
    unsigned u = __float_as_uint(f);
    return (u >> 31) ? ~u : (u | 0x80000000u);
}
__device__ __forceinline__ float dec_f(unsigned u) {
    return (u >> 31) ? __uint_as_float(u & 0x7FFFFFFFu) : __uint_as_float(~u);
}
__device__ __forceinline__ float tanh_fast(float x) {
    float y;
    asm("tanh.approx.f32 %0, %1;" : "=f"(y) : "f"(x));
    return y;
}

// mma.sync m16n8k16 bf16 -> f32 (sm_80+ baseline PTX; HMMA on sm_103)
#define MMA_BF16(c0,c1,c2,c3,a0,a1,a2,a3,b0,b1) \
    asm volatile("mma.sync.aligned.m16n8k16.row.col.f32.bf16.bf16.f32 " \
        "{%0,%1,%2,%3}, {%4,%5,%6,%7}, {%8,%9}, {%0,%1,%2,%3};" \
        : "+f"(c0), "+f"(c1), "+f"(c2), "+f"(c3) \
        : "r"(a0), "r"(a1), "r"(a2), "r"(a3), "r"(b0), "r"(b1))

__device__ __forceinline__ void split_bf16(float v, __nv_bfloat16& h, __nv_bfloat16& l) {
    h = __float2bfloat16_rn(v);
    l = __float2bfloat16_rn(v - __bfloat162float(h));
}

// ---- smem geometry (words) ----
__host__ __device__ constexpr int gc_kp(int F)  { return (F == 75) ? 80 : 64; }
__host__ __device__ constexpr int gc_rsw(int F) { return gc_kp(F) / 2 + 4; }   // 44 / 36
__host__ __device__ constexpr int gc_smem_bytes(int F, int D) {
    int dd = (D > 0) ? D : 1;
    return 4 * (64 * gc_rsw(F) * 4) + 64 * dd * 4 + 2 * 64 * 4;
}
__host__ __device__ constexpr int d1_smem_bytes() {
    // Xh,Xl (64 rows) + Wh,Wl (128 rows), RSW=36, + membership + sc/sh(128)
    return (2 * 64 * 36 + 2 * 128 * 36) * 4 + 64 * 4 + 2 * 128 * 4;
}

// ================= graph conv via mma.sync bf16 hi/lo (+bias +tanh +bn1) =============
// Block = 64 atoms, 256 threads (8 warps; warp tile = 16 rows x 32 cols).
// Two K-passes sharing one X and one W smem buffer pair:
//   pass 0: X = self feats, W = Ws;  pass 1 (D>0): X = neighbor sums, W = Wn.
// acc = Xh@Wh + Xh@Wl + Xl@Wh accumulated across both passes.
template <int F, int D>
__global__ __launch_bounds__(256) void gc_mma_kernel(
    const float* __restrict__ feat,
    const int* __restrict__ adj,
    const float* __restrict__ Ws,   // [F][64] slice for this degree
    const float* __restrict__ Wn,   // [F][64] slice (unused if D==0)
    const float* __restrict__ bias, // [64]
    const float* __restrict__ bn_g, const float* __restrict__ bn_b,
    const float* __restrict__ bn_m, const float* __restrict__ bn_v,
    float* __restrict__ out,
    int atom0, int cnt)
{
    constexpr int KP  = gc_kp(F);
    constexpr int RSW = gc_rsw(F);
    constexpr int RS2 = 2 * RSW;
    constexpr int TILE = 64 * RSW;       // words per tile
    constexpr int DD  = (D > 0) ? D : 1;

    extern __shared__ uint32_t smem[];
    uint32_t* s_wh = smem;
    uint32_t* s_wl = smem + TILE;
    uint32_t* s_xh = smem + 2 * TILE;
    uint32_t* s_xl = smem + 3 * TILE;
    int*   s_adj = (int*)(smem + 4 * TILE);
    float* s_sc  = (float*)(s_adj + 64 * DD);
    float* s_sh  = s_sc + 64;
    __nv_bfloat16* s_whb = (__nv_bfloat16*)s_wh;
    __nv_bfloat16* s_wlb = (__nv_bfloat16*)s_wl;
    __nv_bfloat16* s_xhb = (__nv_bfloat16*)s_xh;
    __nv_bfloat16* s_xlb = (__nv_bfloat16*)s_xl;

    const int t = threadIdx.x;
    const int lane = t & 31;
    const int warp = t >> 5;
    const int abase = blockIdx.x * 64;
    const int nat = min(64, cnt - abase);

    // bn scale/shift
    if (t < 64) {
        float sc = bn_g[t] * rsqrtf(bn_v[t] + 1e-3f);
        s_sc[t] = sc;
        s_sh[t] = bn_b[t] - bn_m[t] * sc;
    }
    // adjacency (rows for this tile are contiguous)
    if (D > 0)
        for (int u = t; u < nat * D; u += 256)
            s_adj[u] = adj[abase * D + u];

    // ---- pass 0 staging: W = Ws, X = self ----
    for (int e = t; e < 64 * KP; e += 256) {
        int n = e & 63, k = e >> 6;
        float w = (k < F) ? Ws[k * 64 + n] : 0.f;
        __nv_bfloat16 h, l; split_bf16(w, h, l);
        s_whb[n * RS2 + k] = h;
        s_wlb[n * RS2 + k] = l;
    }
    for (int a = warp; a < 64; a += 8) {
        const float* row = feat + (size_t)(atom0 + abase + a) * F;
        for (int k = lane; k < KP; k += 32) {
            float v = (a < nat && k < F) ? row[k] : 0.f;
            __nv_bfloat16 h, l; split_bf16(v, h, l);
            s_xhb[a * RS2 + k] = h;
            s_xlb[a * RS2 + k] = l;
        }
    }
    __syncthreads();

    // ---- fragment indices ----
    const int g   = lane >> 2;      // 0..7
    const int tIG = lane & 3;       // 0..3
    const int c0  = (warp & 1) * 32;
    const int row0 = (warp >> 1) * 16 + g;
    const int row1 = row0 + 8;

    float c[4][4];
    #pragma unroll
    for (int nt = 0; nt < 4; nt++) {
        float2 bb = *(const float2*)(bias + c0 + nt * 8 + tIG * 2);
        c[nt][0] = bb.x; c[nt][1] = bb.y; c[nt][2] = bb.x; c[nt][3] = bb.y;
    }

    // ---- pass 0 MMA ----
    #pragma unroll
    for (int ks = 0; ks < KP / 16; ks++) {
        const int koff = ks * 8 + tIG;
        uint32_t a0h = s_xh[row0 * RSW + koff];
        uint32_t a1h = s_xh[row1 * RSW + koff];
        uint32_t a2h = s_xh[row0 * RSW + koff + 4];
        uint32_t a3h = s_xh[row1 * RSW + koff + 4];
        uint32_t a0l = s_xl[row0 * RSW + koff];
        uint32_t a1l = s_xl[row1 * RSW + koff];
        uint32_t a2l = s_xl[row0 * RSW + koff + 4];
        uint32_t a3l = s_xl[row1 * RSW + koff + 4];
        #pragma unroll
        for (int nt = 0; nt < 4; nt++) {
            const int n = c0 + nt * 8 + g;
            uint32_t b0h = s_wh[n * RSW + koff];
            uint32_t b1h = s_wh[n * RSW + koff + 4];
            uint32_t b0l = s_wl[n * RSW + koff];
            uint32_t b1l = s_wl[n * RSW + koff + 4];
            MMA_BF16(c[nt][0], c[nt][1], c[nt][2], c[nt][3],
                     a0h, a1h, a2h, a3h, b0h, b1h);
            MMA_BF16(c[nt][0], c[nt][1], c[nt][2], c[nt][3],
                     a0h, a1h, a2h, a3h, b0l, b1l);
            MMA_BF16(c[nt][0], c[nt][1], c[nt][2], c[nt][3],
                     a0l, a1l, a2l, a3l, b0h, b1h);
        }
    }

    // ---- pass 1 (neighbor sums) ----
    if (D > 0) {
        __syncthreads();   // all reads of pass-0 tiles complete
        for (int e = t; e < 64 * KP; e += 256) {
            int n = e & 63, k = e >> 6;
            float w = (k < F) ? Wn[k * 64 + n] : 0.f;
            __nv_bfloat16 h, l; split_bf16(w, h, l);
            s_whb[n * RS2 + k] = h;
            s_wlb[n * RS2 + k] = l;
        }
        for (int a = warp; a < 64; a += 8) {
            int nb[DD];
            if (a < nat) {
                #pragma unroll
                for (int m = 0; m < DD; m++) nb[m] = s_adj[a * D + m];
            }
            for (int k = lane; k < KP; k += 32) {
                float v = 0.f;
                if (a < nat && k < F) {
                    #pragma unroll
                    for (int m = 0; m < DD; m++)
                        v += feat[(size_t)nb[m] * F + k];
                }
                __nv_bfloat16 h, l; split_bf16(v, h, l);
                s_xhb[a * RS2 + k] = h;
                s_xlb[a * RS2 + k] = l;
            }
        }
        __syncthreads();

        #pragma unroll
        for (int ks = 0; ks < KP / 16; ks++) {
            const int koff = ks * 8 + tIG;
            uint32_t a0h = s_xh[row0 * RSW + koff];
            uint32_t a1h = s_xh[row1 * RSW + koff];
            uint32_t a2h = s_xh[row0 * RSW + koff + 4];
            uint32_t a3h = s_xh[row1 * RSW + koff + 4];
            uint32_t a0l = s_xl[row0 * RSW + koff];
            uint32_t a1l = s_xl[row1 * RSW + koff];
            uint32_t a2l = s_xl[row0 * RSW + koff + 4];
            uint32_t a3l = s_xl[row1 * RSW + koff + 4];
            #pragma unroll
            for (int nt = 0; nt < 4; nt++) {
                const int n = c0 + nt * 8 + g;
                uint32_t b0h = s_wh[n * RSW + koff];
                uint32_t b1h = s_wh[n * RSW + koff + 4];
                uint32_t b0l = s_wl[n * RSW + koff];
                uint32_t b1l = s_wl[n * RSW + koff + 4];
                MMA_BF16(c[nt][0], c[nt][1], c[nt][2], c[nt][3],
                         a0h, a1h, a2h, a3h, b0h, b1h);
                MMA_BF16(c[nt][0], c[nt][1], c[nt][2], c[nt][3],
                         a0h, a1h, a2h, a3h, b0l, b1l);
                MMA_BF16(c[nt][0], c[nt][1], c[nt][2], c[nt][3],
                         a0l, a1l, a2l, a3l, b0h, b1h);
            }
        }
    }

    // ---- epilogue: tanh + bn + store ----
    #pragma unroll
    for (int nt = 0; nt < 4; nt++) {
        const int n = c0 + nt * 8 + tIG * 2;
        float2 sc2 = *(const float2*)(s_sc + n);
        float2 sh2 = *(const float2*)(s_sh + n);
        if (row0 < nat) {
            float2 o;
            o.x = sc2.x * tanh_fast(c[nt][0]) + sh2.x;
            o.y = sc2.y * tanh_fast(c[nt][1]) + sh2.y;
            *(float2*)(out + (size_t)(atom0 + abase + row0) * 64 + n) = o;
        }
        if (row1 < nat) {
            float2 o;
            o.x = sc2.x * tanh_fast(c[nt][2]) + sh2.x;
            o.y = sc2.y * tanh_fast(c[nt][3]) + sh2.y;
            *(float2*)(out + (size_t)(atom0 + abase + row1) * 64 + n) = o;
        }
    }
}

// ================= graph pool (float4) =================
__global__ __launch_bounds__(256) void pool_kernel(
    const float4* __restrict__ in, float4* __restrict__ out,
    const int* __restrict__ a1, const int* __restrict__ a2,
    const int* __restrict__ a3, const int* __restrict__ a4,
    const int* __restrict__ a5, const int* __restrict__ a6)
{
    int idx  = blockIdx.x * 256 + threadIdx.x;  // NA*16 total
    int atom = idx >> 4;
    int q    = idx & 15;
    float4 v = in[idx];

    if (atom >= 20000) {
        const int* ap; int d, li;
        if      (atom < 100000) { d = 1; ap = a1; li = atom - 20000;  }
        else if (atom < 250000) { d = 2; ap = a2; li = atom - 100000; }
        else if (atom < 400000) { d = 3; ap = a3; li = atom - 250000; }
        else if (atom < 475000) { d = 4; ap = a4; li = atom - 400000; }
        else if (atom < 495000) { d = 5; ap = a5; li = atom - 475000; }
        else                    { d = 6; ap = a6; li = atom - 495000; }
        for (int m = 0; m < d; m++) {
            int nb = ap[li * d + m];
            float4 u = in[nb * 16 + q];
            v.x = fmaxf(v.x, u.x); v.y = fmaxf(v.y, u.y);
            v.z = fmaxf(v.z, u.z); v.w = fmaxf(v.w, u.w);
        }
    }
    out[idx] = v;
}

// ====== dense1 [64]->[128] via mma.sync (+tanh +bn3), fused segment gather ======
// Block = 64 atoms, 256 threads (8 warps; warp tile = 16 rows x 64 cols).
__global__ __launch_bounds__(256) void dense1_mma_gather_kernel(
    const float* __restrict__ in,
    const int* __restrict__ membership,
    const float* __restrict__ W,   // [64][128]
    const float* __restrict__ b,   // [128]
    const float* __restrict__ bn_g, const float* __restrict__ bn_b,
    const float* __restrict__ bn_m, const float* __restrict__ bn_v,
    float* __restrict__ gsum, unsigned* __restrict__ gmax,
    int cnt)
{
    constexpr int RSW = 36;           // words per 64-k row
    constexpr int RS2 = 2 * RSW;
    constexpr int XT  = 64 * RSW;     // X tile words
    constexpr int WT  = 128 * RSW;    // W tile words

    extern __shared__ uint32_t smem[];
    uint32_t* s_wh = smem;
    uint32_t* s_wl = smem + WT;
    uint32_t* s_xh = smem + 2 * WT;
    uint32_t* s_xl = smem + 2 * WT + XT;
    int*   s_mem = (int*)(smem + 2 * WT + 2 * XT);
    float* s_sc  = (float*)(s_mem + 64);
    float* s_sh  = s_sc + 128;
    __nv_bfloat16* s_whb = (__nv_bfloat16*)s_wh;
    __nv_bfloat16* s_wlb = (__nv_bfloat16*)s_wl;
    __nv_bfloat16* s_xhb = (__nv_bfloat16*)s_xh;
    __nv_bfloat16* s_xlb = (__nv_bfloat16*)s_xl;

    const int t = threadIdx.x;
    const int lane = t & 31;
    const int warp = t >> 5;
    const int abase = blockIdx.x * 64;
    const int nat = min(64, cnt - abase);

    if (t < 128) {
        float sc = bn_g[t] * rsqrtf(bn_v[t] + 1e-3f);
        s_sc[t] = sc;
        s_sh[t] = bn_b[t] - bn_m[t] * sc;
    }
    if (t < nat) s_mem[t] = membership[abase + t];

    // stage W^T (bf16 hi/lo): s_w[n][k] = W[k][n]
    for (int e = t; e < 128 * 64; e += 256) {
        int n = e & 127, k = e >> 7;
        float w = W[k * 128 + n];
        __nv_bfloat16 h, l; split_bf16(w, h, l);
        s_whb[n * RS2 + k] = h;
        s_wlb[n * RS2 + k] = l;
    }
    // stage X
    for (int a = warp; a < 64; a += 8) {
        const float* row = in + (size_t)(abase + a) * 64;
        for (int k = lane; k < 64; k += 32) {
            float v = (a < nat) ? row[k] : 0.f;
            __nv_bfloat16 h, l; split_bf16(v, h, l);
            s_xhb[a * RS2 + k] = h;
            s_xlb[a * RS2 + k] = l;
        }
    }
    __syncthreads();

    const int g   = lane >> 2;
    const int tIG = lane & 3;
    const int c0  = (warp & 1) * 64;
    const int row0 = (warp >> 1) * 16 + g;
    const int row1 = row0 + 8;

    float c[8][4];
    #pragma unroll
    for (int nt = 0; nt < 8; nt++) {
        float2 bb = *(const float2*)(b + c0 + nt * 8 + tIG * 2);
        c[nt][0] = bb.x; c[nt][1] = bb.y; c[nt][2] = bb.x; c[nt][3] = bb.y;
    }

    #pragma unroll
    for (int ks = 0; ks < 4; ks++) {
        const int koff = ks * 8 + tIG;
        uint32_t a0h = s_xh[row0 * RSW + koff];
        uint32_t a1h = s_xh[row1 * RSW + koff];
        uint32_t a2h = s_xh[row0 * RSW + koff + 4];
        uint32_t a3h = s_xh[row1 * RSW + koff + 4];
        uint32_t a0l = s_xl[row0 * RSW + koff];
        uint32_t a1l = s_xl[row1 * RSW + koff];
        uint32_t a2l = s_xl[row0 * RSW + koff + 4];
        uint32_t a3l = s_xl[row1 * RSW + koff + 4];
        #pragma unroll
        for (int nt = 0; nt < 8; nt++) {
            const int n = c0 + nt * 8 + g;
            uint32_t b0h = s_wh[n * RSW + koff];
            uint32_t b1h = s_wh[n * RSW + koff + 4];
            uint32_t b0l = s_wl[n * RSW + koff];
            uint32_t b1l = s_wl[n * RSW + koff + 4];
            MMA_BF16(c[nt][0], c[nt][1], c[nt][2], c[nt][3],
                     a0h, a1h, a2h, a3h, b0h, b1h);
            MMA_BF16(c[nt][0], c[nt][1], c[nt][2], c[nt][3],
                     a0h, a1h, a2h, a3h, b0l, b1l);
            MMA_BF16(c[nt][0], c[nt][1], c[nt][2], c[nt][3],
                     a0l, a1l, a2l, a3l, b0h, b1h);
        }
    }

    // epilogue: tanh + bn, then atomic segment sum/max
    const int m0 = (row0 < nat) ? s_mem[row0] : 0;
    const int m1 = (row1 < nat) ? s_mem[row1] : 0;
    #pragma unroll
    for (int nt = 0; nt < 8; nt++) {
        const int n = c0 + nt * 8 + tIG * 2;
        float2 sc2 = *(const float2*)(s_sc + n);
        float2 sh2 = *(const float2*)(s_sh + n);
        if (row0 < nat) {
            float v0 = sc2.x * tanh_fast(c[nt][0]) + sh2.x;
            float v1 = sc2.y * tanh_fast(c[nt][1]) + sh2.y;
            atomicAdd(&gsum[m0 * 128 + n], v0);
            atomicAdd(&gsum[m0 * 128 + n + 1], v1);
            atomicMax(&gmax[m0 * 128 + n], enc_f(v0));
            atomicMax(&gmax[m0 * 128 + n + 1], enc_f(v1));
        }
        if (row1 < nat) {
            float v0 = sc2.x * tanh_fast(c[nt][2]) + sh2.x;
            float v1 = sc2.y * tanh_fast(c[nt][3]) + sh2.y;
            atomicAdd(&gsum[m1 * 128 + n], v0);
            atomicAdd(&gsum[m1 * 128 + n + 1], v1);
            atomicMax(&gmax[m1 * 128 + n], enc_f(v0));
            atomicMax(&gmax[m1 * 128 + n + 1], enc_f(v1));
        }
    }
}

// ================= head =================
__global__ void head_kernel(const float* __restrict__ gsum, const unsigned* __restrict__ gmax,
                            const float* __restrict__ d2W, const float* __restrict__ d2b,
                            const float* __restrict__ d3W, const float* __restrict__ d3b,
                            float* __restrict__ out)
{
    __shared__ float sg[256];
    __shared__ float sred[64];
    const int row = blockIdx.x;
    const int t   = threadIdx.x;  // 64 threads

    for (int k = t; k < 256; k += 64) {
        float v = (k < 128) ? gsum[row * 128 + k] : dec_f(gmax[row * 128 + (k - 128)]);
        sg[k] = tanh_fast(v);
    }
    __syncthreads();

    float acc = d2b[t];
    for (int k = 0; k < 256; k++)
        acc = fmaf(sg[k], d2W[k * 64 + t], acc);
    float s = 1.f / (1.f + expf(-acc));

    sred[t] = s * d3W[t];
    __syncthreads();
    if (t < 32) {
        float x = sred[t] + sred[t + 32];
        #pragma unroll
        for (int off = 16; off; off >>= 1)
            x += __shfl_down_sync(0xffffffffu, x, off);
        if (t == 0) out[row] = x + d3b[0];
    }
}

// ================= dispatch helpers =================
template <int F, int D>
static void gc_launch_one(const float* feat, const int* adj, const float* Ws,
                          const float* Wn, const float* b, const float* bg,
                          const float* bb, const float* bm, const float* bv,
                          float* out, int atom0, int cnt)
{
    constexpr int SZ = gc_smem_bytes(F, D);
    static bool attr_set = false;
    if (!attr_set) {
        cudaFuncSetAttribute(gc_mma_kernel<F, D>,
                             cudaFuncAttributeMaxDynamicSharedMemorySize, SZ);
        attr_set = true;
    }
    gc_mma_kernel<F, D><<<(cnt + 63) / 64, 256, SZ>>>(
        feat, adj, Ws, Wn, b, bg, bb, bm, bv, out, atom0, cnt);
}

template <int F>
static void launch_gc(int d, const float* feat, const int* adj,
                      const float* Ws, const float* Wn, const float* bias,
                      const float* bg, const float* bb, const float* bm, const float* bv,
                      float* out, int atom0, int cnt)
{
    switch (d) {
    case 0: gc_launch_one<F,0>(feat,adj,Ws,Wn,bias,bg,bb,bm,bv,out,atom0,cnt); break;
    case 1: gc_launch_one<F,1>(feat,adj,Ws,Wn,bias,bg,bb,bm,bv,out,atom0,cnt); break;
    case 2: gc_launch_one<F,2>(feat,adj,Ws,Wn,bias,bg,bb,bm,bv,out,atom0,cnt); break;
    case 3: gc_launch_one<F,3>(feat,adj,Ws,Wn,bias,bg,bb,bm,bv,out,atom0,cnt); break;
    case 4: gc_launch_one<F,4>(feat,adj,Ws,Wn,bias,bg,bb,bm,bv,out,atom0,cnt); break;
    case 5: gc_launch_one<F,5>(feat,adj,Ws,Wn,bias,bg,bb,bm,bv,out,atom0,cnt); break;
    case 6: gc_launch_one<F,6>(feat,adj,Ws,Wn,bias,bg,bb,bm,bv,out,atom0,cnt); break;
    }
}

// ================= launch =================
extern "C" void kernel_launch(void* const* d_in, const int* in_sizes, int n_in,
                              void* d_out, int out_size)
{
    const float* feat       = (const float*)d_in[0];
    const int*   membership = (const int*)d_in[1];
    const int*   adj[6]     = {(const int*)d_in[2], (const int*)d_in[3], (const int*)d_in[4],
                               (const int*)d_in[5], (const int*)d_in[6], (const int*)d_in[7]};
    const float* gc1_Wn = (const float*)d_in[8];
    const float* gc1_Ws = (const float*)d_in[9];
    const float* gc1_b  = (const float*)d_in[10];
    const float* gc2_Wn = (const float*)d_in[11];
    const float* gc2_Ws = (const float*)d_in[12];
    const float* gc2_b  = (const float*)d_in[13];
    const float* bn1g = (const float*)d_in[14];
    const float* bn1b = (const float*)d_in[15];
    const float* bn1m = (const float*)d_in[16];
    const float* bn1v = (const float*)d_in[17];
    const float* bn3g = (const float*)d_in[18];
    const float* bn3b = (const float*)d_in[19];
    const float* bn3m = (const float*)d_in[20];
    const float* bn3v = (const float*)d_in[21];
    const float* d1W = (const float*)d_in[22];
    const float* d1b = (const float*)d_in[23];
    const float* d2W = (const float*)d_in[24];
    const float* d2b = (const float*)d_in[25];
    const float* d3W = (const float*)d_in[26];
    const float* d3b = (const float*)d_in[27];

    float *h1, *h2, *gsum; unsigned* gmax;
    cudaGetSymbolAddress((void**)&h1, g_h1);
    cudaGetSymbolAddress((void**)&h2, g_h2);
    cudaGetSymbolAddress((void**)&gsum, g_gsum);
    cudaGetSymbolAddress((void**)&gmax, g_gmax);

    // ---- gc1 (+tanh +bn1): feat[NA,75] -> h1[NA,64]
    for (int d = 0; d <= 6; d++) {
        launch_gc<75>(d, feat, d ? adj[d - 1] : nullptr,
                      gc1_Ws + d * 75 * 64, d ? gc1_Wn + (d - 1) * 75 * 64 : nullptr,
                      gc1_b + d * 64, bn1g, bn1b, bn1m, bn1v,
                      h1, H_DEG_OFF[d], H_DEG_CNT[d]);
    }

    // ---- pool1: h1 -> h2
    pool_kernel<<<NA * 16 / 256, 256>>>((const float4*)h1, (float4*)h2,
                                        adj[0], adj[1], adj[2], adj[3], adj[4], adj[5]);

    // ---- gc2 (+tanh +bn1): h2[NA,64] -> h1[NA,64]
    for (int d = 0; d <= 6; d++) {
        launch_gc<64>(d, h2, d ? adj[d - 1] : nullptr,
                      gc2_Ws + d * 64 * 64, d ? gc2_Wn + (d - 1) * 64 * 64 : nullptr,
                      gc2_b + d * 64, bn1g, bn1b, bn1m, bn1v,
                      h1, H_DEG_OFF[d], H_DEG_CNT[d]);
    }

    // ---- pool2: h1 -> h2
    pool_kernel<<<NA * 16 / 256, 256>>>((const float4*)h1, (float4*)h2,
                                        adj[0], adj[1], adj[2], adj[3], adj[4], adj[5]);

    // ---- zero gather accumulators, then fused dense1(mma) + segment gather
    cudaMemsetAsync(gsum, 0, 1024 * 128 * sizeof(float));
    cudaMemsetAsync(gmax, 0, 1024 * 128 * sizeof(unsigned));
    {
        static bool attr_set = false;
        if (!attr_set) {
            cudaFuncSetAttribute(dense1_mma_gather_kernel,
                                 cudaFuncAttributeMaxDynamicSharedMemorySize, d1_smem_bytes());
            attr_set = true;
        }
        dense1_mma_gather_kernel<<<(NA + 63) / 64, 256, d1_smem_bytes()>>>(
            h2, membership, d1W, d1b, bn3g, bn3b, bn3m, bn3v, gsum, gmax, NA);
    }

    // ---- head
    head_kernel<<<1024, 64>>>(gsum, gmax, d2W, d2b, d3W, d3b, (float*)d_out);
}

// round 8
// speedup vs baseline: 2.7793x; 1.3498x over previous
#include <cuda_runtime.h>
#include <cuda_bf16.h>
#include <cstdint>

// ---------------- problem constants ----------------
#define NA 500000

// ---------------- scratch (device globals; no allocation allowed) ----------------
__device__ float    g_h1[(size_t)NA * 64];
__device__ float    g_h2[(size_t)NA * 64];
__device__ float    g_gsum[1024 * 128];
__device__ unsigned g_gmax[1024 * 128];
// precomputed weight tiles (bf16 hi/lo, transposed, smem image)
// layout per degree: [WsH | WsL | WnH | WnL], tile = 64 rows * RSW words
__device__ uint32_t g_w1[7 * 4 * 2816];   // gc1: RSW=44
__device__ uint32_t g_w2[7 * 4 * 2304];   // gc2: RSW=36

// ---------------- helpers ----------------
__device__ __forceinline__ unsigned enc_f(float f) {
    unsigned u = __float_as_uint(f);
    return (u >> 31) ? ~u : (u | 0x80000000u);
}
__device__ __forceinline__ float dec_f(unsigned u) {
    return (u >> 31) ? __uint_as_float(u & 0x7FFFFFFFu) : __uint_as_float(~u);
}
__device__ __forceinline__ float tanh_fast(float x) {
    float y;
    asm("tanh.approx.f32 %0, %1;" : "=f"(y) : "f"(x));
    return y;
}
#define COMP(v, i) ((i) == 0 ? (v).x : (i) == 1 ? (v).y : (i) == 2 ? (v).z : (v).w)

// mma.sync m16n8k16 bf16 -> f32 (sm_80+ baseline PTX; HMMA on sm_103)
#define MMA_BF16(c0,c1,c2,c3,a0,a1,a2,a3,b0,b1) \
    asm volatile("mma.sync.aligned.m16n8k16.row.col.f32.bf16.bf16.f32 " \
        "{%0,%1,%2,%3}, {%4,%5,%6,%7}, {%8,%9}, {%0,%1,%2,%3};" \
        : "+f"(c0), "+f"(c1), "+f"(c2), "+f"(c3) \
        : "r"(a0), "r"(a1), "r"(a2), "r"(a3), "r"(b0), "r"(b1))

__device__ __forceinline__ void split_bf16(float v, __nv_bfloat16& h, __nv_bfloat16& l) {
    h = __float2bfloat16_rn(v);
    l = __float2bfloat16_rn(v - __bfloat162float(h));
}

// ---- geometry ----
__host__ __device__ constexpr int gc_kp(int F)  { return (F == 75) ? 80 : 64; }
__host__ __device__ constexpr int gc_rsw(int F) { return gc_kp(F) / 2 + 4; }   // 44 / 36
__host__ __device__ constexpr int gc_tile(int F) { return 64 * gc_rsw(F); }    // words
__host__ __device__ constexpr int gc_smem_bytes(int F) {
    return 4 * gc_tile(F) * 4 + 64 * 6 * 4 + 2 * 64 * 4;
}

// ================= weight prep: fp32 -> transposed bf16 hi/lo tiles =================
__global__ void prep_weights(const float* __restrict__ Ws1, const float* __restrict__ Wn1,
                             const float* __restrict__ Ws2, const float* __restrict__ Wn2)
{
    const int idx = blockIdx.x * 256 + threadIdx.x;
    constexpr int T1 = 7 * 2 * 64 * 88;   // stage1 bf16 elements (RS2=88)
    constexpr int T2 = 7 * 2 * 64 * 72;   // stage2 (RS2=72)
    if (idx < T1) {
        int k = idx % 88, n = (idx / 88) & 63, part = (idx / (88 * 64)) & 1, d = idx / (88 * 128);
        float w = 0.f;
        if (k < 75) {
            if (part == 0) w = Ws1[(d * 75 + k) * 64 + n];
            else if (d > 0) w = Wn1[((d - 1) * 75 + k) * 64 + n];
        }
        __nv_bfloat16 h, l; split_bf16(w, h, l);
        __nv_bfloat16* th = (__nv_bfloat16*)(g_w1 + d * 4 * 2816 + (part * 2 + 0) * 2816);
        __nv_bfloat16* tl = (__nv_bfloat16*)(g_w1 + d * 4 * 2816 + (part * 2 + 1) * 2816);
        th[n * 88 + k] = h;
        tl[n * 88 + k] = l;
    } else if (idx < T1 + T2) {
        int i2 = idx - T1;
        int k = i2 % 72, n = (i2 / 72) & 63, part = (i2 / (72 * 64)) & 1, d = i2 / (72 * 128);
        float w = 0.f;
        if (k < 64) {
            if (part == 0) w = Ws2[(d * 64 + k) * 64 + n];
            else if (d > 0) w = Wn2[((d - 1) * 64 + k) * 64 + n];
        }
        __nv_bfloat16 h, l; split_bf16(w, h, l);
        __nv_bfloat16* th = (__nv_bfloat16*)(g_w2 + d * 4 * 2304 + (part * 2 + 0) * 2304);
        __nv_bfloat16* tl = (__nv_bfloat16*)(g_w2 + d * 4 * 2304 + (part * 2 + 1) * 2304);
        th[n * 72 + k] = h;
        tl[n * 72 + k] = l;
    }
}

// ================= neighbor-sum staging (templated for unrolled gathers) =============
template <int F, int D>
__device__ __forceinline__ void stage_sum(
    const float* __restrict__ feat, const int* __restrict__ s_adj,
    __nv_bfloat16* s_xhb, __nv_bfloat16* s_xlb, int warp, int lane, int nat)
{
    constexpr int KP  = gc_kp(F);
    constexpr int RS2 = 2 * gc_rsw(F);
    for (int a = warp; a < 64; a += 8) {
        int nb[D];
        if (a < nat) {
            #pragma unroll
            for (int m = 0; m < D; m++) nb[m] = s_adj[a * D + m];
        }
        for (int k = lane; k < KP; k += 32) {
            float v = 0.f;
            if (a < nat && k < F) {
                #pragma unroll
                for (int m = 0; m < D; m++)
                    v += feat[(size_t)nb[m] * F + k];
            }
            __nv_bfloat16 h, l; split_bf16(v, h, l);
            s_xhb[a * RS2 + k] = h;
            s_xlb[a * RS2 + k] = l;
        }
    }
}

// ================= merged graph conv (all degrees, one launch) =======================
// Block = 64 atoms of ONE degree segment; 256 threads (8 warps, 16x32 warp tile).
// Weights copied from precomputed tiles (uint4); X gathered + split to bf16 hi/lo.
// acc = Xh@Wh + Xh@Wl + Xl@Wh over [self-pass, sum-pass].
template <int F>
__global__ __launch_bounds__(256) void gc_mma_all(
    const float* __restrict__ feat,
    const int* __restrict__ a1, const int* __restrict__ a2, const int* __restrict__ a3,
    const int* __restrict__ a4, const int* __restrict__ a5, const int* __restrict__ a6,
    const float* __restrict__ gc_b,   // [7][64]
    const float* __restrict__ bn_g, const float* __restrict__ bn_b,
    const float* __restrict__ bn_m, const float* __restrict__ bn_v,
    float* __restrict__ out)
{
    constexpr int KP   = gc_kp(F);
    constexpr int RSW  = gc_rsw(F);
    constexpr int RS2  = 2 * RSW;
    constexpr int TILE = gc_tile(F);
    constexpr int OFFS[8] = {0, 20000, 100000, 250000, 400000, 475000, 495000, 500000};
    constexpr int BOFF[8] = {0, 313, 1563, 3907, 6251, 7423, 7736, 7815};

    extern __shared__ uint32_t smem[];
    uint32_t* s_wh = smem;
    uint32_t* s_wl = smem + TILE;
    uint32_t* s_xh = smem + 2 * TILE;
    uint32_t* s_xl = smem + 3 * TILE;
    int*   s_adj = (int*)(smem + 4 * TILE);
    float* s_sc  = (float*)(s_adj + 64 * 6);
    float* s_sh  = s_sc + 64;
    __nv_bfloat16* s_xhb = (__nv_bfloat16*)s_xh;
    __nv_bfloat16* s_xlb = (__nv_bfloat16*)s_xl;

    const int t = threadIdx.x;
    const int lane = t & 31;
    const int warp = t >> 5;

    // block -> degree (uniform within block)
    int d = 0;
    #pragma unroll
    for (int i = 1; i < 7; i++) if ((int)blockIdx.x >= BOFF[i]) d = i;
    const int lblk  = blockIdx.x - BOFF[d];
    const int atom0 = OFFS[d];
    const int cnt   = OFFS[d + 1] - OFFS[d];
    const int abase = lblk * 64;
    const int nat   = min(64, cnt - abase);
    const int* adj = (d == 1) ? a1 : (d == 2) ? a2 : (d == 3) ? a3 :
                     (d == 4) ? a4 : (d == 5) ? a5 : (d == 6) ? a6 : nullptr;
    const uint32_t* wbase = (F == 75 ? g_w1 : g_w2) + d * 4 * TILE;
    const float* bias = gc_b + d * 64;

    // bn scale/shift
    if (t < 64) {
        float sc = bn_g[t] * rsqrtf(bn_v[t] + 1e-3f);
        s_sc[t] = sc;
        s_sh[t] = bn_b[t] - bn_m[t] * sc;
    }
    // adjacency
    if (d > 0)
        for (int u = t; u < nat * d; u += 256)
            s_adj[u] = adj[abase * d + u];

    // ---- pass 0: W = Ws tiles (uint4 copy), X = self ----
    {
        const uint4* src = (const uint4*)wbase;
        uint4* dh = (uint4*)s_wh;
        uint4* dl = (uint4*)s_wl;
        #pragma unroll 2
        for (int i = t; i < TILE / 4; i += 256) {
            dh[i] = src[i];
            dl[i] = src[i + TILE / 4];
        }
    }
    for (int a = warp; a < 64; a += 8) {
        const float* row = feat + (size_t)(atom0 + abase + a) * F;
        for (int k = lane; k < KP; k += 32) {
            float v = (a < nat && k < F) ? row[k] : 0.f;
            __nv_bfloat16 h, l; split_bf16(v, h, l);
            s_xhb[a * RS2 + k] = h;
            s_xlb[a * RS2 + k] = l;
        }
    }
    __syncthreads();

    // fragment indices
    const int g   = lane >> 2;
    const int tIG = lane & 3;
    const int c0  = (warp & 1) * 32;
    const int row0 = (warp >> 1) * 16 + g;
    const int row1 = row0 + 8;

    float c[4][4];
    #pragma unroll
    for (int nt = 0; nt < 4; nt++) {
        float2 bb = *(const float2*)(bias + c0 + nt * 8 + tIG * 2);
        c[nt][0] = bb.x; c[nt][1] = bb.y; c[nt][2] = bb.x; c[nt][3] = bb.y;
    }

    #pragma unroll
    for (int ks = 0; ks < KP / 16; ks++) {
        const int koff = ks * 8 + tIG;
        uint32_t a0h = s_xh[row0 * RSW + koff];
        uint32_t a1h = s_xh[row1 * RSW + koff];
        uint32_t a2h = s_xh[row0 * RSW + koff + 4];
        uint32_t a3h = s_xh[row1 * RSW + koff + 4];
        uint32_t a0l = s_xl[row0 * RSW + koff];
        uint32_t a1l = s_xl[row1 * RSW + koff];
        uint32_t a2l = s_xl[row0 * RSW + koff + 4];
        uint32_t a3l = s_xl[row1 * RSW + koff + 4];
        #pragma unroll
        for (int nt = 0; nt < 4; nt++) {
            const int n = c0 + nt * 8 + g;
            uint32_t b0h = s_wh[n * RSW + koff];
            uint32_t b1h = s_wh[n * RSW + koff + 4];
            uint32_t b0l = s_wl[n * RSW + koff];
            uint32_t b1l = s_wl[n * RSW + koff + 4];
            MMA_BF16(c[nt][0], c[nt][1], c[nt][2], c[nt][3],
                     a0h, a1h, a2h, a3h, b0h, b1h);
            MMA_BF16(c[nt][0], c[nt][1], c[nt][2], c[nt][3],
                     a0h, a1h, a2h, a3h, b0l, b1l);
            MMA_BF16(c[nt][0], c[nt][1], c[nt][2], c[nt][3],
                     a0l, a1l, a2l, a3l, b0h, b1h);
        }
    }

    // ---- pass 1: W = Wn tiles, X = neighbor sums ----
    if (d > 0) {
        __syncthreads();
        {
            const uint4* src = (const uint4*)(wbase + 2 * TILE);
            uint4* dh = (uint4*)s_wh;
            uint4* dl = (uint4*)s_wl;
            #pragma unroll 2
            for (int i = t; i < TILE / 4; i += 256) {
                dh[i] = src[i];
                dl[i] = src[i + TILE / 4];
            }
        }
        switch (d) {
        case 1: stage_sum<F,1>(feat, s_adj, s_xhb, s_xlb, warp, lane, nat); break;
        case 2: stage_sum<F,2>(feat, s_adj, s_xhb, s_xlb, warp, lane, nat); break;
        case 3: stage_sum<F,3>(feat, s_adj, s_xhb, s_xlb, warp, lane, nat); break;
        case 4: stage_sum<F,4>(feat, s_adj, s_xhb, s_xlb, warp, lane, nat); break;
        case 5: stage_sum<F,5>(feat, s_adj, s_xhb, s_xlb, warp, lane, nat); break;
        case 6: stage_sum<F,6>(feat, s_adj, s_xhb, s_xlb, warp, lane, nat); break;
        }
        __syncthreads();

        #pragma unroll
        for (int ks = 0; ks < KP / 16; ks++) {
            const int koff = ks * 8 + tIG;
            uint32_t a0h = s_xh[row0 * RSW + koff];
            uint32_t a1h = s_xh[row1 * RSW + koff];
            uint32_t a2h = s_xh[row0 * RSW + koff + 4];
            uint32_t a3h = s_xh[row1 * RSW + koff + 4];
            uint32_t a0l = s_xl[row0 * RSW + koff];
            uint32_t a1l = s_xl[row1 * RSW + koff];
            uint32_t a2l = s_xl[row0 * RSW + koff + 4];
            uint32_t a3l = s_xl[row1 * RSW + koff + 4];
            #pragma unroll
            for (int nt = 0; nt < 4; nt++) {
                const int n = c0 + nt * 8 + g;
                uint32_t b0h = s_wh[n * RSW + koff];
                uint32_t b1h = s_wh[n * RSW + koff + 4];
                uint32_t b0l = s_wl[n * RSW + koff];
                uint32_t b1l = s_wl[n * RSW + koff + 4];
                MMA_BF16(c[nt][0], c[nt][1], c[nt][2], c[nt][3],
                         a0h, a1h, a2h, a3h, b0h, b1h);
                MMA_BF16(c[nt][0], c[nt][1], c[nt][2], c[nt][3],
                         a0h, a1h, a2h, a3h, b0l, b1l);
                MMA_BF16(c[nt][0], c[nt][1], c[nt][2], c[nt][3],
                         a0l, a1l, a2l, a3l, b0h, b1h);
            }
        }
    }

    // ---- epilogue: tanh + bn + store ----
    #pragma unroll
    for (int nt = 0; nt < 4; nt++) {
        const int n = c0 + nt * 8 + tIG * 2;
        float2 sc2 = *(const float2*)(s_sc + n);
        float2 sh2 = *(const float2*)(s_sh + n);
        if (row0 < nat) {
            float2 o;
            o.x = sc2.x * tanh_fast(c[nt][0]) + sh2.x;
            o.y = sc2.y * tanh_fast(c[nt][1]) + sh2.y;
            *(float2*)(out + (size_t)(atom0 + abase + row0) * 64 + n) = o;
        }
        if (row1 < nat) {
            float2 o;
            o.x = sc2.x * tanh_fast(c[nt][2]) + sh2.x;
            o.y = sc2.y * tanh_fast(c[nt][3]) + sh2.y;
            *(float2*)(out + (size_t)(atom0 + abase + row1) * 64 + n) = o;
        }
    }
}

// ================= graph pool (float4) =================
__global__ __launch_bounds__(256) void pool_kernel(
    const float4* __restrict__ in, float4* __restrict__ out,
    const int* __restrict__ a1, const int* __restrict__ a2,
    const int* __restrict__ a3, const int* __restrict__ a4,
    const int* __restrict__ a5, const int* __restrict__ a6)
{
    int idx  = blockIdx.x * 256 + threadIdx.x;  // NA*16 total
    int atom = idx >> 4;
    int q    = idx & 15;
    float4 v = in[idx];

    if (atom >= 20000) {
        const int* ap; int d, li;
        if      (atom < 100000) { d = 1; ap = a1; li = atom - 20000;  }
        else if (atom < 250000) { d = 2; ap = a2; li = atom - 100000; }
        else if (atom < 400000) { d = 3; ap = a3; li = atom - 250000; }
        else if (atom < 475000) { d = 4; ap = a4; li = atom - 400000; }
        else if (atom < 495000) { d = 5; ap = a5; li = atom - 475000; }
        else                    { d = 6; ap = a6; li = atom - 495000; }
        for (int m = 0; m < d; m++) {
            int nb = ap[li * d + m];
            float4 u = in[nb * 16 + q];
            v.x = fmaxf(v.x, u.x); v.y = fmaxf(v.y, u.y);
            v.z = fmaxf(v.z, u.z); v.w = fmaxf(v.w, u.w);
        }
    }
    out[idx] = v;
}

// ================= dense1 [64]->[128] + tanh + bn3, fused segment gather ==============
// (round-4 proven scalar version)
__global__ __launch_bounds__(256) void dense1_gather_kernel(
    const float* __restrict__ in,
    const int* __restrict__ membership,
    const float* __restrict__ W,   // [64][128]
    const float* __restrict__ b,   // [128]
    const float* __restrict__ bn_g, const float* __restrict__ bn_b,
    const float* __restrict__ bn_m, const float* __restrict__ bn_v,
    float* __restrict__ gsum, unsigned* __restrict__ gmax,
    int cnt)
{
    __shared__ float s_in[64][68];
    __shared__ int   s_mem[64];

    const int t    = threadIdx.x;
    const int ablk = blockIdx.x * 64;
    const int nat  = min(64, cnt - ablk);

    for (int idx = t; idx < nat * 16; idx += 256) {
        int a = idx >> 4, q = idx & 15;
        *(float4*)&s_in[a][q * 4] = *(const float4*)(in + (size_t)(ablk + a) * 64 + q * 4);
    }
    if (t < nat) s_mem[t] = membership[ablk + t];
    __syncthreads();

    const int j   = (t & 31) * 4;
    const int grp = t >> 5;

    float acc[8][4];
    {
        float4 b4 = *(const float4*)(b + j);
        #pragma unroll
        for (int r = 0; r < 8; r++) {
            acc[r][0] = b4.x; acc[r][1] = b4.y; acc[r][2] = b4.z; acc[r][3] = b4.w;
        }
    }

    for (int k0 = 0; k0 < 64; k0 += 4) {
        float4 w[4];
        #pragma unroll
        for (int kk = 0; kk < 4; kk++)
            w[kk] = *(const float4*)(W + (k0 + kk) * 128 + j);
        #pragma unroll
        for (int r = 0; r < 8; r++) {
            float4 xv = *(const float4*)&s_in[grp * 8 + r][k0];
            #pragma unroll
            for (int kk = 0; kk < 4; kk++) {
                float x = COMP(xv, kk);
                acc[r][0] = fmaf(x, w[kk].x, acc[r][0]);
                acc[r][1] = fmaf(x, w[kk].y, acc[r][1]);
                acc[r][2] = fmaf(x, w[kk].z, acc[r][2]);
                acc[r][3] = fmaf(x, w[kk].w, acc[r][3]);
            }
        }
    }

    float4 g4 = *(const float4*)(bn_g + j);
    float4 v4 = *(const float4*)(bn_v + j);
    float4 bb4 = *(const float4*)(bn_b + j);
    float4 m4 = *(const float4*)(bn_m + j);
    float sc[4], sh[4];
    #pragma unroll
    for (int c = 0; c < 4; c++) {
        sc[c] = COMP(g4, c) * rsqrtf(COMP(v4, c) + 1e-3f);
        sh[c] = COMP(bb4, c) - COMP(m4, c) * sc[c];
    }

    #pragma unroll
    for (int r = 0; r < 8; r++) {
        int a = grp * 8 + r;
        if (a < nat) {
            int m = s_mem[a];
            #pragma unroll
            for (int c = 0; c < 4; c++) {
                float v = sc[c] * tanh_fast(acc[r][c]) + sh[c];
                atomicAdd(&gsum[m * 128 + j + c], v);
                atomicMax(&gmax[m * 128 + j + c], enc_f(v));
            }
        }
    }
}

// ================= head =================
__global__ void head_kernel(const float* __restrict__ gsum, const unsigned* __restrict__ gmax,
                            const float* __restrict__ d2W, const float* __restrict__ d2b,
                            const float* __restrict__ d3W, const float* __restrict__ d3b,
                            float* __restrict__ out)
{
    __shared__ float sg[256];
    __shared__ float sred[64];
    const int row = blockIdx.x;
    const int t   = threadIdx.x;  // 64 threads

    for (int k = t; k < 256; k += 64) {
        float v = (k < 128) ? gsum[row * 128 + k] : dec_f(gmax[row * 128 + (k - 128)]);
        sg[k] = tanh_fast(v);
    }
    __syncthreads();

    float acc = d2b[t];
    for (int k = 0; k < 256; k++)
        acc = fmaf(sg[k], d2W[k * 64 + t], acc);
    float s = 1.f / (1.f + expf(-acc));

    sred[t] = s * d3W[t];
    __syncthreads();
    if (t < 32) {
        float x = sred[t] + sred[t + 32];
        #pragma unroll
        for (int off = 16; off; off >>= 1)
            x += __shfl_down_sync(0xffffffffu, x, off);
        if (t == 0) out[row] = x + d3b[0];
    }
}

// ================= launch =================
extern "C" void kernel_launch(void* const* d_in, const int* in_sizes, int n_in,
                              void* d_out, int out_size)
{
    const float* feat       = (const float*)d_in[0];
    const int*   membership = (const int*)d_in[1];
    const int*   adj[6]     = {(const int*)d_in[2], (const int*)d_in[3], (const int*)d_in[4],
                               (const int*)d_in[5], (const int*)d_in[6], (const int*)d_in[7]};
    const float* gc1_Wn = (const float*)d_in[8];
    const float* gc1_Ws = (const float*)d_in[9];
    const float* gc1_b  = (const float*)d_in[10];
    const float* gc2_Wn = (const float*)d_in[11];
    const float* gc2_Ws = (const float*)d_in[12];
    const float* gc2_b  = (const float*)d_in[13];
    const float* bn1g = (const float*)d_in[14];
    const float* bn1b = (const float*)d_in[15];
    const float* bn1m = (const float*)d_in[16];
    const float* bn1v = (const float*)d_in[17];
    const float* bn3g = (const float*)d_in[18];
    const float* bn3b = (const float*)d_in[19];
    const float* bn3m = (const float*)d_in[20];
    const float* bn3v = (const float*)d_in[21];
    const float* d1W = (const float*)d_in[22];
    const float* d1b = (const float*)d_in[23];
    const float* d2W = (const float*)d_in[24];
    const float* d2b = (const float*)d_in[25];
    const float* d3W = (const float*)d_in[26];
    const float* d3b = (const float*)d_in[27];

    float *h1, *h2, *gsum; unsigned* gmax;
    cudaGetSymbolAddress((void**)&h1, g_h1);
    cudaGetSymbolAddress((void**)&h2, g_h2);
    cudaGetSymbolAddress((void**)&gsum, g_gsum);
    cudaGetSymbolAddress((void**)&gmax, g_gmax);

    constexpr int SZ75 = gc_smem_bytes(75);
    constexpr int SZ64 = gc_smem_bytes(64);
    static bool attr_set = false;
    if (!attr_set) {
        cudaFuncSetAttribute(gc_mma_all<75>, cudaFuncAttributeMaxDynamicSharedMemorySize, SZ75);
        cudaFuncSetAttribute(gc_mma_all<64>, cudaFuncAttributeMaxDynamicSharedMemorySize, SZ64);
        attr_set = true;
    }

    // ---- weight prep (every call; deterministic) ----
    prep_weights<<<560, 256>>>(gc1_Ws, gc1_Wn, gc2_Ws, gc2_Wn);

    // ---- gc1 (+tanh +bn1): feat[NA,75] -> h1[NA,64]
    gc_mma_all<75><<<7815, 256, SZ75>>>(feat, adj[0], adj[1], adj[2], adj[3], adj[4], adj[5],
                                        gc1_b, bn1g, bn1b, bn1m, bn1v, h1);

    // ---- pool1: h1 -> h2
    pool_kernel<<<NA * 16 / 256, 256>>>((const float4*)h1, (float4*)h2,
                                        adj[0], adj[1], adj[2], adj[3], adj[4], adj[5]);

    // ---- gc2 (+tanh +bn1): h2[NA,64] -> h1[NA,64]
    gc_mma_all<64><<<7815, 256, SZ64>>>(h2, adj[0], adj[1], adj[2], adj[3], adj[4], adj[5],
                                        gc2_b, bn1g, bn1b, bn1m, bn1v, h1);

    // ---- pool2: h1 -> h2
    pool_kernel<<<NA * 16 / 256, 256>>>((const float4*)h1, (float4*)h2,
                                        adj[0], adj[1], adj[2], adj[3], adj[4], adj[5]);

    // ---- zero gather accumulators, then fused dense1 + segment gather
    cudaMemsetAsync(gsum, 0, 1024 * 128 * sizeof(float));
    cudaMemsetAsync(gmax, 0, 1024 * 128 * sizeof(unsigned));
    dense1_gather_kernel<<<(NA + 63) / 64, 256>>>(h2, membership, d1W, d1b,
                                                  bn3g, bn3b, bn3m, bn3v,
                                                  gsum, gmax, NA);

    // ---- head
    head_kernel<<<1024, 64>>>(gsum, gmax, d2W, d2b, d3W, d3b, (float*)d_out);
}

// round 10
// speedup vs baseline: 2.9333x; 1.0554x over previous
#include <cuda_runtime.h>
#include <cuda_bf16.h>
#include <cstdint>

// ---------------- problem constants ----------------
#define NA 500000

// ---------------- scratch (device globals; no allocation allowed) ----------------
__device__ float    g_h1[(size_t)NA * 64];
__device__ float    g_h2[(size_t)NA * 64];
__device__ float    g_gsum[1024 * 128];
__device__ unsigned g_gmax[1024 * 128];
// precomputed weight tiles (bf16 hi/lo, transposed, smem image)
__device__ uint32_t g_w1[7 * 4 * 2816];   // gc1: RSW=44
__device__ uint32_t g_w2[7 * 4 * 2304];   // gc2: RSW=36
__device__ uint32_t g_wd[2 * 4608];       // dense1: 128 rows x RSW=36, hi|lo

// ---------------- helpers ----------------
__device__ __forceinline__ unsigned enc_f(float f) {
    unsigned u = __float_as_uint(f);
    return (u >> 31) ? ~u : (u | 0x80000000u);
}
__device__ __forceinline__ float dec_f(unsigned u) {
    return (u >> 31) ? __uint_as_float(u & 0x7FFFFFFFu) : __uint_as_float(~u);
}
__device__ __forceinline__ float tanh_fast(float x) {
    float y;
    asm("tanh.approx.f32 %0, %1;" : "=f"(y) : "f"(x));
    return y;
}

// mma.sync m16n8k16 bf16 -> f32 (sm_80+ baseline PTX; HMMA on sm_103)
#define MMA_BF16(c0,c1,c2,c3,a0,a1,a2,a3,b0,b1) \
    asm volatile("mma.sync.aligned.m16n8k16.row.col.f32.bf16.bf16.f32 " \
        "{%0,%1,%2,%3}, {%4,%5,%6,%7}, {%8,%9}, {%0,%1,%2,%3};" \
        : "+f"(c0), "+f"(c1), "+f"(c2), "+f"(c3) \
        : "r"(a0), "r"(a1), "r"(a2), "r"(a3), "r"(b0), "r"(b1))

__device__ __forceinline__ void split_bf16(float v, __nv_bfloat16& h, __nv_bfloat16& l) {
    h = __float2bfloat16_rn(v);
    l = __float2bfloat16_rn(v - __bfloat162float(h));
}

// ---- geometry ----
__host__ __device__ constexpr int gc_kp(int F)  { return (F == 75) ? 80 : 64; }
__host__ __device__ constexpr int gc_rsw(int F) { return gc_kp(F) / 2 + 4; }   // 44 / 36
__host__ __device__ constexpr int gc_tile(int F) { return 64 * gc_rsw(F); }    // words
__host__ __device__ constexpr int gc_smem_bytes(int F) {
    return 4 * gc_tile(F) * 4 + 64 * 6 * 4 + 2 * 64 * 4;
}
// d1 fused kernel smem: Wh,Wl(128x36) + Xh,Xl(64x36) + adj + mem + sc/sh(128)
__host__ __device__ constexpr int d1_smem_bytes() {
    return (2 * 4608 + 2 * 2304) * 4 + 64 * 6 * 4 + 64 * 4 + 2 * 128 * 4;
}

// ================= weight prep: fp32 -> transposed bf16 hi/lo tiles =================
__global__ void prep_weights(const float* __restrict__ Ws1, const float* __restrict__ Wn1,
                             const float* __restrict__ Ws2, const float* __restrict__ Wn2,
                             const float* __restrict__ Wd)
{
    const int idx = blockIdx.x * 256 + threadIdx.x;
    constexpr int T1 = 7 * 2 * 64 * 88;   // stage1 bf16 elements (RS2=88)
    constexpr int T2 = 7 * 2 * 64 * 72;   // stage2 (RS2=72)
    constexpr int T3 = 128 * 72;          // dense1 (RS2=72)
    if (idx < T1) {
        int k = idx % 88, n = (idx / 88) & 63, part = (idx / (88 * 64)) & 1, d = idx / (88 * 128);
        float w = 0.f;
        if (k < 75) {
            if (part == 0) w = Ws1[(d * 75 + k) * 64 + n];
            else if (d > 0) w = Wn1[((d - 1) * 75 + k) * 64 + n];
        }
        __nv_bfloat16 h, l; split_bf16(w, h, l);
        __nv_bfloat16* th = (__nv_bfloat16*)(g_w1 + d * 4 * 2816 + (part * 2 + 0) * 2816);
        __nv_bfloat16* tl = (__nv_bfloat16*)(g_w1 + d * 4 * 2816 + (part * 2 + 1) * 2816);
        th[n * 88 + k] = h;
        tl[n * 88 + k] = l;
    } else if (idx < T1 + T2) {
        int i2 = idx - T1;
        int k = i2 % 72, n = (i2 / 72) & 63, part = (i2 / (72 * 64)) & 1, d = i2 / (72 * 128);
        float w = 0.f;
        if (k < 64) {
            if (part == 0) w = Ws2[(d * 64 + k) * 64 + n];
            else if (d > 0) w = Wn2[((d - 1) * 64 + k) * 64 + n];
        }
        __nv_bfloat16 h, l; split_bf16(w, h, l);
        __nv_bfloat16* th = (__nv_bfloat16*)(g_w2 + d * 4 * 2304 + (part * 2 + 0) * 2304);
        __nv_bfloat16* tl = (__nv_bfloat16*)(g_w2 + d * 4 * 2304 + (part * 2 + 1) * 2304);
        th[n * 72 + k] = h;
        tl[n * 72 + k] = l;
    } else if (idx < T1 + T2 + T3) {
        int i3 = idx - T1 - T2;
        int k = i3 % 72, n = i3 / 72;   // n in [0,128)
        float w = (k < 64) ? Wd[k * 128 + n] : 0.f;
        __nv_bfloat16 h, l; split_bf16(w, h, l);
        ((__nv_bfloat16*)g_wd)[n * 72 + k] = h;
        ((__nv_bfloat16*)(g_wd + 4608))[n * 72 + k] = l;
    }
}

// ================= neighbor staging helpers (templated) =============
template <int F, int D>
__device__ __forceinline__ void stage_sum(
    const float* __restrict__ feat, const int* __restrict__ s_adj,
    __nv_bfloat16* s_xhb, __nv_bfloat16* s_xlb, int warp, int lane, int nat)
{
    constexpr int KP  = gc_kp(F);
    constexpr int RS2 = 2 * gc_rsw(F);
    for (int a = warp; a < 64; a += 8) {
        int nb[D];
        if (a < nat) {
            #pragma unroll
            for (int m = 0; m < D; m++) nb[m] = s_adj[a * D + m];
        }
        for (int k = lane; k < KP; k += 32) {
            float v = 0.f;
            if (a < nat && k < F) {
                #pragma unroll
                for (int m = 0; m < D; m++)
                    v += feat[(size_t)nb[m] * F + k];
            }
            __nv_bfloat16 h, l; split_bf16(v, h, l);
            s_xhb[a * RS2 + k] = h;
            s_xlb[a * RS2 + k] = l;
        }
    }
}

// pooled staging for dense1: X = max(self, neighbors), 64 feats
template <int D>
__device__ __forceinline__ void stage_pool(
    const float* __restrict__ feat, const int* __restrict__ s_adj,
    __nv_bfloat16* s_xhb, __nv_bfloat16* s_xlb,
    int atom0, int abase, int warp, int lane, int nat)
{
    for (int a = warp; a < 64; a += 8) {
        int nb[D > 0 ? D : 1];
        if (D > 0 && a < nat) {
            #pragma unroll
            for (int m = 0; m < D; m++) nb[m] = s_adj[a * D + m];
        }
        const float* self = feat + (size_t)(atom0 + abase + a) * 64;
        for (int k = lane; k < 64; k += 32) {
            float v = 0.f;
            if (a < nat) {
                v = self[k];
                if (D > 0) {
                    #pragma unroll
                    for (int m = 0; m < D; m++)
                        v = fmaxf(v, feat[(size_t)nb[m] * 64 + k]);
                }
            }
            __nv_bfloat16 h, l; split_bf16(v, h, l);
            s_xhb[a * 72 + k] = h;
            s_xlb[a * 72 + k] = l;
        }
    }
}

// ================= merged graph conv (all degrees, one launch) =======================
template <int F>
__global__ __launch_bounds__(256) void gc_mma_all(
    const float* __restrict__ feat,
    const int* __restrict__ a1, const int* __restrict__ a2, const int* __restrict__ a3,
    const int* __restrict__ a4, const int* __restrict__ a5, const int* __restrict__ a6,
    const float* __restrict__ gc_b,   // [7][64]
    const float* __restrict__ bn_g, const float* __restrict__ bn_b,
    const float* __restrict__ bn_m, const float* __restrict__ bn_v,
    float* __restrict__ out)
{
    constexpr int KP   = gc_kp(F);
    constexpr int RSW  = gc_rsw(F);
    constexpr int RS2  = 2 * RSW;
    constexpr int TILE = gc_tile(F);
    constexpr int OFFS[8] = {0, 20000, 100000, 250000, 400000, 475000, 495000, 500000};
    constexpr int BOFF[8] = {0, 313, 1563, 3907, 6251, 7423, 7736, 7815};

    extern __shared__ uint32_t smem[];
    uint32_t* s_wh = smem;
    uint32_t* s_wl = smem + TILE;
    uint32_t* s_xh = smem + 2 * TILE;
    uint32_t* s_xl = smem + 3 * TILE;
    int*   s_adj = (int*)(smem + 4 * TILE);
    float* s_sc  = (float*)(s_adj + 64 * 6);
    float* s_sh  = s_sc + 64;
    __nv_bfloat16* s_xhb = (__nv_bfloat16*)s_xh;
    __nv_bfloat16* s_xlb = (__nv_bfloat16*)s_xl;

    const int t = threadIdx.x;
    const int lane = t & 31;
    const int warp = t >> 5;

    int d = 0;
    #pragma unroll
    for (int i = 1; i < 7; i++) if ((int)blockIdx.x >= BOFF[i]) d = i;
    const int lblk  = blockIdx.x - BOFF[d];
    const int atom0 = OFFS[d];
    const int cnt   = OFFS[d + 1] - OFFS[d];
    const int abase = lblk * 64;
    const int nat   = min(64, cnt - abase);
    const int* adj = (d == 1) ? a1 : (d == 2) ? a2 : (d == 3) ? a3 :
                     (d == 4) ? a4 : (d == 5) ? a5 : (d == 6) ? a6 : nullptr;
    const uint32_t* wbase = (F == 75 ? g_w1 : g_w2) + d * 4 * TILE;
    const float* bias = gc_b + d * 64;

    if (t < 64) {
        float sc = bn_g[t] * rsqrtf(bn_v[t] + 1e-3f);
        s_sc[t] = sc;
        s_sh[t] = bn_b[t] - bn_m[t] * sc;
    }
    if (d > 0)
        for (int u = t; u < nat * d; u += 256)
            s_adj[u] = adj[abase * d + u];

    // ---- pass 0: W = Ws tiles (uint4 copy), X = self ----
    {
        const uint4* src = (const uint4*)wbase;
        uint4* dh = (uint4*)s_wh;
        uint4* dl = (uint4*)s_wl;
        #pragma unroll 2
        for (int i = t; i < TILE / 4; i += 256) {
            dh[i] = src[i];
            dl[i] = src[i + TILE / 4];
        }
    }
    for (int a = warp; a < 64; a += 8) {
        const float* row = feat + (size_t)(atom0 + abase + a) * F;
        for (int k = lane; k < KP; k += 32) {
            float v = (a < nat && k < F) ? row[k] : 0.f;
            __nv_bfloat16 h, l; split_bf16(v, h, l);
            s_xhb[a * RS2 + k] = h;
            s_xlb[a * RS2 + k] = l;
        }
    }
    __syncthreads();

    const int g   = lane >> 2;
    const int tIG = lane & 3;
    const int c0  = (warp & 1) * 32;
    const int row0 = (warp >> 1) * 16 + g;
    const int row1 = row0 + 8;

    float c[4][4];
    #pragma unroll
    for (int nt = 0; nt < 4; nt++) {
        float2 bb = *(const float2*)(bias + c0 + nt * 8 + tIG * 2);
        c[nt][0] = bb.x; c[nt][1] = bb.y; c[nt][2] = bb.x; c[nt][3] = bb.y;
    }

    #pragma unroll
    for (int ks = 0; ks < KP / 16; ks++) {
        const int koff = ks * 8 + tIG;
        uint32_t a0h = s_xh[row0 * RSW + koff];
        uint32_t a1h = s_xh[row1 * RSW + koff];
        uint32_t a2h = s_xh[row0 * RSW + koff + 4];
        uint32_t a3h = s_xh[row1 * RSW + koff + 4];
        uint32_t a0l = s_xl[row0 * RSW + koff];
        uint32_t a1l = s_xl[row1 * RSW + koff];
        uint32_t a2l = s_xl[row0 * RSW + koff + 4];
        uint32_t a3l = s_xl[row1 * RSW + koff + 4];
        #pragma unroll
        for (int nt = 0; nt < 4; nt++) {
            const int n = c0 + nt * 8 + g;
            uint32_t b0h = s_wh[n * RSW + koff];
            uint32_t b1h = s_wh[n * RSW + koff + 4];
            uint32_t b0l = s_wl[n * RSW + koff];
            uint32_t b1l = s_wl[n * RSW + koff + 4];
            MMA_BF16(c[nt][0], c[nt][1], c[nt][2], c[nt][3],
                     a0h, a1h, a2h, a3h, b0h, b1h);
            MMA_BF16(c[nt][0], c[nt][1], c[nt][2], c[nt][3],
                     a0h, a1h, a2h, a3h, b0l, b1l);
            MMA_BF16(c[nt][0], c[nt][1], c[nt][2], c[nt][3],
                     a0l, a1l, a2l, a3l, b0h, b1h);
        }
    }

    // ---- pass 1: W = Wn tiles, X = neighbor sums ----
    if (d > 0) {
        __syncthreads();
        {
            const uint4* src = (const uint4*)(wbase + 2 * TILE);
            uint4* dh = (uint4*)s_wh;
            uint4* dl = (uint4*)s_wl;
            #pragma unroll 2
            for (int i = t; i < TILE / 4; i += 256) {
                dh[i] = src[i];
                dl[i] = src[i + TILE / 4];
            }
        }
        switch (d) {
        case 1: stage_sum<F,1>(feat, s_adj, s_xhb, s_xlb, warp, lane, nat); break;
        case 2: stage_sum<F,2>(feat, s_adj, s_xhb, s_xlb, warp, lane, nat); break;
        case 3: stage_sum<F,3>(feat, s_adj, s_xhb, s_xlb, warp, lane, nat); break;
        case 4: stage_sum<F,4>(feat, s_adj, s_xhb, s_xlb, warp, lane, nat); break;
        case 5: stage_sum<F,5>(feat, s_adj, s_xhb, s_xlb, warp, lane, nat); break;
        case 6: stage_sum<F,6>(feat, s_adj, s_xhb, s_xlb, warp, lane, nat); break;
        }
        __syncthreads();

        #pragma unroll
        for (int ks = 0; ks < KP / 16; ks++) {
            const int koff = ks * 8 + tIG;
            uint32_t a0h = s_xh[row0 * RSW + koff];
            uint32_t a1h = s_xh[row1 * RSW + koff];
            uint32_t a2h = s_xh[row0 * RSW + koff + 4];
            uint32_t a3h = s_xh[row1 * RSW + koff + 4];
            uint32_t a0l = s_xl[row0 * RSW + koff];
            uint32_t a1l = s_xl[row1 * RSW + koff];
            uint32_t a2l = s_xl[row0 * RSW + koff + 4];
            uint32_t a3l = s_xl[row1 * RSW + koff + 4];
            #pragma unroll
            for (int nt = 0; nt < 4; nt++) {
                const int n = c0 + nt * 8 + g;
                uint32_t b0h = s_wh[n * RSW + koff];
                uint32_t b1h = s_wh[n * RSW + koff + 4];
                uint32_t b0l = s_wl[n * RSW + koff];
                uint32_t b1l = s_wl[n * RSW + koff + 4];
                MMA_BF16(c[nt][0], c[nt][1], c[nt][2], c[nt][3],
                         a0h, a1h, a2h, a3h, b0h, b1h);
                MMA_BF16(c[nt][0], c[nt][1], c[nt][2], c[nt][3],
                         a0h, a1h, a2h, a3h, b0l, b1l);
                MMA_BF16(c[nt][0], c[nt][1], c[nt][2], c[nt][3],
                         a0l, a1l, a2l, a3l, b0h, b1h);
            }
        }
    }

    // ---- epilogue: tanh + bn + store ----
    #pragma unroll
    for (int nt = 0; nt < 4; nt++) {
        const int n = c0 + nt * 8 + tIG * 2;
        float2 sc2 = *(const float2*)(s_sc + n);
        float2 sh2 = *(const float2*)(s_sh + n);
        if (row0 < nat) {
            float2 o;
            o.x = sc2.x * tanh_fast(c[nt][0]) + sh2.x;
            o.y = sc2.y * tanh_fast(c[nt][1]) + sh2.y;
            *(float2*)(out + (size_t)(atom0 + abase + row0) * 64 + n) = o;
        }
        if (row1 < nat) {
            float2 o;
            o.x = sc2.x * tanh_fast(c[nt][2]) + sh2.x;
            o.y = sc2.y * tanh_fast(c[nt][3]) + sh2.y;
            *(float2*)(out + (size_t)(atom0 + abase + row1) * 64 + n) = o;
        }
    }
}

// ================= graph pool (float4) =================
__global__ __launch_bounds__(256) void pool_kernel(
    const float4* __restrict__ in, float4* __restrict__ out,
    const int* __restrict__ a1, const int* __restrict__ a2,
    const int* __restrict__ a3, const int* __restrict__ a4,
    const int* __restrict__ a5, const int* __restrict__ a6)
{
    int idx  = blockIdx.x * 256 + threadIdx.x;  // NA*16 total
    int atom = idx >> 4;
    int q    = idx & 15;
    float4 v = in[idx];

    if (atom >= 20000) {
        const int* ap; int d, li;
        if      (atom < 100000) { d = 1; ap = a1; li = atom - 20000;  }
        else if (atom < 250000) { d = 2; ap = a2; li = atom - 100000; }
        else if (atom < 400000) { d = 3; ap = a3; li = atom - 250000; }
        else if (atom < 475000) { d = 4; ap = a4; li = atom - 400000; }
        else if (atom < 495000) { d = 5; ap = a5; li = atom - 475000; }
        else                    { d = 6; ap = a6; li = atom - 495000; }
        for (int m = 0; m < d; m++) {
            int nb = ap[li * d + m];
            float4 u = in[nb * 16 + q];
            v.x = fmaxf(v.x, u.x); v.y = fmaxf(v.y, u.y);
            v.z = fmaxf(v.z, u.z); v.w = fmaxf(v.w, u.w);
        }
    }
    out[idx] = v;
}

// ====== fused pool2 + dense1 [64]->[128] via mma (+tanh +bn3) + segment gather ======
// Same degree-segmented grid as gc. X = max(self, neighbors) of h1.
__global__ __launch_bounds__(256) void d1_mma_all(
    const float* __restrict__ feat,   // h1 (gc2 output)
    const int* __restrict__ a1, const int* __restrict__ a2, const int* __restrict__ a3,
    const int* __restrict__ a4, const int* __restrict__ a5, const int* __restrict__ a6,
    const int* __restrict__ membership,
    const float* __restrict__ b,      // [128]
    const float* __restrict__ bn_g, const float* __restrict__ bn_b,
    const float* __restrict__ bn_m, const float* __restrict__ bn_v,
    float* __restrict__ gsum, unsigned* __restrict__ gmax)
{
    constexpr int RSW = 36;
    constexpr int XT  = 64 * RSW;     // 2304
    constexpr int WT  = 128 * RSW;    // 4608
    constexpr int OFFS[8] = {0, 20000, 100000, 250000, 400000, 475000, 495000, 500000};
    constexpr int BOFF[8] = {0, 313, 1563, 3907, 6251, 7423, 7736, 7815};

    extern __shared__ uint32_t smem[];
    uint32_t* s_wh = smem;
    uint32_t* s_wl = smem + WT;
    uint32_t* s_xh = smem + 2 * WT;
    uint32_t* s_xl = smem + 2 * WT + XT;
    int*   s_adj = (int*)(smem + 2 * WT + 2 * XT);
    int*   s_mem = s_adj + 64 * 6;
    float* s_sc  = (float*)(s_mem + 64);
    float* s_sh  = s_sc + 128;
    __nv_bfloat16* s_xhb = (__nv_bfloat16*)s_xh;
    __nv_bfloat16* s_xlb = (__nv_bfloat16*)s_xl;

    const int t = threadIdx.x;
    const int lane = t & 31;
    const int warp = t >> 5;

    int d = 0;
    #pragma unroll
    for (int i = 1; i < 7; i++) if ((int)blockIdx.x >= BOFF[i]) d = i;
    const int lblk  = blockIdx.x - BOFF[d];
    const int atom0 = OFFS[d];
    const int cnt   = OFFS[d + 1] - OFFS[d];
    const int abase = lblk * 64;
    const int nat   = min(64, cnt - abase);
    const int* adj = (d == 1) ? a1 : (d == 2) ? a2 : (d == 3) ? a3 :
                     (d == 4) ? a4 : (d == 5) ? a5 : (d == 6) ? a6 : nullptr;

    if (t < 128) {
        float sc = bn_g[t] * rsqrtf(bn_v[t] + 1e-3f);
        s_sc[t] = sc;
        s_sh[t] = bn_b[t] - bn_m[t] * sc;
    }
    if (t < nat) s_mem[t] = membership[atom0 + abase + t];
    if (d > 0)
        for (int u = t; u < nat * d; u += 256)
            s_adj[u] = adj[abase * d + u];

    // W tiles (uint4 copy from precomputed) — no s_adj dependence, safe before sync
    {
        const uint4* src = (const uint4*)g_wd;
        uint4* dh = (uint4*)s_wh;
        uint4* dl = (uint4*)s_wl;
        #pragma unroll 2
        for (int i = t; i < WT / 4; i += 256) {
            dh[i] = src[i];
            dl[i] = src[i + WT / 4];
        }
    }

    // BARRIER: s_adj (and s_mem/s_sc/s_sh) must be fully written before stage_pool
    // reads cross-warp adjacency entries. (This was the round-9 illegal-access bug.)
    __syncthreads();

    // X = pooled rows
    switch (d) {
    case 0: stage_pool<0>(feat, s_adj, s_xhb, s_xlb, atom0, abase, warp, lane, nat); break;
    case 1: stage_pool<1>(feat, s_adj, s_xhb, s_xlb, atom0, abase, warp, lane, nat); break;
    case 2: stage_pool<2>(feat, s_adj, s_xhb, s_xlb, atom0, abase, warp, lane, nat); break;
    case 3: stage_pool<3>(feat, s_adj, s_xhb, s_xlb, atom0, abase, warp, lane, nat); break;
    case 4: stage_pool<4>(feat, s_adj, s_xhb, s_xlb, atom0, abase, warp, lane, nat); break;
    case 5: stage_pool<5>(feat, s_adj, s_xhb, s_xlb, atom0, abase, warp, lane, nat); break;
    case 6: stage_pool<6>(feat, s_adj, s_xhb, s_xlb, atom0, abase, warp, lane, nat); break;
    }
    __syncthreads();

    const int g   = lane >> 2;
    const int tIG = lane & 3;
    const int c0  = (warp & 1) * 64;
    const int row0 = (warp >> 1) * 16 + g;
    const int row1 = row0 + 8;

    float c[8][4];
    #pragma unroll
    for (int nt = 0; nt < 8; nt++) {
        float2 bb = *(const float2*)(b + c0 + nt * 8 + tIG * 2);
        c[nt][0] = bb.x; c[nt][1] = bb.y; c[nt][2] = bb.x; c[nt][3] = bb.y;
    }

    #pragma unroll
    for (int ks = 0; ks < 4; ks++) {
        const int koff = ks * 8 + tIG;
        uint32_t a0h = s_xh[row0 * RSW + koff];
        uint32_t a1h = s_xh[row1 * RSW + koff];
        uint32_t a2h = s_xh[row0 * RSW + koff + 4];
        uint32_t a3h = s_xh[row1 * RSW + koff + 4];
        uint32_t a0l = s_xl[row0 * RSW + koff];
        uint32_t a1l = s_xl[row1 * RSW + koff];
        uint32_t a2l = s_xl[row0 * RSW + koff + 4];
        uint32_t a3l = s_xl[row1 * RSW + koff + 4];
        #pragma unroll
        for (int nt = 0; nt < 8; nt++) {
            const int n = c0 + nt * 8 + g;
            uint32_t b0h = s_wh[n * RSW + koff];
            uint32_t b1h = s_wh[n * RSW + koff + 4];
            uint32_t b0l = s_wl[n * RSW + koff];
            uint32_t b1l = s_wl[n * RSW + koff + 4];
            MMA_BF16(c[nt][0], c[nt][1], c[nt][2], c[nt][3],
                     a0h, a1h, a2h, a3h, b0h, b1h);
            MMA_BF16(c[nt][0], c[nt][1], c[nt][2], c[nt][3],
                     a0h, a1h, a2h, a3h, b0l, b1l);
            MMA_BF16(c[nt][0], c[nt][1], c[nt][2], c[nt][3],
                     a0l, a1l, a2l, a3l, b0h, b1h);
        }
    }

    // epilogue: tanh + bn, then atomic segment sum/max
    const int m0 = (row0 < nat) ? s_mem[row0] : 0;
    const int m1 = (row1 < nat) ? s_mem[row1] : 0;
    #pragma unroll
    for (int nt = 0; nt < 8; nt++) {
        const int n = c0 + nt * 8 + tIG * 2;
        float2 sc2 = *(const float2*)(s_sc + n);
        float2 sh2 = *(const float2*)(s_sh + n);
        if (row0 < nat) {
            float v0 = sc2.x * tanh_fast(c[nt][0]) + sh2.x;
            float v1 = sc2.y * tanh_fast(c[nt][1]) + sh2.y;
            atomicAdd(&gsum[m0 * 128 + n], v0);
            atomicAdd(&gsum[m0 * 128 + n + 1], v1);
            atomicMax(&gmax[m0 * 128 + n], enc_f(v0));
            atomicMax(&gmax[m0 * 128 + n + 1], enc_f(v1));
        }
        if (row1 < nat) {
            float v0 = sc2.x * tanh_fast(c[nt][2]) + sh2.x;
            float v1 = sc2.y * tanh_fast(c[nt][3]) + sh2.y;
            atomicAdd(&gsum[m1 * 128 + n], v0);
            atomicAdd(&gsum[m1 * 128 + n + 1], v1);
            atomicMax(&gmax[m1 * 128 + n], enc_f(v0));
            atomicMax(&gmax[m1 * 128 + n + 1], enc_f(v1));
        }
    }
}

// ================= head =================
__global__ void head_kernel(const float* __restrict__ gsum, const unsigned* __restrict__ gmax,
                            const float* __restrict__ d2W, const float* __restrict__ d2b,
                            const float* __restrict__ d3W, const float* __restrict__ d3b,
                            float* __restrict__ out)
{
    __shared__ float sg[256];
    __shared__ float sred[64];
    const int row = blockIdx.x;
    const int t   = threadIdx.x;  // 64 threads

    for (int k = t; k < 256; k += 64) {
        float v = (k < 128) ? gsum[row * 128 + k] : dec_f(gmax[row * 128 + (k - 128)]);
        sg[k] = tanh_fast(v);
    }
    __syncthreads();

    float acc = d2b[t];
    for (int k = 0; k < 256; k++)
        acc = fmaf(sg[k], d2W[k * 64 + t], acc);
    float s = 1.f / (1.f + expf(-acc));

    sred[t] = s * d3W[t];
    __syncthreads();
    if (t < 32) {
        float x = sred[t] + sred[t + 32];
        #pragma unroll
        for (int off = 16; off; off >>= 1)
            x += __shfl_down_sync(0xffffffffu, x, off);
        if (t == 0) out[row] = x + d3b[0];
    }
}

// ================= launch =================
extern "C" void kernel_launch(void* const* d_in, const int* in_sizes, int n_in,
                              void* d_out, int out_size)
{
    const float* feat       = (const float*)d_in[0];
    const int*   membership = (const int*)d_in[1];
    const int*   adj[6]     = {(const int*)d_in[2], (const int*)d_in[3], (const int*)d_in[4],
                               (const int*)d_in[5], (const int*)d_in[6], (const int*)d_in[7]};
    const float* gc1_Wn = (const float*)d_in[8];
    const float* gc1_Ws = (const float*)d_in[9];
    const float* gc1_b  = (const float*)d_in[10];
    const float* gc2_Wn = (const float*)d_in[11];
    const float* gc2_Ws = (const float*)d_in[12];
    const float* gc2_b  = (const float*)d_in[13];
    const float* bn1g = (const float*)d_in[14];
    const float* bn1b = (const float*)d_in[15];
    const float* bn1m = (const float*)d_in[16];
    const float* bn1v = (const float*)d_in[17];
    const float* bn3g = (const float*)d_in[18];
    const float* bn3b = (const float*)d_in[19];
    const float* bn3m = (const float*)d_in[20];
    const float* bn3v = (const float*)d_in[21];
    const float* d1W = (const float*)d_in[22];
    const float* d1b = (const float*)d_in[23];
    const float* d2W = (const float*)d_in[24];
    const float* d2b = (const float*)d_in[25];
    const float* d3W = (const float*)d_in[26];
    const float* d3b = (const float*)d_in[27];

    float *h1, *h2, *gsum; unsigned* gmax;
    cudaGetSymbolAddress((void**)&h1, g_h1);
    cudaGetSymbolAddress((void**)&h2, g_h2);
    cudaGetSymbolAddress((void**)&gsum, g_gsum);
    cudaGetSymbolAddress((void**)&gmax, g_gmax);

    constexpr int SZ75 = gc_smem_bytes(75);
    constexpr int SZ64 = gc_smem_bytes(64);
    constexpr int SZD1 = d1_smem_bytes();
    static bool attr_set = false;
    if (!attr_set) {
        cudaFuncSetAttribute(gc_mma_all<75>, cudaFuncAttributeMaxDynamicSharedMemorySize, SZ75);
        cudaFuncSetAttribute(gc_mma_all<64>, cudaFuncAttributeMaxDynamicSharedMemorySize, SZ64);
        cudaFuncSetAttribute(d1_mma_all, cudaFuncAttributeMaxDynamicSharedMemorySize, SZD1);
        attr_set = true;
    }

    // ---- weight prep (every call; deterministic) ----
    prep_weights<<<596, 256>>>(gc1_Ws, gc1_Wn, gc2_Ws, gc2_Wn, d1W);

    // ---- gc1 (+tanh +bn1): feat[NA,75] -> h1[NA,64]
    gc_mma_all<75><<<7815, 256, SZ75>>>(feat, adj[0], adj[1], adj[2], adj[3], adj[4], adj[5],
                                        gc1_b, bn1g, bn1b, bn1m, bn1v, h1);

    // ---- pool1: h1 -> h2
    pool_kernel<<<NA * 16 / 256, 256>>>((const float4*)h1, (float4*)h2,
                                        adj[0], adj[1], adj[2], adj[3], adj[4], adj[5]);

    // ---- gc2 (+tanh +bn1): h2[NA,64] -> h1[NA,64]
    gc_mma_all<64><<<7815, 256, SZ64>>>(h2, adj[0], adj[1], adj[2], adj[3], adj[4], adj[5],
                                        gc2_b, bn1g, bn1b, bn1m, bn1v, h1);

    // ---- zero gather accumulators, then fused pool2+dense1(mma)+segment gather
    cudaMemsetAsync(gsum, 0, 1024 * 128 * sizeof(float));
    cudaMemsetAsync(gmax, 0, 1024 * 128 * sizeof(unsigned));
    d1_mma_all<<<7815, 256, SZD1>>>(h1, adj[0], adj[1], adj[2], adj[3], adj[4], adj[5],
                                    membership, d1b, bn3g, bn3b, bn3m, bn3v, gsum, gmax);

    // ---- head
    head_kernel<<<1024, 64>>>(gsum, gmax, d2W, d2b, d3W, d3b, (float*)d_out);
}

// round 11
// speedup vs baseline: 4.0503x; 1.3808x over previous
#include <cuda_runtime.h>
#include <cuda_bf16.h>
#include <cstdint>

// ---------------- problem constants ----------------
#define NA 500000

// ---------------- scratch (device globals; no allocation allowed) ----------------
__device__ float    g_h1[(size_t)NA * 64];
__device__ float    g_h2[(size_t)NA * 64];
__device__ float    g_gsum[1024 * 128];
__device__ unsigned g_gmax[1024 * 128];
// precomputed weight tiles (bf16 hi/lo, transposed, smem image)
__device__ uint32_t g_w1[7 * 4 * 2816];   // gc1: RSW=44
__device__ uint32_t g_w2[7 * 4 * 2304];   // gc2: RSW=36
__device__ uint32_t g_wd[2 * 4608];       // dense1: 128 rows x RSW=36, hi|lo

// ---------------- helpers ----------------
__device__ __forceinline__ unsigned enc_f(float f) {
    unsigned u = __float_as_uint(f);
    return (u >> 31) ? ~u : (u | 0x80000000u);
}
__device__ __forceinline__ float dec_f(unsigned u) {
    return (u >> 31) ? __uint_as_float(u & 0x7FFFFFFFu) : __uint_as_float(~u);
}
__device__ __forceinline__ float tanh_fast(float x) {
    float y;
    asm("tanh.approx.f32 %0, %1;" : "=f"(y) : "f"(x));
    return y;
}

// mma.sync m16n8k16 bf16 -> f32 (sm_80+ baseline PTX; HMMA on sm_103)
#define MMA_BF16(c0,c1,c2,c3,a0,a1,a2,a3,b0,b1) \
    asm volatile("mma.sync.aligned.m16n8k16.row.col.f32.bf16.bf16.f32 " \
        "{%0,%1,%2,%3}, {%4,%5,%6,%7}, {%8,%9}, {%0,%1,%2,%3};" \
        : "+f"(c0), "+f"(c1), "+f"(c2), "+f"(c3) \
        : "r"(a0), "r"(a1), "r"(a2), "r"(a3), "r"(b0), "r"(b1))

__device__ __forceinline__ void split_bf16(float v, __nv_bfloat16& h, __nv_bfloat16& l) {
    h = __float2bfloat16_rn(v);
    l = __float2bfloat16_rn(v - __bfloat162float(h));
}

// ---- geometry ----
__host__ __device__ constexpr int gc_kp(int F)  { return (F == 75) ? 80 : 64; }
__host__ __device__ constexpr int gc_rsw(int F) { return gc_kp(F) / 2 + 4; }   // 44 / 36
__host__ __device__ constexpr int gc_tile(int F) { return 64 * gc_rsw(F); }    // words
__host__ __device__ constexpr int gc_smem_bytes(int F) {
    return 4 * gc_tile(F) * 4 + 64 * 6 * 4 + 2 * 64 * 4;
}
// d1 fused kernel smem: Wh,Wl(128x36) + Xh,Xl(64x36) + adj + mem + sc/sh(128)
__host__ __device__ constexpr int d1_smem_bytes() {
    return (2 * 4608 + 2 * 2304) * 4 + 64 * 6 * 4 + 64 * 4 + 2 * 128 * 4;
}

// ================= weight prep: fp32 -> transposed bf16 hi/lo tiles =================
__global__ void prep_weights(const float* __restrict__ Ws1, const float* __restrict__ Wn1,
                             const float* __restrict__ Ws2, const float* __restrict__ Wn2,
                             const float* __restrict__ Wd)
{
    const int idx = blockIdx.x * 256 + threadIdx.x;
    constexpr int T1 = 7 * 2 * 64 * 88;   // stage1 bf16 elements (RS2=88)
    constexpr int T2 = 7 * 2 * 64 * 72;   // stage2 (RS2=72)
    constexpr int T3 = 128 * 72;          // dense1 (RS2=72)
    if (idx < T1) {
        int k = idx % 88, n = (idx / 88) & 63, part = (idx / (88 * 64)) & 1, d = idx / (88 * 128);
        float w = 0.f;
        if (k < 75) {
            if (part == 0) w = Ws1[(d * 75 + k) * 64 + n];
            else if (d > 0) w = Wn1[((d - 1) * 75 + k) * 64 + n];
        }
        __nv_bfloat16 h, l; split_bf16(w, h, l);
        __nv_bfloat16* th = (__nv_bfloat16*)(g_w1 + d * 4 * 2816 + (part * 2 + 0) * 2816);
        __nv_bfloat16* tl = (__nv_bfloat16*)(g_w1 + d * 4 * 2816 + (part * 2 + 1) * 2816);
        th[n * 88 + k] = h;
        tl[n * 88 + k] = l;
    } else if (idx < T1 + T2) {
        int i2 = idx - T1;
        int k = i2 % 72, n = (i2 / 72) & 63, part = (i2 / (72 * 64)) & 1, d = i2 / (72 * 128);
        float w = 0.f;
        if (k < 64) {
            if (part == 0) w = Ws2[(d * 64 + k) * 64 + n];
            else if (d > 0) w = Wn2[((d - 1) * 64 + k) * 64 + n];
        }
        __nv_bfloat16 h, l; split_bf16(w, h, l);
        __nv_bfloat16* th = (__nv_bfloat16*)(g_w2 + d * 4 * 2304 + (part * 2 + 0) * 2304);
        __nv_bfloat16* tl = (__nv_bfloat16*)(g_w2 + d * 4 * 2304 + (part * 2 + 1) * 2304);
        th[n * 72 + k] = h;
        tl[n * 72 + k] = l;
    } else if (idx < T1 + T2 + T3) {
        int i3 = idx - T1 - T2;
        int k = i3 % 72, n = i3 / 72;   // n in [0,128)
        float w = (k < 64) ? Wd[k * 128 + n] : 0.f;
        __nv_bfloat16 h, l; split_bf16(w, h, l);
        ((__nv_bfloat16*)g_wd)[n * 72 + k] = h;
        ((__nv_bfloat16*)(g_wd + 4608))[n * 72 + k] = l;
    }
}

// ================= staging helpers (batched loads for MLP) =============
// neighbor-sum staging: all NK*D gathers issued into registers before convert/store
template <int F, int D>
__device__ __forceinline__ void stage_sum(
    const float* __restrict__ feat, const int* __restrict__ s_adj,
    __nv_bfloat16* s_xhb, __nv_bfloat16* s_xlb, int warp, int lane, int nat)
{
    constexpr int KP  = gc_kp(F);
    constexpr int RS2 = 2 * gc_rsw(F);
    constexpr int NK  = (KP + 31) / 32;
    #pragma unroll 1
    for (int a = warp; a < 64; a += 8) {
        const bool act = a < nat;
        int nb[D];
        #pragma unroll
        for (int m = 0; m < D; m++) nb[m] = act ? s_adj[a * D + m] : 0;
        float x[NK][D];
        #pragma unroll
        for (int kk = 0; kk < NK; kk++) {
            int k = lane + kk * 32;
            bool ok = act && k < F;
            #pragma unroll
            for (int m = 0; m < D; m++)
                x[kk][m] = ok ? feat[(size_t)nb[m] * F + k] : 0.f;
        }
        #pragma unroll
        for (int kk = 0; kk < NK; kk++) {
            int k = lane + kk * 32;
            if (k < KP) {
                float v = 0.f;
                #pragma unroll
                for (int m = 0; m < D; m++) v += x[kk][m];
                __nv_bfloat16 h, l; split_bf16(v, h, l);
                s_xhb[a * RS2 + k] = h;
                s_xlb[a * RS2 + k] = l;
            }
        }
    }
}

// self staging (batched)
template <int F>
__device__ __forceinline__ void stage_self(
    const float* __restrict__ feat,
    __nv_bfloat16* s_xhb, __nv_bfloat16* s_xlb,
    int atom0, int abase, int warp, int lane, int nat)
{
    constexpr int KP  = gc_kp(F);
    constexpr int RS2 = 2 * gc_rsw(F);
    constexpr int NK  = (KP + 31) / 32;
    #pragma unroll 1
    for (int a = warp; a < 64; a += 8) {
        const float* row = feat + (size_t)(atom0 + abase + a) * F;
        const bool act = a < nat;
        float x[NK];
        #pragma unroll
        for (int kk = 0; kk < NK; kk++) {
            int k = lane + kk * 32;
            x[kk] = (act && k < F) ? row[k] : 0.f;
        }
        #pragma unroll
        for (int kk = 0; kk < NK; kk++) {
            int k = lane + kk * 32;
            if (k < KP) {
                __nv_bfloat16 h, l; split_bf16(x[kk], h, l);
                s_xhb[a * RS2 + k] = h;
                s_xlb[a * RS2 + k] = l;
            }
        }
    }
}

// pooled staging for dense1: X = max(self, neighbors), 64 feats (batched)
template <int D>
__device__ __forceinline__ void stage_pool(
    const float* __restrict__ feat, const int* __restrict__ s_adj,
    __nv_bfloat16* s_xhb, __nv_bfloat16* s_xlb,
    int atom0, int abase, int warp, int lane, int nat)
{
    constexpr int DD = (D > 0) ? D : 1;
    #pragma unroll 1
    for (int a = warp; a < 64; a += 8) {
        const bool act = a < nat;
        int nb[DD];
        #pragma unroll
        for (int m = 0; m < DD; m++)
            nb[m] = (D > 0 && act) ? s_adj[a * D + m] : 0;
        const float* self = feat + (size_t)(atom0 + abase + a) * 64;
        float s[2], x[2][DD];
        #pragma unroll
        for (int kk = 0; kk < 2; kk++) {
            int k = lane + kk * 32;
            s[kk] = act ? self[k] : 0.f;
            if (D > 0) {
                #pragma unroll
                for (int m = 0; m < D; m++)
                    x[kk][m] = act ? feat[(size_t)nb[m] * 64 + k] : 0.f;
            }
        }
        #pragma unroll
        for (int kk = 0; kk < 2; kk++) {
            int k = lane + kk * 32;
            float v = s[kk];
            if (D > 0) {
                #pragma unroll
                for (int m = 0; m < D; m++) v = fmaxf(v, x[kk][m]);
            }
            __nv_bfloat16 h, l; split_bf16(v, h, l);
            s_xhb[a * 72 + k] = h;
            s_xlb[a * 72 + k] = l;
        }
    }
}

// ================= merged graph conv (all degrees, one launch) =======================
template <int F>
__global__ __launch_bounds__(256, F == 75 ? 4 : 5) void gc_mma_all(
    const float* __restrict__ feat,
    const int* __restrict__ a1, const int* __restrict__ a2, const int* __restrict__ a3,
    const int* __restrict__ a4, const int* __restrict__ a5, const int* __restrict__ a6,
    const float* __restrict__ gc_b,   // [7][64]
    const float* __restrict__ bn_g, const float* __restrict__ bn_b,
    const float* __restrict__ bn_m, const float* __restrict__ bn_v,
    float* __restrict__ out)
{
    constexpr int KP   = gc_kp(F);
    constexpr int RSW  = gc_rsw(F);
    constexpr int TILE = gc_tile(F);
    constexpr int OFFS[8] = {0, 20000, 100000, 250000, 400000, 475000, 495000, 500000};
    constexpr int BOFF[8] = {0, 313, 1563, 3907, 6251, 7423, 7736, 7815};

    extern __shared__ uint32_t smem[];
    uint32_t* s_wh = smem;
    uint32_t* s_wl = smem + TILE;
    uint32_t* s_xh = smem + 2 * TILE;
    uint32_t* s_xl = smem + 3 * TILE;
    int*   s_adj = (int*)(smem + 4 * TILE);
    float* s_sc  = (float*)(s_adj + 64 * 6);
    float* s_sh  = s_sc + 64;
    __nv_bfloat16* s_xhb = (__nv_bfloat16*)s_xh;
    __nv_bfloat16* s_xlb = (__nv_bfloat16*)s_xl;

    const int t = threadIdx.x;
    const int lane = t & 31;
    const int warp = t >> 5;

    int d = 0;
    #pragma unroll
    for (int i = 1; i < 7; i++) if ((int)blockIdx.x >= BOFF[i]) d = i;
    const int lblk  = blockIdx.x - BOFF[d];
    const int atom0 = OFFS[d];
    const int cnt   = OFFS[d + 1] - OFFS[d];
    const int abase = lblk * 64;
    const int nat   = min(64, cnt - abase);
    const int* adj = (d == 1) ? a1 : (d == 2) ? a2 : (d == 3) ? a3 :
                     (d == 4) ? a4 : (d == 5) ? a5 : (d == 6) ? a6 : nullptr;
    const uint32_t* wbase = (F == 75 ? g_w1 : g_w2) + d * 4 * TILE;
    const float* bias = gc_b + d * 64;

    if (t < 64) {
        float sc = bn_g[t] * rsqrtf(bn_v[t] + 1e-3f);
        s_sc[t] = sc;
        s_sh[t] = bn_b[t] - bn_m[t] * sc;
    }
    if (d > 0)
        for (int u = t; u < nat * d; u += 256)
            s_adj[u] = adj[abase * d + u];

    // ---- pass 0: W = Ws tiles (uint4 copy), X = self ----
    {
        const uint4* src = (const uint4*)wbase;
        uint4* dh = (uint4*)s_wh;
        uint4* dl = (uint4*)s_wl;
        #pragma unroll 2
        for (int i = t; i < TILE / 4; i += 256) {
            dh[i] = src[i];
            dl[i] = src[i + TILE / 4];
        }
    }
    stage_self<F>(feat, s_xhb, s_xlb, atom0, abase, warp, lane, nat);
    __syncthreads();

    const int g   = lane >> 2;
    const int tIG = lane & 3;
    const int c0  = (warp & 1) * 32;
    const int row0 = (warp >> 1) * 16 + g;
    const int row1 = row0 + 8;

    float c[4][4];
    #pragma unroll
    for (int nt = 0; nt < 4; nt++) {
        float2 bb = *(const float2*)(bias + c0 + nt * 8 + tIG * 2);
        c[nt][0] = bb.x; c[nt][1] = bb.y; c[nt][2] = bb.x; c[nt][3] = bb.y;
    }

    #pragma unroll
    for (int ks = 0; ks < KP / 16; ks++) {
        const int koff = ks * 8 + tIG;
        uint32_t a0h = s_xh[row0 * RSW + koff];
        uint32_t a1h = s_xh[row1 * RSW + koff];
        uint32_t a2h = s_xh[row0 * RSW + koff + 4];
        uint32_t a3h = s_xh[row1 * RSW + koff + 4];
        uint32_t a0l = s_xl[row0 * RSW + koff];
        uint32_t a1l = s_xl[row1 * RSW + koff];
        uint32_t a2l = s_xl[row0 * RSW + koff + 4];
        uint32_t a3l = s_xl[row1 * RSW + koff + 4];
        #pragma unroll
        for (int nt = 0; nt < 4; nt++) {
            const int n = c0 + nt * 8 + g;
            uint32_t b0h = s_wh[n * RSW + koff];
            uint32_t b1h = s_wh[n * RSW + koff + 4];
            uint32_t b0l = s_wl[n * RSW + koff];
            uint32_t b1l = s_wl[n * RSW + koff + 4];
            MMA_BF16(c[nt][0], c[nt][1], c[nt][2], c[nt][3],
                     a0h, a1h, a2h, a3h, b0h, b1h);
            MMA_BF16(c[nt][0], c[nt][1], c[nt][2], c[nt][3],
                     a0h, a1h, a2h, a3h, b0l, b1l);
            MMA_BF16(c[nt][0], c[nt][1], c[nt][2], c[nt][3],
                     a0l, a1l, a2l, a3l, b0h, b1h);
        }
    }

    // ---- pass 1: W = Wn tiles, X = neighbor sums ----
    if (d > 0) {
        __syncthreads();
        {
            const uint4* src = (const uint4*)(wbase + 2 * TILE);
            uint4* dh = (uint4*)s_wh;
            uint4* dl = (uint4*)s_wl;
            #pragma unroll 2
            for (int i = t; i < TILE / 4; i += 256) {
                dh[i] = src[i];
                dl[i] = src[i + TILE / 4];
            }
        }
        switch (d) {
        case 1: stage_sum<F,1>(feat, s_adj, s_xhb, s_xlb, warp, lane, nat); break;
        case 2: stage_sum<F,2>(feat, s_adj, s_xhb, s_xlb, warp, lane, nat); break;
        case 3: stage_sum<F,3>(feat, s_adj, s_xhb, s_xlb, warp, lane, nat); break;
        case 4: stage_sum<F,4>(feat, s_adj, s_xhb, s_xlb, warp, lane, nat); break;
        case 5: stage_sum<F,5>(feat, s_adj, s_xhb, s_xlb, warp, lane, nat); break;
        case 6: stage_sum<F,6>(feat, s_adj, s_xhb, s_xlb, warp, lane, nat); break;
        }
        __syncthreads();

        #pragma unroll
        for (int ks = 0; ks < KP / 16; ks++) {
            const int koff = ks * 8 + tIG;
            uint32_t a0h = s_xh[row0 * RSW + koff];
            uint32_t a1h = s_xh[row1 * RSW + koff];
            uint32_t a2h = s_xh[row0 * RSW + koff + 4];
            uint32_t a3h = s_xh[row1 * RSW + koff + 4];
            uint32_t a0l = s_xl[row0 * RSW + koff];
            uint32_t a1l = s_xl[row1 * RSW + koff];
            uint32_t a2l = s_xl[row0 * RSW + koff + 4];
            uint32_t a3l = s_xl[row1 * RSW + koff + 4];
            #pragma unroll
            for (int nt = 0; nt < 4; nt++) {
                const int n = c0 + nt * 8 + g;
                uint32_t b0h = s_wh[n * RSW + koff];
                uint32_t b1h = s_wh[n * RSW + koff + 4];
                uint32_t b0l = s_wl[n * RSW + koff];
                uint32_t b1l = s_wl[n * RSW + koff + 4];
                MMA_BF16(c[nt][0], c[nt][1], c[nt][2], c[nt][3],
                         a0h, a1h, a2h, a3h, b0h, b1h);
                MMA_BF16(c[nt][0], c[nt][1], c[nt][2], c[nt][3],
                         a0h, a1h, a2h, a3h, b0l, b1l);
                MMA_BF16(c[nt][0], c[nt][1], c[nt][2], c[nt][3],
                         a0l, a1l, a2l, a3l, b0h, b1h);
            }
        }
    }

    // ---- epilogue: tanh + bn + store ----
    #pragma unroll
    for (int nt = 0; nt < 4; nt++) {
        const int n = c0 + nt * 8 + tIG * 2;
        float2 sc2 = *(const float2*)(s_sc + n);
        float2 sh2 = *(const float2*)(s_sh + n);
        if (row0 < nat) {
            float2 o;
            o.x = sc2.x * tanh_fast(c[nt][0]) + sh2.x;
            o.y = sc2.y * tanh_fast(c[nt][1]) + sh2.y;
            *(float2*)(out + (size_t)(atom0 + abase + row0) * 64 + n) = o;
        }
        if (row1 < nat) {
            float2 o;
            o.x = sc2.x * tanh_fast(c[nt][2]) + sh2.x;
            o.y = sc2.y * tanh_fast(c[nt][3]) + sh2.y;
            *(float2*)(out + (size_t)(atom0 + abase + row1) * 64 + n) = o;
        }
    }
}

// ================= graph pool (float4) =================
__global__ __launch_bounds__(256) void pool_kernel(
    const float4* __restrict__ in, float4* __restrict__ out,
    const int* __restrict__ a1, const int* __restrict__ a2,
    const int* __restrict__ a3, const int* __restrict__ a4,
    const int* __restrict__ a5, const int* __restrict__ a6)
{
    int idx  = blockIdx.x * 256 + threadIdx.x;  // NA*16 total
    int atom = idx >> 4;
    int q    = idx & 15;
    float4 v = in[idx];

    if (atom >= 20000) {
        const int* ap; int d, li;
        if      (atom < 100000) { d = 1; ap = a1; li = atom - 20000;  }
        else if (atom < 250000) { d = 2; ap = a2; li = atom - 100000; }
        else if (atom < 400000) { d = 3; ap = a3; li = atom - 250000; }
        else if (atom < 475000) { d = 4; ap = a4; li = atom - 400000; }
        else if (atom < 495000) { d = 5; ap = a5; li = atom - 475000; }
        else                    { d = 6; ap = a6; li = atom - 495000; }
        for (int m = 0; m < d; m++) {
            int nb = ap[li * d + m];
            float4 u = in[nb * 16 + q];
            v.x = fmaxf(v.x, u.x); v.y = fmaxf(v.y, u.y);
            v.z = fmaxf(v.z, u.z); v.w = fmaxf(v.w, u.w);
        }
    }
    out[idx] = v;
}

// ====== fused pool2 + dense1 [64]->[128] via mma (+tanh +bn3) + segment gather ======
__global__ __launch_bounds__(256) void d1_mma_all(
    const float* __restrict__ feat,   // h1 (gc2 output)
    const int* __restrict__ a1, const int* __restrict__ a2, const int* __restrict__ a3,
    const int* __restrict__ a4, const int* __restrict__ a5, const int* __restrict__ a6,
    const int* __restrict__ membership,
    const float* __restrict__ b,      // [128]
    const float* __restrict__ bn_g, const float* __restrict__ bn_b,
    const float* __restrict__ bn_m, const float* __restrict__ bn_v,
    float* __restrict__ gsum, unsigned* __restrict__ gmax)
{
    constexpr int RSW = 36;
    constexpr int XT  = 64 * RSW;     // 2304
    constexpr int WT  = 128 * RSW;    // 4608
    constexpr int OFFS[8] = {0, 20000, 100000, 250000, 400000, 475000, 495000, 500000};
    constexpr int BOFF[8] = {0, 313, 1563, 3907, 6251, 7423, 7736, 7815};

    extern __shared__ uint32_t smem[];
    uint32_t* s_wh = smem;
    uint32_t* s_wl = smem + WT;
    uint32_t* s_xh = smem + 2 * WT;
    uint32_t* s_xl = smem + 2 * WT + XT;
    int*   s_adj = (int*)(smem + 2 * WT + 2 * XT);
    int*   s_mem = s_adj + 64 * 6;
    float* s_sc  = (float*)(s_mem + 64);
    float* s_sh  = s_sc + 128;
    __nv_bfloat16* s_xhb = (__nv_bfloat16*)s_xh;
    __nv_bfloat16* s_xlb = (__nv_bfloat16*)s_xl;

    const int t = threadIdx.x;
    const int lane = t & 31;
    const int warp = t >> 5;

    int d = 0;
    #pragma unroll
    for (int i = 1; i < 7; i++) if ((int)blockIdx.x >= BOFF[i]) d = i;
    const int lblk  = blockIdx.x - BOFF[d];
    const int atom0 = OFFS[d];
    const int cnt   = OFFS[d + 1] - OFFS[d];
    const int abase = lblk * 64;
    const int nat   = min(64, cnt - abase);
    const int* adj = (d == 1) ? a1 : (d == 2) ? a2 : (d == 3) ? a3 :
                     (d == 4) ? a4 : (d == 5) ? a5 : (d == 6) ? a6 : nullptr;

    if (t < 128) {
        float sc = bn_g[t] * rsqrtf(bn_v[t] + 1e-3f);
        s_sc[t] = sc;
        s_sh[t] = bn_b[t] - bn_m[t] * sc;
    }
    if (t < nat) s_mem[t] = membership[atom0 + abase + t];
    if (d > 0)
        for (int u = t; u < nat * d; u += 256)
            s_adj[u] = adj[abase * d + u];

    // W tiles (uint4 copy from precomputed)
    {
        const uint4* src = (const uint4*)g_wd;
        uint4* dh = (uint4*)s_wh;
        uint4* dl = (uint4*)s_wl;
        #pragma unroll 2
        for (int i = t; i < WT / 4; i += 256) {
            dh[i] = src[i];
            dl[i] = src[i + WT / 4];
        }
    }

    // BARRIER: s_adj/s_mem/sc/sh fully written before stage_pool reads them.
    __syncthreads();

    switch (d) {
    case 0: stage_pool<0>(feat, s_adj, s_xhb, s_xlb, atom0, abase, warp, lane, nat); break;
    case 1: stage_pool<1>(feat, s_adj, s_xhb, s_xlb, atom0, abase, warp, lane, nat); break;
    case 2: stage_pool<2>(feat, s_adj, s_xhb, s_xlb, atom0, abase, warp, lane, nat); break;
    case 3: stage_pool<3>(feat, s_adj, s_xhb, s_xlb, atom0, abase, warp, lane, nat); break;
    case 4: stage_pool<4>(feat, s_adj, s_xhb, s_xlb, atom0, abase, warp, lane, nat); break;
    case 5: stage_pool<5>(feat, s_adj, s_xhb, s_xlb, atom0, abase, warp, lane, nat); break;
    case 6: stage_pool<6>(feat, s_adj, s_xhb, s_xlb, atom0, abase, warp, lane, nat); break;
    }
    __syncthreads();

    const int g   = lane >> 2;
    const int tIG = lane & 3;
    const int c0  = (warp & 1) * 64;
    const int row0 = (warp >> 1) * 16 + g;
    const int row1 = row0 + 8;

    float c[8][4];
    #pragma unroll
    for (int nt = 0; nt < 8; nt++) {
        float2 bb = *(const float2*)(b + c0 + nt * 8 + tIG * 2);
        c[nt][0] = bb.x; c[nt][1] = bb.y; c[nt][2] = bb.x; c[nt][3] = bb.y;
    }

    #pragma unroll
    for (int ks = 0; ks < 4; ks++) {
        const int koff = ks * 8 + tIG;
        uint32_t a0h = s_xh[row0 * RSW + koff];
        uint32_t a1h = s_xh[row1 * RSW + koff];
        uint32_t a2h = s_xh[row0 * RSW + koff + 4];
        uint32_t a3h = s_xh[row1 * RSW + koff + 4];
        uint32_t a0l = s_xl[row0 * RSW + koff];
        uint32_t a1l = s_xl[row1 * RSW + koff];
        uint32_t a2l = s_xl[row0 * RSW + koff + 4];
        uint32_t a3l = s_xl[row1 * RSW + koff + 4];
        #pragma unroll
        for (int nt = 0; nt < 8; nt++) {
            const int n = c0 + nt * 8 + g;
            uint32_t b0h = s_wh[n * RSW + koff];
            uint32_t b1h = s_wh[n * RSW + koff + 4];
            uint32_t b0l = s_wl[n * RSW + koff];
            uint32_t b1l = s_wl[n * RSW + koff + 4];
            MMA_BF16(c[nt][0], c[nt][1], c[nt][2], c[nt][3],
                     a0h, a1h, a2h, a3h, b0h, b1h);
            MMA_BF16(c[nt][0], c[nt][1], c[nt][2], c[nt][3],
                     a0h, a1h, a2h, a3h, b0l, b1l);
            MMA_BF16(c[nt][0], c[nt][1], c[nt][2], c[nt][3],
                     a0l, a1l, a2l, a3l, b0h, b1h);
        }
    }

    // epilogue: tanh + bn, then atomic segment sum/max
    const int m0 = (row0 < nat) ? s_mem[row0] : 0;
    const int m1 = (row1 < nat) ? s_mem[row1] : 0;
    #pragma unroll
    for (int nt = 0; nt < 8; nt++) {
        const int n = c0 + nt * 8 + tIG * 2;
        float2 sc2 = *(const float2*)(s_sc + n);
        float2 sh2 = *(const float2*)(s_sh + n);
        if (row0 < nat) {
            float v0 = sc2.x * tanh_fast(c[nt][0]) + sh2.x;
            float v1 = sc2.y * tanh_fast(c[nt][1]) + sh2.y;
            atomicAdd(&gsum[m0 * 128 + n], v0);
            atomicAdd(&gsum[m0 * 128 + n + 1], v1);
            atomicMax(&gmax[m0 * 128 + n], enc_f(v0));
            atomicMax(&gmax[m0 * 128 + n + 1], enc_f(v1));
        }
        if (row1 < nat) {
            float v0 = sc2.x * tanh_fast(c[nt][2]) + sh2.x;
            float v1 = sc2.y * tanh_fast(c[nt][3]) + sh2.y;
            atomicAdd(&gsum[m1 * 128 + n], v0);
            atomicAdd(&gsum[m1 * 128 + n + 1], v1);
            atomicMax(&gmax[m1 * 128 + n], enc_f(v0));
            atomicMax(&gmax[m1 * 128 + n + 1], enc_f(v1));
        }
    }
}

// ================= head =================
__global__ void head_kernel(const float* __restrict__ gsum, const unsigned* __restrict__ gmax,
                            const float* __restrict__ d2W, const float* __restrict__ d2b,
                            const float* __restrict__ d3W, const float* __restrict__ d3b,
                            float* __restrict__ out)
{
    __shared__ float sg[256];
    __shared__ float sred[64];
    const int row = blockIdx.x;
    const int t   = threadIdx.x;  // 64 threads

    for (int k = t; k < 256; k += 64) {
        float v = (k < 128) ? gsum[row * 128 + k] : dec_f(gmax[row * 128 + (k - 128)]);
        sg[k] = tanh_fast(v);
    }
    __syncthreads();

    float acc = d2b[t];
    for (int k = 0; k < 256; k++)
        acc = fmaf(sg[k], d2W[k * 64 + t], acc);
    float s = 1.f / (1.f + expf(-acc));

    sred[t] = s * d3W[t];
    __syncthreads();
    if (t < 32) {
        float x = sred[t] + sred[t + 32];
        #pragma unroll
        for (int off = 16; off; off >>= 1)
            x += __shfl_down_sync(0xffffffffu, x, off);
        if (t == 0) out[row] = x + d3b[0];
    }
}

// ================= launch =================
extern "C" void kernel_launch(void* const* d_in, const int* in_sizes, int n_in,
                              void* d_out, int out_size)
{
    const float* feat       = (const float*)d_in[0];
    const int*   membership = (const int*)d_in[1];
    const int*   adj[6]     = {(const int*)d_in[2], (const int*)d_in[3], (const int*)d_in[4],
                               (const int*)d_in[5], (const int*)d_in[6], (const int*)d_in[7]};
    const float* gc1_Wn = (const float*)d_in[8];
    const float* gc1_Ws = (const float*)d_in[9];
    const float* gc1_b  = (const float*)d_in[10];
    const float* gc2_Wn = (const float*)d_in[11];
    const float* gc2_Ws = (const float*)d_in[12];
    const float* gc2_b  = (const float*)d_in[13];
    const float* bn1g = (const float*)d_in[14];
    const float* bn1b = (const float*)d_in[15];
    const float* bn1m = (const float*)d_in[16];
    const float* bn1v = (const float*)d_in[17];
    const float* bn3g = (const float*)d_in[18];
    const float* bn3b = (const float*)d_in[19];
    const float* bn3m = (const float*)d_in[20];
    const float* bn3v = (const float*)d_in[21];
    const float* d1W = (const float*)d_in[22];
    const float* d1b = (const float*)d_in[23];
    const float* d2W = (const float*)d_in[24];
    const float* d2b = (const float*)d_in[25];
    const float* d3W = (const float*)d_in[26];
    const float* d3b = (const float*)d_in[27];

    float *h1, *h2, *gsum; unsigned* gmax;
    cudaGetSymbolAddress((void**)&h1, g_h1);
    cudaGetSymbolAddress((void**)&h2, g_h2);
    cudaGetSymbolAddress((void**)&gsum, g_gsum);
    cudaGetSymbolAddress((void**)&gmax, g_gmax);

    constexpr int SZ75 = gc_smem_bytes(75);
    constexpr int SZ64 = gc_smem_bytes(64);
    constexpr int SZD1 = d1_smem_bytes();
    static bool attr_set = false;
    if (!attr_set) {
        cudaFuncSetAttribute(gc_mma_all<75>, cudaFuncAttributeMaxDynamicSharedMemorySize, SZ75);
        cudaFuncSetAttribute(gc_mma_all<64>, cudaFuncAttributeMaxDynamicSharedMemorySize, SZ64);
        cudaFuncSetAttribute(d1_mma_all, cudaFuncAttributeMaxDynamicSharedMemorySize, SZD1);
        attr_set = true;
    }

    // ---- weight prep (every call; deterministic) ----
    prep_weights<<<596, 256>>>(gc1_Ws, gc1_Wn, gc2_Ws, gc2_Wn, d1W);

    // ---- gc1 (+tanh +bn1): feat[NA,75] -> h1[NA,64]
    gc_mma_all<75><<<7815, 256, SZ75>>>(feat, adj[0], adj[1], adj[2], adj[3], adj[4], adj[5],
                                        gc1_b, bn1g, bn1b, bn1m, bn1v, h1);

    // ---- pool1: h1 -> h2
    pool_kernel<<<NA * 16 / 256, 256>>>((const float4*)h1, (float4*)h2,
                                        adj[0], adj[1], adj[2], adj[3], adj[4], adj[5]);

    // ---- gc2 (+tanh +bn1): h2[NA,64] -> h1[NA,64]
    gc_mma_all<64><<<7815, 256, SZ64>>>(h2, adj[0], adj[1], adj[2], adj[3], adj[4], adj[5],
                                        gc2_b, bn1g, bn1b, bn1m, bn1v, h1);

    // ---- zero gather accumulators, then fused pool2+dense1(mma)+segment gather
    cudaMemsetAsync(gsum, 0, 1024 * 128 * sizeof(float));
    cudaMemsetAsync(gmax, 0, 1024 * 128 * sizeof(unsigned));
    d1_mma_all<<<7815, 256, SZD1>>>(h1, adj[0], adj[1], adj[2], adj[3], adj[4], adj[5],
                                    membership, d1b, bn3g, bn3b, bn3m, bn3v, gsum, gmax);

    // ---- head
    head_kernel<<<1024, 64>>>(gsum, gmax, d2W, d2b, d3W, d3b, (float*)d_out);
}

// round 12
// speedup vs baseline: 4.0511x; 1.0002x over previous
#include <cuda_runtime.h>
#include <cuda_bf16.h>
#include <cstdint>

// ---------------- problem constants ----------------
#define NA 500000

// ---------------- scratch (device globals; no allocation allowed) ----------------
__device__ float    g_h1[(size_t)NA * 64];
__device__ float    g_h2[(size_t)NA * 64];
__device__ float    g_gsum[1024 * 128];
__device__ unsigned g_gmax[1024 * 128];
// precomputed weight tiles (bf16 hi/lo, transposed, smem image)
__device__ uint32_t g_w1[7 * 4 * 2816];   // gc1: RSW=44
__device__ uint32_t g_w2[7 * 4 * 2304];   // gc2: RSW=36
__device__ uint32_t g_wd[2 * 4608];       // dense1: 128 rows x RSW=36, hi|lo

// ---------------- helpers ----------------
__device__ __forceinline__ unsigned enc_f(float f) {
    unsigned u = __float_as_uint(f);
    return (u >> 31) ? ~u : (u | 0x80000000u);
}
__device__ __forceinline__ float dec_f(unsigned u) {
    return (u >> 31) ? __uint_as_float(u & 0x7FFFFFFFu) : __uint_as_float(~u);
}
__device__ __forceinline__ float tanh_fast(float x) {
    float y;
    asm("tanh.approx.f32 %0, %1;" : "=f"(y) : "f"(x));
    return y;
}

// mma.sync m16n8k16 bf16 -> f32 (sm_80+ baseline PTX; HMMA on sm_103)
#define MMA_BF16(c0,c1,c2,c3,a0,a1,a2,a3,b0,b1) \
    asm volatile("mma.sync.aligned.m16n8k16.row.col.f32.bf16.bf16.f32 " \
        "{%0,%1,%2,%3}, {%4,%5,%6,%7}, {%8,%9}, {%0,%1,%2,%3};" \
        : "+f"(c0), "+f"(c1), "+f"(c2), "+f"(c3) \
        : "r"(a0), "r"(a1), "r"(a2), "r"(a3), "r"(b0), "r"(b1))

__device__ __forceinline__ void split_bf16(float v, __nv_bfloat16& h, __nv_bfloat16& l) {
    h = __float2bfloat16_rn(v);
    l = __float2bfloat16_rn(v - __bfloat162float(h));
}
// pack a float pair into bf16x2 hi and lo words (bit-identical to split_bf16 per elem)
__device__ __forceinline__ void split2(float v0, float v1, uint32_t& hi, uint32_t& lo) {
    __nv_bfloat16 h0 = __float2bfloat16_rn(v0);
    __nv_bfloat16 h1 = __float2bfloat16_rn(v1);
    __nv_bfloat162 hp = __halves2bfloat162(h0, h1);
    __nv_bfloat162 lp = __halves2bfloat162(
        __float2bfloat16_rn(v0 - __bfloat162float(h0)),
        __float2bfloat16_rn(v1 - __bfloat162float(h1)));
    hi = *(uint32_t*)&hp;
    lo = *(uint32_t*)&lp;
}

// ---- geometry ----
__host__ __device__ constexpr int gc_kp(int F)  { return (F == 75) ? 80 : 64; }
__host__ __device__ constexpr int gc_rsw(int F) { return gc_kp(F) / 2 + 4; }   // 44 / 36
__host__ __device__ constexpr int gc_tile(int F) { return 64 * gc_rsw(F); }    // words
__host__ __device__ constexpr int gc_smem_bytes(int F) {
    return 4 * gc_tile(F) * 4 + 64 * 6 * 4 + 2 * 64 * 4;
}
// d1 fused kernel smem: Wh,Wl(128x36) + Xh,Xl(64x36) + adj + mem + sc/sh(128)
__host__ __device__ constexpr int d1_smem_bytes() {
    return (2 * 4608 + 2 * 2304) * 4 + 64 * 6 * 4 + 64 * 4 + 2 * 128 * 4;
}

// ================= weight prep: fp32 -> transposed bf16 hi/lo tiles =================
__global__ void prep_weights(const float* __restrict__ Ws1, const float* __restrict__ Wn1,
                             const float* __restrict__ Ws2, const float* __restrict__ Wn2,
                             const float* __restrict__ Wd)
{
    const int idx = blockIdx.x * 256 + threadIdx.x;
    constexpr int T1 = 7 * 2 * 64 * 88;   // stage1 bf16 elements (RS2=88)
    constexpr int T2 = 7 * 2 * 64 * 72;   // stage2 (RS2=72)
    constexpr int T3 = 128 * 72;          // dense1 (RS2=72)
    if (idx < T1) {
        int k = idx % 88, n = (idx / 88) & 63, part = (idx / (88 * 64)) & 1, d = idx / (88 * 128);
        float w = 0.f;
        if (k < 75) {
            if (part == 0) w = Ws1[(d * 75 + k) * 64 + n];
            else if (d > 0) w = Wn1[((d - 1) * 75 + k) * 64 + n];
        }
        __nv_bfloat16 h, l; split_bf16(w, h, l);
        __nv_bfloat16* th = (__nv_bfloat16*)(g_w1 + d * 4 * 2816 + (part * 2 + 0) * 2816);
        __nv_bfloat16* tl = (__nv_bfloat16*)(g_w1 + d * 4 * 2816 + (part * 2 + 1) * 2816);
        th[n * 88 + k] = h;
        tl[n * 88 + k] = l;
    } else if (idx < T1 + T2) {
        int i2 = idx - T1;
        int k = i2 % 72, n = (i2 / 72) & 63, part = (i2 / (72 * 64)) & 1, d = i2 / (72 * 128);
        float w = 0.f;
        if (k < 64) {
            if (part == 0) w = Ws2[(d * 64 + k) * 64 + n];
            else if (d > 0) w = Wn2[((d - 1) * 64 + k) * 64 + n];
        }
        __nv_bfloat16 h, l; split_bf16(w, h, l);
        __nv_bfloat16* th = (__nv_bfloat16*)(g_w2 + d * 4 * 2304 + (part * 2 + 0) * 2304);
        __nv_bfloat16* tl = (__nv_bfloat16*)(g_w2 + d * 4 * 2304 + (part * 2 + 1) * 2304);
        th[n * 72 + k] = h;
        tl[n * 72 + k] = l;
    } else if (idx < T1 + T2 + T3) {
        int i3 = idx - T1 - T2;
        int k = i3 % 72, n = i3 / 72;   // n in [0,128)
        float w = (k < 64) ? Wd[k * 128 + n] : 0.f;
        __nv_bfloat16 h, l; split_bf16(w, h, l);
        ((__nv_bfloat16*)g_wd)[n * 72 + k] = h;
        ((__nv_bfloat16*)(g_wd + 4608))[n * 72 + k] = l;
    }
}

// ================= staging helpers =============
// ---- F=75 paths (scalar loads, proven round-11 versions) ----
template <int F, int D>
__device__ __forceinline__ void stage_sum(
    const float* __restrict__ feat, const int* __restrict__ s_adj,
    __nv_bfloat16* s_xhb, __nv_bfloat16* s_xlb, int warp, int lane, int nat)
{
    constexpr int KP  = gc_kp(F);
    constexpr int RS2 = 2 * gc_rsw(F);
    constexpr int NK  = (KP + 31) / 32;
    #pragma unroll 1
    for (int a = warp; a < 64; a += 8) {
        const bool act = a < nat;
        int nb[D];
        #pragma unroll
        for (int m = 0; m < D; m++) nb[m] = act ? s_adj[a * D + m] : 0;
        float x[NK][D];
        #pragma unroll
        for (int kk = 0; kk < NK; kk++) {
            int k = lane + kk * 32;
            bool ok = act && k < F;
            #pragma unroll
            for (int m = 0; m < D; m++)
                x[kk][m] = ok ? feat[(size_t)nb[m] * F + k] : 0.f;
        }
        #pragma unroll
        for (int kk = 0; kk < NK; kk++) {
            int k = lane + kk * 32;
            if (k < KP) {
                float v = 0.f;
                #pragma unroll
                for (int m = 0; m < D; m++) v += x[kk][m];
                __nv_bfloat16 h, l; split_bf16(v, h, l);
                s_xhb[a * RS2 + k] = h;
                s_xlb[a * RS2 + k] = l;
            }
        }
    }
}

template <int F>
__device__ __forceinline__ void stage_self(
    const float* __restrict__ feat,
    __nv_bfloat16* s_xhb, __nv_bfloat16* s_xlb,
    int atom0, int abase, int warp, int lane, int nat)
{
    constexpr int KP  = gc_kp(F);
    constexpr int RS2 = 2 * gc_rsw(F);
    constexpr int NK  = (KP + 31) / 32;
    #pragma unroll 1
    for (int a = warp; a < 64; a += 8) {
        const float* row = feat + (size_t)(atom0 + abase + a) * F;
        const bool act = a < nat;
        float x[NK];
        #pragma unroll
        for (int kk = 0; kk < NK; kk++) {
            int k = lane + kk * 32;
            x[kk] = (act && k < F) ? row[k] : 0.f;
        }
        #pragma unroll
        for (int kk = 0; kk < NK; kk++) {
            int k = lane + kk * 32;
            if (k < KP) {
                __nv_bfloat16 h, l; split_bf16(x[kk], h, l);
                s_xhb[a * RS2 + k] = h;
                s_xlb[a * RS2 + k] = l;
            }
        }
    }
}

// ---- F=64 paths (float2 loads, packed 32-bit stores) ----
__device__ __forceinline__ void stage_self64(
    const float* __restrict__ feat, uint32_t* s_xh, uint32_t* s_xl,
    int atom0, int abase, int warp, int lane, int nat)
{
    #pragma unroll 1
    for (int a = warp; a < 64; a += 8) {
        float2 u = make_float2(0.f, 0.f);
        if (a < nat)
            u = *(const float2*)(feat + (size_t)(atom0 + abase + a) * 64 + 2 * lane);
        uint32_t hi, lo; split2(u.x, u.y, hi, lo);
        s_xh[a * 36 + lane] = hi;
        s_xl[a * 36 + lane] = lo;
    }
}

template <int D>
__device__ __forceinline__ void stage_sum64(
    const float* __restrict__ feat, const int* __restrict__ s_adj,
    uint32_t* s_xh, uint32_t* s_xl, int warp, int lane, int nat)
{
    #pragma unroll 1
    for (int a = warp; a < 64; a += 8) {
        const bool act = a < nat;
        int nb[D];
        #pragma unroll
        for (int m = 0; m < D; m++) nb[m] = act ? s_adj[a * D + m] : 0;
        float2 x[D];
        #pragma unroll
        for (int m = 0; m < D; m++)
            x[m] = act ? *(const float2*)(feat + (size_t)nb[m] * 64 + 2 * lane)
                       : make_float2(0.f, 0.f);
        float v0 = 0.f, v1 = 0.f;
        #pragma unroll
        for (int m = 0; m < D; m++) { v0 += x[m].x; v1 += x[m].y; }
        uint32_t hi, lo; split2(v0, v1, hi, lo);
        s_xh[a * 36 + lane] = hi;
        s_xl[a * 36 + lane] = lo;
    }
}

// pooled staging for dense1: X = max(self, neighbors), float2 + packed stores
template <int D>
__device__ __forceinline__ void stage_pool(
    const float* __restrict__ feat, const int* __restrict__ s_adj,
    uint32_t* s_xh, uint32_t* s_xl,
    int atom0, int abase, int warp, int lane, int nat)
{
    constexpr int DD = (D > 0) ? D : 1;
    #pragma unroll 1
    for (int a = warp; a < 64; a += 8) {
        const bool act = a < nat;
        int nb[DD];
        #pragma unroll
        for (int m = 0; m < DD; m++)
            nb[m] = (D > 0 && act) ? s_adj[a * D + m] : 0;
        float2 s = make_float2(0.f, 0.f);
        if (act)
            s = *(const float2*)(feat + (size_t)(atom0 + abase + a) * 64 + 2 * lane);
        if (D > 0) {
            float2 x[DD];
            #pragma unroll
            for (int m = 0; m < D; m++)
                x[m] = act ? *(const float2*)(feat + (size_t)nb[m] * 64 + 2 * lane)
                           : make_float2(0.f, 0.f);
            #pragma unroll
            for (int m = 0; m < D; m++) {
                s.x = fmaxf(s.x, x[m].x);
                s.y = fmaxf(s.y, x[m].y);
            }
        }
        uint32_t hi, lo; split2(s.x, s.y, hi, lo);
        s_xh[a * 36 + lane] = hi;
        s_xl[a * 36 + lane] = lo;
    }
}

// ================= merged graph conv (all degrees, one launch) =======================
template <int F>
__global__ __launch_bounds__(256, F == 75 ? 4 : 5) void gc_mma_all(
    const float* __restrict__ feat,
    const int* __restrict__ a1, const int* __restrict__ a2, const int* __restrict__ a3,
    const int* __restrict__ a4, const int* __restrict__ a5, const int* __restrict__ a6,
    const float* __restrict__ gc_b,   // [7][64]
    const float* __restrict__ bn_g, const float* __restrict__ bn_b,
    const float* __restrict__ bn_m, const float* __restrict__ bn_v,
    float* __restrict__ out)
{
    constexpr int KP   = gc_kp(F);
    constexpr int RSW  = gc_rsw(F);
    constexpr int TILE = gc_tile(F);
    constexpr int OFFS[8] = {0, 20000, 100000, 250000, 400000, 475000, 495000, 500000};
    constexpr int BOFF[8] = {0, 313, 1563, 3907, 6251, 7423, 7736, 7815};

    extern __shared__ uint32_t smem[];
    uint32_t* s_wh = smem;
    uint32_t* s_wl = smem + TILE;
    uint32_t* s_xh = smem + 2 * TILE;
    uint32_t* s_xl = smem + 3 * TILE;
    int*   s_adj = (int*)(smem + 4 * TILE);
    float* s_sc  = (float*)(s_adj + 64 * 6);
    float* s_sh  = s_sc + 64;
    __nv_bfloat16* s_xhb = (__nv_bfloat16*)s_xh;
    __nv_bfloat16* s_xlb = (__nv_bfloat16*)s_xl;

    const int t = threadIdx.x;
    const int lane = t & 31;
    const int warp = t >> 5;

    int d = 0;
    #pragma unroll
    for (int i = 1; i < 7; i++) if ((int)blockIdx.x >= BOFF[i]) d = i;
    const int lblk  = blockIdx.x - BOFF[d];
    const int atom0 = OFFS[d];
    const int cnt   = OFFS[d + 1] - OFFS[d];
    const int abase = lblk * 64;
    const int nat   = min(64, cnt - abase);
    const int* adj = (d == 1) ? a1 : (d == 2) ? a2 : (d == 3) ? a3 :
                     (d == 4) ? a4 : (d == 5) ? a5 : (d == 6) ? a6 : nullptr;
    const uint32_t* wbase = (F == 75 ? g_w1 : g_w2) + d * 4 * TILE;
    const float* bias = gc_b + d * 64;

    if (t < 64) {
        float sc = bn_g[t] * rsqrtf(bn_v[t] + 1e-3f);
        s_sc[t] = sc;
        s_sh[t] = bn_b[t] - bn_m[t] * sc;
    }
    if (d > 0)
        for (int u = t; u < nat * d; u += 256)
            s_adj[u] = adj[abase * d + u];

    // ---- pass 0: W = Ws tiles (uint4 copy), X = self ----
    {
        const uint4* src = (const uint4*)wbase;
        uint4* dh = (uint4*)s_wh;
        uint4* dl = (uint4*)s_wl;
        #pragma unroll 2
        for (int i = t; i < TILE / 4; i += 256) {
            dh[i] = src[i];
            dl[i] = src[i + TILE / 4];
        }
    }
    if constexpr (F == 64)
        stage_self64(feat, s_xh, s_xl, atom0, abase, warp, lane, nat);
    else
        stage_self<F>(feat, s_xhb, s_xlb, atom0, abase, warp, lane, nat);
    __syncthreads();

    const int g   = lane >> 2;
    const int tIG = lane & 3;
    const int c0  = (warp & 1) * 32;
    const int row0 = (warp >> 1) * 16 + g;
    const int row1 = row0 + 8;

    float c[4][4];
    #pragma unroll
    for (int nt = 0; nt < 4; nt++) {
        float2 bb = *(const float2*)(bias + c0 + nt * 8 + tIG * 2);
        c[nt][0] = bb.x; c[nt][1] = bb.y; c[nt][2] = bb.x; c[nt][3] = bb.y;
    }

    #pragma unroll
    for (int ks = 0; ks < KP / 16; ks++) {
        const int koff = ks * 8 + tIG;
        uint32_t a0h = s_xh[row0 * RSW + koff];
        uint32_t a1h = s_xh[row1 * RSW + koff];
        uint32_t a2h = s_xh[row0 * RSW + koff + 4];
        uint32_t a3h = s_xh[row1 * RSW + koff + 4];
        uint32_t a0l = s_xl[row0 * RSW + koff];
        uint32_t a1l = s_xl[row1 * RSW + koff];
        uint32_t a2l = s_xl[row0 * RSW + koff + 4];
        uint32_t a3l = s_xl[row1 * RSW + koff + 4];
        #pragma unroll
        for (int nt = 0; nt < 4; nt++) {
            const int n = c0 + nt * 8 + g;
            uint32_t b0h = s_wh[n * RSW + koff];
            uint32_t b1h = s_wh[n * RSW + koff + 4];
            uint32_t b0l = s_wl[n * RSW + koff];
            uint32_t b1l = s_wl[n * RSW + koff + 4];
            MMA_BF16(c[nt][0], c[nt][1], c[nt][2], c[nt][3],
                     a0h, a1h, a2h, a3h, b0h, b1h);
            MMA_BF16(c[nt][0], c[nt][1], c[nt][2], c[nt][3],
                     a0h, a1h, a2h, a3h, b0l, b1l);
            MMA_BF16(c[nt][0], c[nt][1], c[nt][2], c[nt][3],
                     a0l, a1l, a2l, a3l, b0h, b1h);
        }
    }

    // ---- pass 1: W = Wn tiles, X = neighbor sums ----
    if (d > 0) {
        __syncthreads();
        {
            const uint4* src = (const uint4*)(wbase + 2 * TILE);
            uint4* dh = (uint4*)s_wh;
            uint4* dl = (uint4*)s_wl;
            #pragma unroll 2
            for (int i = t; i < TILE / 4; i += 256) {
                dh[i] = src[i];
                dl[i] = src[i + TILE / 4];
            }
        }
        if constexpr (F == 64) {
            switch (d) {
            case 1: stage_sum64<1>(feat, s_adj, s_xh, s_xl, warp, lane, nat); break;
            case 2: stage_sum64<2>(feat, s_adj, s_xh, s_xl, warp, lane, nat); break;
            case 3: stage_sum64<3>(feat, s_adj, s_xh, s_xl, warp, lane, nat); break;
            case 4: stage_sum64<4>(feat, s_adj, s_xh, s_xl, warp, lane, nat); break;
            case 5: stage_sum64<5>(feat, s_adj, s_xh, s_xl, warp, lane, nat); break;
            case 6: stage_sum64<6>(feat, s_adj, s_xh, s_xl, warp, lane, nat); break;
            }
        } else {
            switch (d) {
            case 1: stage_sum<F,1>(feat, s_adj, s_xhb, s_xlb, warp, lane, nat); break;
            case 2: stage_sum<F,2>(feat, s_adj, s_xhb, s_xlb, warp, lane, nat); break;
            case 3: stage_sum<F,3>(feat, s_adj, s_xhb, s_xlb, warp, lane, nat); break;
            case 4: stage_sum<F,4>(feat, s_adj, s_xhb, s_xlb, warp, lane, nat); break;
            case 5: stage_sum<F,5>(feat, s_adj, s_xhb, s_xlb, warp, lane, nat); break;
            case 6: stage_sum<F,6>(feat, s_adj, s_xhb, s_xlb, warp, lane, nat); break;
            }
        }
        __syncthreads();

        #pragma unroll
        for (int ks = 0; ks < KP / 16; ks++) {
            const int koff = ks * 8 + tIG;
            uint32_t a0h = s_xh[row0 * RSW + koff];
            uint32_t a1h = s_xh[row1 * RSW + koff];
            uint32_t a2h = s_xh[row0 * RSW + koff + 4];
            uint32_t a3h = s_xh[row1 * RSW + koff + 4];
            uint32_t a0l = s_xl[row0 * RSW + koff];
            uint32_t a1l = s_xl[row1 * RSW + koff];
            uint32_t a2l = s_xl[row0 * RSW + koff + 4];
            uint32_t a3l = s_xl[row1 * RSW + koff + 4];
            #pragma unroll
            for (int nt = 0; nt < 4; nt++) {
                const int n = c0 + nt * 8 + g;
                uint32_t b0h = s_wh[n * RSW + koff];
                uint32_t b1h = s_wh[n * RSW + koff + 4];
                uint32_t b0l = s_wl[n * RSW + koff];
                uint32_t b1l = s_wl[n * RSW + koff + 4];
                MMA_BF16(c[nt][0], c[nt][1], c[nt][2], c[nt][3],
                         a0h, a1h, a2h, a3h, b0h, b1h);
                MMA_BF16(c[nt][0], c[nt][1], c[nt][2], c[nt][3],
                         a0h, a1h, a2h, a3h, b0l, b1l);
                MMA_BF16(c[nt][0], c[nt][1], c[nt][2], c[nt][3],
                         a0l, a1l, a2l, a3l, b0h, b1h);
            }
        }
    }

    // ---- epilogue: tanh + bn + store ----
    #pragma unroll
    for (int nt = 0; nt < 4; nt++) {
        const int n = c0 + nt * 8 + tIG * 2;
        float2 sc2 = *(const float2*)(s_sc + n);
        float2 sh2 = *(const float2*)(s_sh + n);
        if (row0 < nat) {
            float2 o;
            o.x = sc2.x * tanh_fast(c[nt][0]) + sh2.x;
            o.y = sc2.y * tanh_fast(c[nt][1]) + sh2.y;
            *(float2*)(out + (size_t)(atom0 + abase + row0) * 64 + n) = o;
        }
        if (row1 < nat) {
            float2 o;
            o.x = sc2.x * tanh_fast(c[nt][2]) + sh2.x;
            o.y = sc2.y * tanh_fast(c[nt][3]) + sh2.y;
            *(float2*)(out + (size_t)(atom0 + abase + row1) * 64 + n) = o;
        }
    }
}

// ================= graph pool (float4) =================
__global__ __launch_bounds__(256) void pool_kernel(
    const float4* __restrict__ in, float4* __restrict__ out,
    const int* __restrict__ a1, const int* __restrict__ a2,
    const int* __restrict__ a3, const int* __restrict__ a4,
    const int* __restrict__ a5, const int* __restrict__ a6)
{
    int idx  = blockIdx.x * 256 + threadIdx.x;  // NA*16 total
    int atom = idx >> 4;
    int q    = idx & 15;
    float4 v = in[idx];

    if (atom >= 20000) {
        const int* ap; int d, li;
        if      (atom < 100000) { d = 1; ap = a1; li = atom - 20000;  }
        else if (atom < 250000) { d = 2; ap = a2; li = atom - 100000; }
        else if (atom < 400000) { d = 3; ap = a3; li = atom - 250000; }
        else if (atom < 475000) { d = 4; ap = a4; li = atom - 400000; }
        else if (atom < 495000) { d = 5; ap = a5; li = atom - 475000; }
        else                    { d = 6; ap = a6; li = atom - 495000; }
        for (int m = 0; m < d; m++) {
            int nb = ap[li * d + m];
            float4 u = in[nb * 16 + q];
            v.x = fmaxf(v.x, u.x); v.y = fmaxf(v.y, u.y);
            v.z = fmaxf(v.z, u.z); v.w = fmaxf(v.w, u.w);
        }
    }
    out[idx] = v;
}

// ====== fused pool2 + dense1 [64]->[128] via mma (+tanh +bn3) + segment gather ======
__global__ __launch_bounds__(256) void d1_mma_all(
    const float* __restrict__ feat,   // h1 (gc2 output)
    const int* __restrict__ a1, const int* __restrict__ a2, const int* __restrict__ a3,
    const int* __restrict__ a4, const int* __restrict__ a5, const int* __restrict__ a6,
    const int* __restrict__ membership,
    const float* __restrict__ b,      // [128]
    const float* __restrict__ bn_g, const float* __restrict__ bn_b,
    const float* __restrict__ bn_m, const float* __restrict__ bn_v,
    float* __restrict__ gsum, unsigned* __restrict__ gmax)
{
    constexpr int RSW = 36;
    constexpr int XT  = 64 * RSW;     // 2304
    constexpr int WT  = 128 * RSW;    // 4608
    constexpr int OFFS[8] = {0, 20000, 100000, 250000, 400000, 475000, 495000, 500000};
    constexpr int BOFF[8] = {0, 313, 1563, 3907, 6251, 7423, 7736, 7815};

    extern __shared__ uint32_t smem[];
    uint32_t* s_wh = smem;
    uint32_t* s_wl = smem + WT;
    uint32_t* s_xh = smem + 2 * WT;
    uint32_t* s_xl = smem + 2 * WT + XT;
    int*   s_adj = (int*)(smem + 2 * WT + 2 * XT);
    int*   s_mem = s_adj + 64 * 6;
    float* s_sc  = (float*)(s_mem + 64);
    float* s_sh  = s_sc + 128;

    const int t = threadIdx.x;
    const int lane = t & 31;
    const int warp = t >> 5;

    int d = 0;
    #pragma unroll
    for (int i = 1; i < 7; i++) if ((int)blockIdx.x >= BOFF[i]) d = i;
    const int lblk  = blockIdx.x - BOFF[d];
    const int atom0 = OFFS[d];
    const int cnt   = OFFS[d + 1] - OFFS[d];
    const int abase = lblk * 64;
    const int nat   = min(64, cnt - abase);
    const int* adj = (d == 1) ? a1 : (d == 2) ? a2 : (d == 3) ? a3 :
                     (d == 4) ? a4 : (d == 5) ? a5 : (d == 6) ? a6 : nullptr;

    if (t < 128) {
        float sc = bn_g[t] * rsqrtf(bn_v[t] + 1e-3f);
        s_sc[t] = sc;
        s_sh[t] = bn_b[t] - bn_m[t] * sc;
    }
    if (t < nat) s_mem[t] = membership[atom0 + abase + t];
    if (d > 0)
        for (int u = t; u < nat * d; u += 256)
            s_adj[u] = adj[abase * d + u];

    // W tiles (uint4 copy from precomputed)
    {
        const uint4* src = (const uint4*)g_wd;
        uint4* dh = (uint4*)s_wh;
        uint4* dl = (uint4*)s_wl;
        #pragma unroll 2
        for (int i = t; i < WT / 4; i += 256) {
            dh[i] = src[i];
            dl[i] = src[i + WT / 4];
        }
    }

    // BARRIER: s_adj/s_mem/sc/sh fully written before stage_pool reads them.
    __syncthreads();

    switch (d) {
    case 0: stage_pool<0>(feat, s_adj, s_xh, s_xl, atom0, abase, warp, lane, nat); break;
    case 1: stage_pool<1>(feat, s_adj, s_xh, s_xl, atom0, abase, warp, lane, nat); break;
    case 2: stage_pool<2>(feat, s_adj, s_xh, s_xl, atom0, abase, warp, lane, nat); break;
    case 3: stage_pool<3>(feat, s_adj, s_xh, s_xl, atom0, abase, warp, lane, nat); break;
    case 4: stage_pool<4>(feat, s_adj, s_xh, s_xl, atom0, abase, warp, lane, nat); break;
    case 5: stage_pool<5>(feat, s_adj, s_xh, s_xl, atom0, abase, warp, lane, nat); break;
    case 6: stage_pool<6>(feat, s_adj, s_xh, s_xl, atom0, abase, warp, lane, nat); break;
    }
    __syncthreads();

    const int g   = lane >> 2;
    const int tIG = lane & 3;
    const int c0  = (warp & 1) * 64;
    const int row0 = (warp >> 1) * 16 + g;
    const int row1 = row0 + 8;

    float c[8][4];
    #pragma unroll
    for (int nt = 0; nt < 8; nt++) {
        float2 bb = *(const float2*)(b + c0 + nt * 8 + tIG * 2);
        c[nt][0] = bb.x; c[nt][1] = bb.y; c[nt][2] = bb.x; c[nt][3] = bb.y;
    }

    #pragma unroll
    for (int ks = 0; ks < 4; ks++) {
        const int koff = ks * 8 + tIG;
        uint32_t a0h = s_xh[row0 * RSW + koff];
        uint32_t a1h = s_xh[row1 * RSW + koff];
        uint32_t a2h = s_xh[row0 * RSW + koff + 4];
        uint32_t a3h = s_xh[row1 * RSW + koff + 4];
        uint32_t a0l = s_xl[row0 * RSW + koff];
        uint32_t a1l = s_xl[row1 * RSW + koff];
        uint32_t a2l = s_xl[row0 * RSW + koff + 4];
        uint32_t a3l = s_xl[row1 * RSW + koff + 4];
        #pragma unroll
        for (int nt = 0; nt < 8; nt++) {
            const int n = c0 + nt * 8 + g;
            uint32_t b0h = s_wh[n * RSW + koff];
            uint32_t b1h = s_wh[n * RSW + koff + 4];
            uint32_t b0l = s_wl[n * RSW + koff];
            uint32_t b1l = s_wl[n * RSW + koff + 4];
            MMA_BF16(c[nt][0], c[nt][1], c[nt][2], c[nt][3],
                     a0h, a1h, a2h, a3h, b0h, b1h);
            MMA_BF16(c[nt][0], c[nt][1], c[nt][2], c[nt][3],
                     a0h, a1h, a2h, a3h, b0l, b1l);
            MMA_BF16(c[nt][0], c[nt][1], c[nt][2], c[nt][3],
                     a0l, a1l, a2l, a3l, b0h, b1h);
        }
    }

    // epilogue: tanh + bn, then atomic segment sum/max
    const int m0 = (row0 < nat) ? s_mem[row0] : 0;
    const int m1 = (row1 < nat) ? s_mem[row1] : 0;
    #pragma unroll
    for (int nt = 0; nt < 8; nt++) {
        const int n = c0 + nt * 8 + tIG * 2;
        float2 sc2 = *(const float2*)(s_sc + n);
        float2 sh2 = *(const float2*)(s_sh + n);
        if (row0 < nat) {
            float v0 = sc2.x * tanh_fast(c[nt][0]) + sh2.x;
            float v1 = sc2.y * tanh_fast(c[nt][1]) + sh2.y;
            atomicAdd(&gsum[m0 * 128 + n], v0);
            atomicAdd(&gsum[m0 * 128 + n + 1], v1);
            atomicMax(&gmax[m0 * 128 + n], enc_f(v0));
            atomicMax(&gmax[m0 * 128 + n + 1], enc_f(v1));
        }
        if (row1 < nat) {
            float v0 = sc2.x * tanh_fast(c[nt][2]) + sh2.x;
            float v1 = sc2.y * tanh_fast(c[nt][3]) + sh2.y;
            atomicAdd(&gsum[m1 * 128 + n], v0);
            atomicAdd(&gsum[m1 * 128 + n + 1], v1);
            atomicMax(&gmax[m1 * 128 + n], enc_f(v0));
            atomicMax(&gmax[m1 * 128 + n + 1], enc_f(v1));
        }
    }
}

// ================= head =================
__global__ void head_kernel(const float* __restrict__ gsum, const unsigned* __restrict__ gmax,
                            const float* __restrict__ d2W, const float* __restrict__ d2b,
                            const float* __restrict__ d3W, const float* __restrict__ d3b,
                            float* __restrict__ out)
{
    __shared__ float sg[256];
    __shared__ float sred[64];
    const int row = blockIdx.x;
    const int t   = threadIdx.x;  // 64 threads

    for (int k = t; k < 256; k += 64) {
        float v = (k < 128) ? gsum[row * 128 + k] : dec_f(gmax[row * 128 + (k - 128)]);
        sg[k] = tanh_fast(v);
    }
    __syncthreads();

    float acc = d2b[t];
    for (int k = 0; k < 256; k++)
        acc = fmaf(sg[k], d2W[k * 64 + t], acc);
    float s = 1.f / (1.f + expf(-acc));

    sred[t] = s * d3W[t];
    __syncthreads();
    if (t < 32) {
        float x = sred[t] + sred[t + 32];
        #pragma unroll
        for (int off = 16; off; off >>= 1)
            x += __shfl_down_sync(0xffffffffu, x, off);
        if (t == 0) out[row] = x + d3b[0];
    }
}

// ================= launch =================
extern "C" void kernel_launch(void* const* d_in, const int* in_sizes, int n_in,
                              void* d_out, int out_size)
{
    const float* feat       = (const float*)d_in[0];
    const int*   membership = (const int*)d_in[1];
    const int*   adj[6]     = {(const int*)d_in[2], (const int*)d_in[3], (const int*)d_in[4],
                               (const int*)d_in[5], (const int*)d_in[6], (const int*)d_in[7]};
    const float* gc1_Wn = (const float*)d_in[8];
    const float* gc1_Ws = (const float*)d_in[9];
    const float* gc1_b  = (const float*)d_in[10];
    const float* gc2_Wn = (const float*)d_in[11];
    const float* gc2_Ws = (const float*)d_in[12];
    const float* gc2_b  = (const float*)d_in[13];
    const float* bn1g = (const float*)d_in[14];
    const float* bn1b = (const float*)d_in[15];
    const float* bn1m = (const float*)d_in[16];
    const float* bn1v = (const float*)d_in[17];
    const float* bn3g = (const float*)d_in[18];
    const float* bn3b = (const float*)d_in[19];
    const float* bn3m = (const float*)d_in[20];
    const float* bn3v = (const float*)d_in[21];
    const float* d1W = (const float*)d_in[22];
    const float* d1b = (const float*)d_in[23];
    const float* d2W = (const float*)d_in[24];
    const float* d2b = (const float*)d_in[25];
    const float* d3W = (const float*)d_in[26];
    const float* d3b = (const float*)d_in[27];

    float *h1, *h2, *gsum; unsigned* gmax;
    cudaGetSymbolAddress((void**)&h1, g_h1);
    cudaGetSymbolAddress((void**)&h2, g_h2);
    cudaGetSymbolAddress((void**)&gsum, g_gsum);
    cudaGetSymbolAddress((void**)&gmax, g_gmax);

    constexpr int SZ75 = gc_smem_bytes(75);
    constexpr int SZ64 = gc_smem_bytes(64);
    constexpr int SZD1 = d1_smem_bytes();
    static bool attr_set = false;
    if (!attr_set) {
        cudaFuncSetAttribute(gc_mma_all<75>, cudaFuncAttributeMaxDynamicSharedMemorySize, SZ75);
        cudaFuncSetAttribute(gc_mma_all<64>, cudaFuncAttributeMaxDynamicSharedMemorySize, SZ64);
        cudaFuncSetAttribute(d1_mma_all, cudaFuncAttributeMaxDynamicSharedMemorySize, SZD1);
        attr_set = true;
    }

    // ---- weight prep (every call; deterministic) ----
    prep_weights<<<596, 256>>>(gc1_Ws, gc1_Wn, gc2_Ws, gc2_Wn, d1W);

    // ---- gc1 (+tanh +bn1): feat[NA,75] -> h1[NA,64]
    gc_mma_all<75><<<7815, 256, SZ75>>>(feat, adj[0], adj[1], adj[2], adj[3], adj[4], adj[5],
                                        gc1_b, bn1g, bn1b, bn1m, bn1v, h1);

    // ---- pool1: h1 -> h2
    pool_kernel<<<NA * 16 / 256, 256>>>((const float4*)h1, (float4*)h2,
                                        adj[0], adj[1], adj[2], adj[3], adj[4], adj[5]);

    // ---- gc2 (+tanh +bn1): h2[NA,64] -> h1[NA,64]
    gc_mma_all<64><<<7815, 256, SZ64>>>(h2, adj[0], adj[1], adj[2], adj[3], adj[4], adj[5],
                                        gc2_b, bn1g, bn1b, bn1m, bn1v, h1);

    // ---- zero gather accumulators, then fused pool2+dense1(mma)+segment gather
    cudaMemsetAsync(gsum, 0, 1024 * 128 * sizeof(float));
    cudaMemsetAsync(gmax, 0, 1024 * 128 * sizeof(unsigned));
    d1_mma_all<<<7815, 256, SZD1>>>(h1, adj[0], adj[1], adj[2], adj[3], adj[4], adj[5],
                                    membership, d1b, bn3g, bn3b, bn3m, bn3v, gsum, gmax);

    // ---- head
    head_kernel<<<1024, 64>>>(gsum, gmax, d2W, d2b, d3W, d3b, (float*)d_out);
}

// round 13
// speedup vs baseline: 4.5653x; 1.1269x over previous
#include <cuda_runtime.h>
#include <cuda_bf16.h>
#include <cstdint>

// ---------------- problem constants ----------------
#define NA 500000

// ---------------- scratch (device globals; no allocation allowed) ----------------
__device__ float    g_h1[(size_t)NA * 64];
__device__ float    g_h2[(size_t)NA * 64];
__device__ float    g_gsum[1024 * 128];
__device__ unsigned g_gmax[1024 * 128];
// precomputed weight tiles (bf16 hi/lo, transposed, smem image)
__device__ uint32_t g_w1[7 * 4 * 2816];   // gc1: RSW=44
__device__ uint32_t g_w2[7 * 4 * 2304];   // gc2: RSW=36
__device__ uint32_t g_wd[2 * 4608];       // dense1: 128 rows x RSW=36, hi|lo

// ---------------- helpers ----------------
__device__ __forceinline__ unsigned enc_f(float f) {
    unsigned u = __float_as_uint(f);
    return (u >> 31) ? ~u : (u | 0x80000000u);
}
__device__ __forceinline__ float dec_f(unsigned u) {
    return (u >> 31) ? __uint_as_float(u & 0x7FFFFFFFu) : __uint_as_float(~u);
}
__device__ __forceinline__ float tanh_fast(float x) {
    float y;
    asm("tanh.approx.f32 %0, %1;" : "=f"(y) : "f"(x));
    return y;
}

// mma.sync m16n8k16 bf16 -> f32 (sm_80+ baseline PTX; HMMA on sm_103)
#define MMA_BF16(c0,c1,c2,c3,a0,a1,a2,a3,b0,b1) \
    asm volatile("mma.sync.aligned.m16n8k16.row.col.f32.bf16.bf16.f32 " \
        "{%0,%1,%2,%3}, {%4,%5,%6,%7}, {%8,%9}, {%0,%1,%2,%3};" \
        : "+f"(c0), "+f"(c1), "+f"(c2), "+f"(c3) \
        : "r"(a0), "r"(a1), "r"(a2), "r"(a3), "r"(b0), "r"(b1))

__device__ __forceinline__ void split_bf16(float v, __nv_bfloat16& h, __nv_bfloat16& l) {
    h = __float2bfloat16_rn(v);
    l = __float2bfloat16_rn(v - __bfloat162float(h));
}
// pack a float pair into bf16x2 hi and lo words (bit-identical to split_bf16 per elem)
__device__ __forceinline__ void split2(float v0, float v1, uint32_t& hi, uint32_t& lo) {
    __nv_bfloat16 h0 = __float2bfloat16_rn(v0);
    __nv_bfloat16 h1 = __float2bfloat16_rn(v1);
    __nv_bfloat162 hp = __halves2bfloat162(h0, h1);
    __nv_bfloat162 lp = __halves2bfloat162(
        __float2bfloat16_rn(v0 - __bfloat162float(h0)),
        __float2bfloat16_rn(v1 - __bfloat162float(h1)));
    hi = *(uint32_t*)&hp;
    lo = *(uint32_t*)&lp;
}

// ---- geometry ----
__host__ __device__ constexpr int gc_kp(int F)  { return (F == 75) ? 80 : 64; }
__host__ __device__ constexpr int gc_rsw(int F) { return gc_kp(F) / 2 + 4; }   // 44 / 36
__host__ __device__ constexpr int gc_tile(int F) { return 64 * gc_rsw(F); }    // words
__host__ __device__ constexpr int gc_smem_bytes(int F) {
    return 4 * gc_tile(F) * 4 + 64 * 6 * 4 + 2 * 64 * 4;
}
// d1 fused kernel smem: Wh,Wl(128x36) + Xh,Xl(64x36) + adj + mem + sc/sh(128)
__host__ __device__ constexpr int d1_smem_bytes() {
    return (2 * 4608 + 2 * 2304) * 4 + 64 * 6 * 4 + 64 * 4 + 2 * 128 * 4;
}

// ================= weight prep: fp32 -> transposed bf16 hi/lo tiles =================
__global__ void prep_weights(const float* __restrict__ Ws1, const float* __restrict__ Wn1,
                             const float* __restrict__ Ws2, const float* __restrict__ Wn2,
                             const float* __restrict__ Wd)
{
    const int idx = blockIdx.x * 256 + threadIdx.x;
    constexpr int T1 = 7 * 2 * 64 * 88;   // stage1 bf16 elements (RS2=88)
    constexpr int T2 = 7 * 2 * 64 * 72;   // stage2 (RS2=72)
    constexpr int T3 = 128 * 72;          // dense1 (RS2=72)
    if (idx < T1) {
        int k = idx % 88, n = (idx / 88) & 63, part = (idx / (88 * 64)) & 1, d = idx / (88 * 128);
        float w = 0.f;
        if (k < 75) {
            if (part == 0) w = Ws1[(d * 75 + k) * 64 + n];
            else if (d > 0) w = Wn1[((d - 1) * 75 + k) * 64 + n];
        }
        __nv_bfloat16 h, l; split_bf16(w, h, l);
        __nv_bfloat16* th = (__nv_bfloat16*)(g_w1 + d * 4 * 2816 + (part * 2 + 0) * 2816);
        __nv_bfloat16* tl = (__nv_bfloat16*)(g_w1 + d * 4 * 2816 + (part * 2 + 1) * 2816);
        th[n * 88 + k] = h;
        tl[n * 88 + k] = l;
    } else if (idx < T1 + T2) {
        int i2 = idx - T1;
        int k = i2 % 72, n = (i2 / 72) & 63, part = (i2 / (72 * 64)) & 1, d = i2 / (72 * 128);
        float w = 0.f;
        if (k < 64) {
            if (part == 0) w = Ws2[(d * 64 + k) * 64 + n];
            else if (d > 0) w = Wn2[((d - 1) * 64 + k) * 64 + n];
        }
        __nv_bfloat16 h, l; split_bf16(w, h, l);
        __nv_bfloat16* th = (__nv_bfloat16*)(g_w2 + d * 4 * 2304 + (part * 2 + 0) * 2304);
        __nv_bfloat16* tl = (__nv_bfloat16*)(g_w2 + d * 4 * 2304 + (part * 2 + 1) * 2304);
        th[n * 72 + k] = h;
        tl[n * 72 + k] = l;
    } else if (idx < T1 + T2 + T3) {
        int i3 = idx - T1 - T2;
        int k = i3 % 72, n = i3 / 72;   // n in [0,128)
        float w = (k < 64) ? Wd[k * 128 + n] : 0.f;
        __nv_bfloat16 h, l; split_bf16(w, h, l);
        ((__nv_bfloat16*)g_wd)[n * 72 + k] = h;
        ((__nv_bfloat16*)(g_wd + 4608))[n * 72 + k] = l;
    }
}

// ================= staging helpers (atom-PAIR batched for 2x MLP) =============
// ---- F=75 paths (scalar loads) ----
template <int F, int D>
__device__ __forceinline__ void stage_sum(
    const float* __restrict__ feat, const int* __restrict__ s_adj,
    __nv_bfloat16* s_xhb, __nv_bfloat16* s_xlb, int warp, int lane, int nat)
{
    constexpr int KP  = gc_kp(F);
    constexpr int RS2 = 2 * gc_rsw(F);
    constexpr int NK  = (KP + 31) / 32;
    #pragma unroll 1
    for (int a0 = warp; a0 < 64; a0 += 16) {
        int as[2] = {a0, a0 + 8};
        bool act[2];
        int nb[2][D];
        #pragma unroll
        for (int p = 0; p < 2; p++) {
            act[p] = as[p] < nat;
            #pragma unroll
            for (int m = 0; m < D; m++)
                nb[p][m] = act[p] ? s_adj[as[p] * D + m] : 0;
        }
        float x[2][NK][D];
        #pragma unroll
        for (int p = 0; p < 2; p++) {
            #pragma unroll
            for (int kk = 0; kk < NK; kk++) {
                int k = lane + kk * 32;
                bool ok = act[p] && k < F;
                #pragma unroll
                for (int m = 0; m < D; m++)
                    x[p][kk][m] = ok ? feat[(size_t)nb[p][m] * F + k] : 0.f;
            }
        }
        #pragma unroll
        for (int p = 0; p < 2; p++) {
            #pragma unroll
            for (int kk = 0; kk < NK; kk++) {
                int k = lane + kk * 32;
                if (k < KP) {
                    float v = 0.f;
                    #pragma unroll
                    for (int m = 0; m < D; m++) v += x[p][kk][m];
                    __nv_bfloat16 h, l; split_bf16(v, h, l);
                    s_xhb[as[p] * RS2 + k] = h;
                    s_xlb[as[p] * RS2 + k] = l;
                }
            }
        }
    }
}

template <int F>
__device__ __forceinline__ void stage_self(
    const float* __restrict__ feat,
    __nv_bfloat16* s_xhb, __nv_bfloat16* s_xlb,
    int atom0, int abase, int warp, int lane, int nat)
{
    constexpr int KP  = gc_kp(F);
    constexpr int RS2 = 2 * gc_rsw(F);
    constexpr int NK  = (KP + 31) / 32;
    #pragma unroll 1
    for (int a0 = warp; a0 < 64; a0 += 16) {
        int as[2] = {a0, a0 + 8};
        float x[2][NK];
        #pragma unroll
        for (int p = 0; p < 2; p++) {
            const float* row = feat + (size_t)(atom0 + abase + as[p]) * F;
            const bool act = as[p] < nat;
            #pragma unroll
            for (int kk = 0; kk < NK; kk++) {
                int k = lane + kk * 32;
                x[p][kk] = (act && k < F) ? row[k] : 0.f;
            }
        }
        #pragma unroll
        for (int p = 0; p < 2; p++) {
            #pragma unroll
            for (int kk = 0; kk < NK; kk++) {
                int k = lane + kk * 32;
                if (k < KP) {
                    __nv_bfloat16 h, l; split_bf16(x[p][kk], h, l);
                    s_xhb[as[p] * RS2 + k] = h;
                    s_xlb[as[p] * RS2 + k] = l;
                }
            }
        }
    }
}

// ---- F=64 paths (float2 loads, packed 32-bit stores) ----
__device__ __forceinline__ void stage_self64(
    const float* __restrict__ feat, uint32_t* s_xh, uint32_t* s_xl,
    int atom0, int abase, int warp, int lane, int nat)
{
    #pragma unroll 1
    for (int a0 = warp; a0 < 64; a0 += 16) {
        int as[2] = {a0, a0 + 8};
        float2 u[2];
        #pragma unroll
        for (int p = 0; p < 2; p++)
            u[p] = (as[p] < nat)
                 ? *(const float2*)(feat + (size_t)(atom0 + abase + as[p]) * 64 + 2 * lane)
                 : make_float2(0.f, 0.f);
        #pragma unroll
        for (int p = 0; p < 2; p++) {
            uint32_t hi, lo; split2(u[p].x, u[p].y, hi, lo);
            s_xh[as[p] * 36 + lane] = hi;
            s_xl[as[p] * 36 + lane] = lo;
        }
    }
}

template <int D>
__device__ __forceinline__ void stage_sum64(
    const float* __restrict__ feat, const int* __restrict__ s_adj,
    uint32_t* s_xh, uint32_t* s_xl, int warp, int lane, int nat)
{
    #pragma unroll 1
    for (int a0 = warp; a0 < 64; a0 += 16) {
        int as[2] = {a0, a0 + 8};
        bool act[2];
        int nb[2][D];
        #pragma unroll
        for (int p = 0; p < 2; p++) {
            act[p] = as[p] < nat;
            #pragma unroll
            for (int m = 0; m < D; m++)
                nb[p][m] = act[p] ? s_adj[as[p] * D + m] : 0;
        }
        float2 x[2][D];
        #pragma unroll
        for (int p = 0; p < 2; p++)
            #pragma unroll
            for (int m = 0; m < D; m++)
                x[p][m] = act[p]
                        ? *(const float2*)(feat + (size_t)nb[p][m] * 64 + 2 * lane)
                        : make_float2(0.f, 0.f);
        #pragma unroll
        for (int p = 0; p < 2; p++) {
            float v0 = 0.f, v1 = 0.f;
            #pragma unroll
            for (int m = 0; m < D; m++) { v0 += x[p][m].x; v1 += x[p][m].y; }
            uint32_t hi, lo; split2(v0, v1, hi, lo);
            s_xh[as[p] * 36 + lane] = hi;
            s_xl[as[p] * 36 + lane] = lo;
        }
    }
}

// pooled staging for dense1: X = max(self, neighbors), float2 + packed stores
template <int D>
__device__ __forceinline__ void stage_pool(
    const float* __restrict__ feat, const int* __restrict__ s_adj,
    uint32_t* s_xh, uint32_t* s_xl,
    int atom0, int abase, int warp, int lane, int nat)
{
    constexpr int DD = (D > 0) ? D : 1;
    #pragma unroll 1
    for (int a0 = warp; a0 < 64; a0 += 16) {
        int as[2] = {a0, a0 + 8};
        bool act[2];
        int nb[2][DD];
        #pragma unroll
        for (int p = 0; p < 2; p++) {
            act[p] = as[p] < nat;
            #pragma unroll
            for (int m = 0; m < DD; m++)
                nb[p][m] = (D > 0 && act[p]) ? s_adj[as[p] * D + m] : 0;
        }
        float2 s[2];
        #pragma unroll
        for (int p = 0; p < 2; p++)
            s[p] = act[p]
                 ? *(const float2*)(feat + (size_t)(atom0 + abase + as[p]) * 64 + 2 * lane)
                 : make_float2(0.f, 0.f);
        if (D > 0) {
            float2 x[2][DD];
            #pragma unroll
            for (int p = 0; p < 2; p++)
                #pragma unroll
                for (int m = 0; m < D; m++)
                    x[p][m] = act[p]
                            ? *(const float2*)(feat + (size_t)nb[p][m] * 64 + 2 * lane)
                            : make_float2(0.f, 0.f);
            #pragma unroll
            for (int p = 0; p < 2; p++)
                #pragma unroll
                for (int m = 0; m < D; m++) {
                    s[p].x = fmaxf(s[p].x, x[p][m].x);
                    s[p].y = fmaxf(s[p].y, x[p][m].y);
                }
        }
        #pragma unroll
        for (int p = 0; p < 2; p++) {
            uint32_t hi, lo; split2(s[p].x, s[p].y, hi, lo);
            s_xh[as[p] * 36 + lane] = hi;
            s_xl[as[p] * 36 + lane] = lo;
        }
    }
}

// ================= merged graph conv (all degrees, one launch) =======================
template <int F>
__global__ __launch_bounds__(256, F == 75 ? 4 : 5) void gc_mma_all(
    const float* __restrict__ feat,
    const int* __restrict__ a1, const int* __restrict__ a2, const int* __restrict__ a3,
    const int* __restrict__ a4, const int* __restrict__ a5, const int* __restrict__ a6,
    const float* __restrict__ gc_b,   // [7][64]
    const float* __restrict__ bn_g, const float* __restrict__ bn_b,
    const float* __restrict__ bn_m, const float* __restrict__ bn_v,
    float* __restrict__ out)
{
    constexpr int KP   = gc_kp(F);
    constexpr int RSW  = gc_rsw(F);
    constexpr int TILE = gc_tile(F);
    constexpr int OFFS[8] = {0, 20000, 100000, 250000, 400000, 475000, 495000, 500000};
    constexpr int BOFF[8] = {0, 313, 1563, 3907, 6251, 7423, 7736, 7815};

    extern __shared__ uint32_t smem[];
    uint32_t* s_wh = smem;
    uint32_t* s_wl = smem + TILE;
    uint32_t* s_xh = smem + 2 * TILE;
    uint32_t* s_xl = smem + 3 * TILE;
    int*   s_adj = (int*)(smem + 4 * TILE);
    float* s_sc  = (float*)(s_adj + 64 * 6);
    float* s_sh  = s_sc + 64;
    __nv_bfloat16* s_xhb = (__nv_bfloat16*)s_xh;
    __nv_bfloat16* s_xlb = (__nv_bfloat16*)s_xl;

    const int t = threadIdx.x;
    const int lane = t & 31;
    const int warp = t >> 5;

    int d = 0;
    #pragma unroll
    for (int i = 1; i < 7; i++) if ((int)blockIdx.x >= BOFF[i]) d = i;
    const int lblk  = blockIdx.x - BOFF[d];
    const int atom0 = OFFS[d];
    const int cnt   = OFFS[d + 1] - OFFS[d];
    const int abase = lblk * 64;
    const int nat   = min(64, cnt - abase);
    const int* adj = (d == 1) ? a1 : (d == 2) ? a2 : (d == 3) ? a3 :
                     (d == 4) ? a4 : (d == 5) ? a5 : (d == 6) ? a6 : nullptr;
    const uint32_t* wbase = (F == 75 ? g_w1 : g_w2) + d * 4 * TILE;
    const float* bias = gc_b + d * 64;

    if (t < 64) {
        float sc = bn_g[t] * rsqrtf(bn_v[t] + 1e-3f);
        s_sc[t] = sc;
        s_sh[t] = bn_b[t] - bn_m[t] * sc;
    }
    if (d > 0)
        for (int u = t; u < nat * d; u += 256)
            s_adj[u] = adj[abase * d + u];

    // ---- pass 0: W = Ws tiles (uint4 copy), X = self ----
    {
        const uint4* src = (const uint4*)wbase;
        uint4* dh = (uint4*)s_wh;
        uint4* dl = (uint4*)s_wl;
        #pragma unroll 2
        for (int i = t; i < TILE / 4; i += 256) {
            dh[i] = src[i];
            dl[i] = src[i + TILE / 4];
        }
    }
    if constexpr (F == 64)
        stage_self64(feat, s_xh, s_xl, atom0, abase, warp, lane, nat);
    else
        stage_self<F>(feat, s_xhb, s_xlb, atom0, abase, warp, lane, nat);
    __syncthreads();

    const int g   = lane >> 2;
    const int tIG = lane & 3;
    const int c0  = (warp & 1) * 32;
    const int row0 = (warp >> 1) * 16 + g;
    const int row1 = row0 + 8;

    float c[4][4];
    #pragma unroll
    for (int nt = 0; nt < 4; nt++) {
        float2 bb = *(const float2*)(bias + c0 + nt * 8 + tIG * 2);
        c[nt][0] = bb.x; c[nt][1] = bb.y; c[nt][2] = bb.x; c[nt][3] = bb.y;
    }

    #pragma unroll
    for (int ks = 0; ks < KP / 16; ks++) {
        const int koff = ks * 8 + tIG;
        uint32_t a0h = s_xh[row0 * RSW + koff];
        uint32_t a1h = s_xh[row1 * RSW + koff];
        uint32_t a2h = s_xh[row0 * RSW + koff + 4];
        uint32_t a3h = s_xh[row1 * RSW + koff + 4];
        uint32_t a0l = s_xl[row0 * RSW + koff];
        uint32_t a1l = s_xl[row1 * RSW + koff];
        uint32_t a2l = s_xl[row0 * RSW + koff + 4];
        uint32_t a3l = s_xl[row1 * RSW + koff + 4];
        #pragma unroll
        for (int nt = 0; nt < 4; nt++) {
            const int n = c0 + nt * 8 + g;
            uint32_t b0h = s_wh[n * RSW + koff];
            uint32_t b1h = s_wh[n * RSW + koff + 4];
            uint32_t b0l = s_wl[n * RSW + koff];
            uint32_t b1l = s_wl[n * RSW + koff + 4];
            MMA_BF16(c[nt][0], c[nt][1], c[nt][2], c[nt][3],
                     a0h, a1h, a2h, a3h, b0h, b1h);
            MMA_BF16(c[nt][0], c[nt][1], c[nt][2], c[nt][3],
                     a0h, a1h, a2h, a3h, b0l, b1l);
            MMA_BF16(c[nt][0], c[nt][1], c[nt][2], c[nt][3],
                     a0l, a1l, a2l, a3l, b0h, b1h);
        }
    }

    // ---- pass 1: W = Wn tiles, X = neighbor sums ----
    if (d > 0) {
        __syncthreads();
        {
            const uint4* src = (const uint4*)(wbase + 2 * TILE);
            uint4* dh = (uint4*)s_wh;
            uint4* dl = (uint4*)s_wl;
            #pragma unroll 2
            for (int i = t; i < TILE / 4; i += 256) {
                dh[i] = src[i];
                dl[i] = src[i + TILE / 4];
            }
        }
        if constexpr (F == 64) {
            switch (d) {
            case 1: stage_sum64<1>(feat, s_adj, s_xh, s_xl, warp, lane, nat); break;
            case 2: stage_sum64<2>(feat, s_adj, s_xh, s_xl, warp, lane, nat); break;
            case 3: stage_sum64<3>(feat, s_adj, s_xh, s_xl, warp, lane, nat); break;
            case 4: stage_sum64<4>(feat, s_adj, s_xh, s_xl, warp, lane, nat); break;
            case 5: stage_sum64<5>(feat, s_adj, s_xh, s_xl, warp, lane, nat); break;
            case 6: stage_sum64<6>(feat, s_adj, s_xh, s_xl, warp, lane, nat); break;
            }
        } else {
            switch (d) {
            case 1: stage_sum<F,1>(feat, s_adj, s_xhb, s_xlb, warp, lane, nat); break;
            case 2: stage_sum<F,2>(feat, s_adj, s_xhb, s_xlb, warp, lane, nat); break;
            case 3: stage_sum<F,3>(feat, s_adj, s_xhb, s_xlb, warp, lane, nat); break;
            case 4: stage_sum<F,4>(feat, s_adj, s_xhb, s_xlb, warp, lane, nat); break;
            case 5: stage_sum<F,5>(feat, s_adj, s_xhb, s_xlb, warp, lane, nat); break;
            case 6: stage_sum<F,6>(feat, s_adj, s_xhb, s_xlb, warp, lane, nat); break;
            }
        }
        __syncthreads();

        #pragma unroll
        for (int ks = 0; ks < KP / 16; ks++) {
            const int koff = ks * 8 + tIG;
            uint32_t a0h = s_xh[row0 * RSW + koff];
            uint32_t a1h = s_xh[row1 * RSW + koff];
            uint32_t a2h = s_xh[row0 * RSW + koff + 4];
            uint32_t a3h = s_xh[row1 * RSW + koff + 4];
            uint32_t a0l = s_xl[row0 * RSW + koff];
            uint32_t a1l = s_xl[row1 * RSW + koff];
            uint32_t a2l = s_xl[row0 * RSW + koff + 4];
            uint32_t a3l = s_xl[row1 * RSW + koff + 4];
            #pragma unroll
            for (int nt = 0; nt < 4; nt++) {
                const int n = c0 + nt * 8 + g;
                uint32_t b0h = s_wh[n * RSW + koff];
                uint32_t b1h = s_wh[n * RSW + koff + 4];
                uint32_t b0l = s_wl[n * RSW + koff];
                uint32_t b1l = s_wl[n * RSW + koff + 4];
                MMA_BF16(c[nt][0], c[nt][1], c[nt][2], c[nt][3],
                         a0h, a1h, a2h, a3h, b0h, b1h);
                MMA_BF16(c[nt][0], c[nt][1], c[nt][2], c[nt][3],
                         a0h, a1h, a2h, a3h, b0l, b1l);
                MMA_BF16(c[nt][0], c[nt][1], c[nt][2], c[nt][3],
                         a0l, a1l, a2l, a3l, b0h, b1h);
            }
        }
    }

    // ---- epilogue: tanh + bn + store ----
    #pragma unroll
    for (int nt = 0; nt < 4; nt++) {
        const int n = c0 + nt * 8 + tIG * 2;
        float2 sc2 = *(const float2*)(s_sc + n);
        float2 sh2 = *(const float2*)(s_sh + n);
        if (row0 < nat) {
            float2 o;
            o.x = sc2.x * tanh_fast(c[nt][0]) + sh2.x;
            o.y = sc2.y * tanh_fast(c[nt][1]) + sh2.y;
            *(float2*)(out + (size_t)(atom0 + abase + row0) * 64 + n) = o;
        }
        if (row1 < nat) {
            float2 o;
            o.x = sc2.x * tanh_fast(c[nt][2]) + sh2.x;
            o.y = sc2.y * tanh_fast(c[nt][3]) + sh2.y;
            *(float2*)(out + (size_t)(atom0 + abase + row1) * 64 + n) = o;
        }
    }
}

// ================= graph pool (float4) =================
__global__ __launch_bounds__(256) void pool_kernel(
    const float4* __restrict__ in, float4* __restrict__ out,
    const int* __restrict__ a1, const int* __restrict__ a2,
    const int* __restrict__ a3, const int* __restrict__ a4,
    const int* __restrict__ a5, const int* __restrict__ a6)
{
    int idx  = blockIdx.x * 256 + threadIdx.x;  // NA*16 total
    int atom = idx >> 4;
    int q    = idx & 15;
    float4 v = in[idx];

    if (atom >= 20000) {
        const int* ap; int d, li;
        if      (atom < 100000) { d = 1; ap = a1; li = atom - 20000;  }
        else if (atom < 250000) { d = 2; ap = a2; li = atom - 100000; }
        else if (atom < 400000) { d = 3; ap = a3; li = atom - 250000; }
        else if (atom < 475000) { d = 4; ap = a4; li = atom - 400000; }
        else if (atom < 495000) { d = 5; ap = a5; li = atom - 475000; }
        else                    { d = 6; ap = a6; li = atom - 495000; }
        for (int m = 0; m < d; m++) {
            int nb = ap[li * d + m];
            float4 u = in[nb * 16 + q];
            v.x = fmaxf(v.x, u.x); v.y = fmaxf(v.y, u.y);
            v.z = fmaxf(v.z, u.z); v.w = fmaxf(v.w, u.w);
        }
    }
    out[idx] = v;
}

// ====== fused pool2 + dense1 [64]->[128] via mma (+tanh +bn3) + segment gather ======
__global__ __launch_bounds__(256) void d1_mma_all(
    const float* __restrict__ feat,   // h1 (gc2 output)
    const int* __restrict__ a1, const int* __restrict__ a2, const int* __restrict__ a3,
    const int* __restrict__ a4, const int* __restrict__ a5, const int* __restrict__ a6,
    const int* __restrict__ membership,
    const float* __restrict__ b,      // [128]
    const float* __restrict__ bn_g, const float* __restrict__ bn_b,
    const float* __restrict__ bn_m, const float* __restrict__ bn_v,
    float* __restrict__ gsum, unsigned* __restrict__ gmax)
{
    constexpr int RSW = 36;
    constexpr int XT  = 64 * RSW;     // 2304
    constexpr int WT  = 128 * RSW;    // 4608
    constexpr int OFFS[8] = {0, 20000, 100000, 250000, 400000, 475000, 495000, 500000};
    constexpr int BOFF[8] = {0, 313, 1563, 3907, 6251, 7423, 7736, 7815};

    extern __shared__ uint32_t smem[];
    uint32_t* s_wh = smem;
    uint32_t* s_wl = smem + WT;
    uint32_t* s_xh = smem + 2 * WT;
    uint32_t* s_xl = smem + 2 * WT + XT;
    int*   s_adj = (int*)(smem + 2 * WT + 2 * XT);
    int*   s_mem = s_adj + 64 * 6;
    float* s_sc  = (float*)(s_mem + 64);
    float* s_sh  = s_sc + 128;

    const int t = threadIdx.x;
    const int lane = t & 31;
    const int warp = t >> 5;

    int d = 0;
    #pragma unroll
    for (int i = 1; i < 7; i++) if ((int)blockIdx.x >= BOFF[i]) d = i;
    const int lblk  = blockIdx.x - BOFF[d];
    const int atom0 = OFFS[d];
    const int cnt   = OFFS[d + 1] - OFFS[d];
    const int abase = lblk * 64;
    const int nat   = min(64, cnt - abase);
    const int* adj = (d == 1) ? a1 : (d == 2) ? a2 : (d == 3) ? a3 :
                     (d == 4) ? a4 : (d == 5) ? a5 : (d == 6) ? a6 : nullptr;

    if (t < 128) {
        float sc = bn_g[t] * rsqrtf(bn_v[t] + 1e-3f);
        s_sc[t] = sc;
        s_sh[t] = bn_b[t] - bn_m[t] * sc;
    }
    if (t < nat) s_mem[t] = membership[atom0 + abase + t];
    if (d > 0)
        for (int u = t; u < nat * d; u += 256)
            s_adj[u] = adj[abase * d + u];

    // W tiles (uint4 copy from precomputed)
    {
        const uint4* src = (const uint4*)g_wd;
        uint4* dh = (uint4*)s_wh;
        uint4* dl = (uint4*)s_wl;
        #pragma unroll 2
        for (int i = t; i < WT / 4; i += 256) {
            dh[i] = src[i];
            dl[i] = src[i + WT / 4];
        }
    }

    // BARRIER: s_adj/s_mem/sc/sh fully written before stage_pool reads them.
    __syncthreads();

    switch (d) {
    case 0: stage_pool<0>(feat, s_adj, s_xh, s_xl, atom0, abase, warp, lane, nat); break;
    case 1: stage_pool<1>(feat, s_adj, s_xh, s_xl, atom0, abase, warp, lane, nat); break;
    case 2: stage_pool<2>(feat, s_adj, s_xh, s_xl, atom0, abase, warp, lane, nat); break;
    case 3: stage_pool<3>(feat, s_adj, s_xh, s_xl, atom0, abase, warp, lane, nat); break;
    case 4: stage_pool<4>(feat, s_adj, s_xh, s_xl, atom0, abase, warp, lane, nat); break;
    case 5: stage_pool<5>(feat, s_adj, s_xh, s_xl, atom0, abase, warp, lane, nat); break;
    case 6: stage_pool<6>(feat, s_adj, s_xh, s_xl, atom0, abase, warp, lane, nat); break;
    }
    __syncthreads();

    const int g   = lane >> 2;
    const int tIG = lane & 3;
    const int c0  = (warp & 1) * 64;
    const int row0 = (warp >> 1) * 16 + g;
    const int row1 = row0 + 8;

    float c[8][4];
    #pragma unroll
    for (int nt = 0; nt < 8; nt++) {
        float2 bb = *(const float2*)(b + c0 + nt * 8 + tIG * 2);
        c[nt][0] = bb.x; c[nt][1] = bb.y; c[nt][2] = bb.x; c[nt][3] = bb.y;
    }

    #pragma unroll
    for (int ks = 0; ks < 4; ks++) {
        const int koff = ks * 8 + tIG;
        uint32_t a0h = s_xh[row0 * RSW + koff];
        uint32_t a1h = s_xh[row1 * RSW + koff];
        uint32_t a2h = s_xh[row0 * RSW + koff + 4];
        uint32_t a3h = s_xh[row1 * RSW + koff + 4];
        uint32_t a0l = s_xl[row0 * RSW + koff];
        uint32_t a1l = s_xl[row1 * RSW + koff];
        uint32_t a2l = s_xl[row0 * RSW + koff + 4];
        uint32_t a3l = s_xl[row1 * RSW + koff + 4];
        #pragma unroll
        for (int nt = 0; nt < 8; nt++) {
            const int n = c0 + nt * 8 + g;
            uint32_t b0h = s_wh[n * RSW + koff];
            uint32_t b1h = s_wh[n * RSW + koff + 4];
            uint32_t b0l = s_wl[n * RSW + koff];
            uint32_t b1l = s_wl[n * RSW + koff + 4];
            MMA_BF16(c[nt][0], c[nt][1], c[nt][2], c[nt][3],
                     a0h, a1h, a2h, a3h, b0h, b1h);
            MMA_BF16(c[nt][0], c[nt][1], c[nt][2], c[nt][3],
                     a0h, a1h, a2h, a3h, b0l, b1l);
            MMA_BF16(c[nt][0], c[nt][1], c[nt][2], c[nt][3],
                     a0l, a1l, a2l, a3l, b0h, b1h);
        }
    }

    // epilogue: tanh + bn, then atomic segment sum/max
    const int m0 = (row0 < nat) ? s_mem[row0] : 0;
    const int m1 = (row1 < nat) ? s_mem[row1] : 0;
    #pragma unroll
    for (int nt = 0; nt < 8; nt++) {
        const int n = c0 + nt * 8 + tIG * 2;
        float2 sc2 = *(const float2*)(s_sc + n);
        float2 sh2 = *(const float2*)(s_sh + n);
        if (row0 < nat) {
            float v0 = sc2.x * tanh_fast(c[nt][0]) + sh2.x;
            float v1 = sc2.y * tanh_fast(c[nt][1]) + sh2.y;
            atomicAdd(&gsum[m0 * 128 + n], v0);
            atomicAdd(&gsum[m0 * 128 + n + 1], v1);
            atomicMax(&gmax[m0 * 128 + n], enc_f(v0));
            atomicMax(&gmax[m0 * 128 + n + 1], enc_f(v1));
        }
        if (row1 < nat) {
            float v0 = sc2.x * tanh_fast(c[nt][2]) + sh2.x;
            float v1 = sc2.y * tanh_fast(c[nt][3]) + sh2.y;
            atomicAdd(&gsum[m1 * 128 + n], v0);
            atomicAdd(&gsum[m1 * 128 + n + 1], v1);
            atomicMax(&gmax[m1 * 128 + n], enc_f(v0));
            atomicMax(&gmax[m1 * 128 + n + 1], enc_f(v1));
        }
    }
}

// ================= head =================
__global__ void head_kernel(const float* __restrict__ gsum, const unsigned* __restrict__ gmax,
                            const float* __restrict__ d2W, const float* __restrict__ d2b,
                            const float* __restrict__ d3W, const float* __restrict__ d3b,
                            float* __restrict__ out)
{
    __shared__ float sg[256];
    __shared__ float sred[64];
    const int row = blockIdx.x;
    const int t   = threadIdx.x;  // 64 threads

    for (int k = t; k < 256; k += 64) {
        float v = (k < 128) ? gsum[row * 128 + k] : dec_f(gmax[row * 128 + (k - 128)]);
        sg[k] = tanh_fast(v);
    }
    __syncthreads();

    float acc = d2b[t];
    for (int k = 0; k < 256; k++)
        acc = fmaf(sg[k], d2W[k * 64 + t], acc);
    float s = 1.f / (1.f + expf(-acc));

    sred[t] = s * d3W[t];
    __syncthreads();
    if (t < 32) {
        float x = sred[t] + sred[t + 32];
        #pragma unroll
        for (int off = 16; off; off >>= 1)
            x += __shfl_down_sync(0xffffffffu, x, off);
        if (t == 0) out[row] = x + d3b[0];
    }
}

// ================= launch =================
extern "C" void kernel_launch(void* const* d_in, const int* in_sizes, int n_in,
                              void* d_out, int out_size)
{
    const float* feat       = (const float*)d_in[0];
    const int*   membership = (const int*)d_in[1];
    const int*   adj[6]     = {(const int*)d_in[2], (const int*)d_in[3], (const int*)d_in[4],
                               (const int*)d_in[5], (const int*)d_in[6], (const int*)d_in[7]};
    const float* gc1_Wn = (const float*)d_in[8];
    const float* gc1_Ws = (const float*)d_in[9];
    const float* gc1_b  = (const float*)d_in[10];
    const float* gc2_Wn = (const float*)d_in[11];
    const float* gc2_Ws = (const float*)d_in[12];
    const float* gc2_b  = (const float*)d_in[13];
    const float* bn1g = (const float*)d_in[14];
    const float* bn1b = (const float*)d_in[15];
    const float* bn1m = (const float*)d_in[16];
    const float* bn1v = (const float*)d_in[17];
    const float* bn3g = (const float*)d_in[18];
    const float* bn3b = (const float*)d_in[19];
    const float* bn3m = (const float*)d_in[20];
    const float* bn3v = (const float*)d_in[21];
    const float* d1W = (const float*)d_in[22];
    const float* d1b = (const float*)d_in[23];
    const float* d2W = (const float*)d_in[24];
    const float* d2b = (const float*)d_in[25];
    const float* d3W = (const float*)d_in[26];
    const float* d3b = (const float*)d_in[27];

    float *h1, *h2, *gsum; unsigned* gmax;
    cudaGetSymbolAddress((void**)&h1, g_h1);
    cudaGetSymbolAddress((void**)&h2, g_h2);
    cudaGetSymbolAddress((void**)&gsum, g_gsum);
    cudaGetSymbolAddress((void**)&gmax, g_gmax);

    constexpr int SZ75 = gc_smem_bytes(75);
    constexpr int SZ64 = gc_smem_bytes(64);
    constexpr int SZD1 = d1_smem_bytes();
    static bool attr_set = false;
    if (!attr_set) {
        cudaFuncSetAttribute(gc_mma_all<75>, cudaFuncAttributeMaxDynamicSharedMemorySize, SZ75);
        cudaFuncSetAttribute(gc_mma_all<64>, cudaFuncAttributeMaxDynamicSharedMemorySize, SZ64);
        cudaFuncSetAttribute(d1_mma_all, cudaFuncAttributeMaxDynamicSharedMemorySize, SZD1);
        attr_set = true;
    }

    // ---- weight prep (every call; deterministic) ----
    prep_weights<<<596, 256>>>(gc1_Ws, gc1_Wn, gc2_Ws, gc2_Wn, d1W);

    // ---- gc1 (+tanh +bn1): feat[NA,75] -> h1[NA,64]
    gc_mma_all<75><<<7815, 256, SZ75>>>(feat, adj[0], adj[1], adj[2], adj[3], adj[4], adj[5],
                                        gc1_b, bn1g, bn1b, bn1m, bn1v, h1);

    // ---- pool1: h1 -> h2
    pool_kernel<<<NA * 16 / 256, 256>>>((const float4*)h1, (float4*)h2,
                                        adj[0], adj[1], adj[2], adj[3], adj[4], adj[5]);

    // ---- gc2 (+tanh +bn1): h2[NA,64] -> h1[NA,64]
    gc_mma_all<64><<<7815, 256, SZ64>>>(h2, adj[0], adj[1], adj[2], adj[3], adj[4], adj[5],
                                        gc2_b, bn1g, bn1b, bn1m, bn1v, h1);

    // ---- zero gather accumulators, then fused pool2+dense1(mma)+segment gather
    cudaMemsetAsync(gsum, 0, 1024 * 128 * sizeof(float));
    cudaMemsetAsync(gmax, 0, 1024 * 128 * sizeof(unsigned));
    d1_mma_all<<<7815, 256, SZD1>>>(h1, adj[0], adj[1], adj[2], adj[3], adj[4], adj[5],
                                    membership, d1b, bn3g, bn3b, bn3m, bn3v, gsum, gmax);

    // ---- head
    head_kernel<<<1024, 64>>>(gsum, gmax, d2W, d2b, d3W, d3b, (float*)d_out);
}

// round 16
// speedup vs baseline: 4.5982x; 1.0072x over previous
#include <cuda_runtime.h>
#include <cuda_bf16.h>
#include <cuda_fp16.h>
#include <cstdint>

// ---------------- problem constants ----------------
#define NA 500000

// ---------------- scratch (device globals; no allocation allowed) ----------------
__device__ float    g_h1[(size_t)NA * 64];
__device__ float    g_h2[(size_t)NA * 64];
__device__ float    g_gsum[1024 * 128];
__device__ unsigned g_gmax[1024 * 128];
// precomputed weight tiles (fp16 hi/lo, transposed, smem image)
__device__ uint32_t g_w1[7 * 4 * 2816];   // gc1: RSW=44  [WsH|WsL|WnH|WnL]
__device__ uint32_t g_w2[7 * 4 * 2304];   // gc2: RSW=36
__device__ uint32_t g_wd[2 * 4608];       // dense1: 128 rows x RSW=36, hi|lo

// ---------------- helpers ----------------
__device__ __forceinline__ unsigned enc_f(float f) {
    unsigned u = __float_as_uint(f);
    return (u >> 31) ? ~u : (u | 0x80000000u);
}
__device__ __forceinline__ float dec_f(unsigned u) {
    return (u >> 31) ? __uint_as_float(u & 0x7FFFFFFFu) : __uint_as_float(~u);
}
__device__ __forceinline__ float tanh_fast(float x) {
    float y;
    asm("tanh.approx.f32 %0, %1;" : "=f"(y) : "f"(x));
    return y;
}

// mma.sync m16n8k16 fp16 -> f32 (sm_80+ baseline PTX; HMMA on sm_103)
#define MMA_F16(c0,c1,c2,c3,a0,a1,a2,a3,b0,b1) \
    asm volatile("mma.sync.aligned.m16n8k16.row.col.f32.f16.f16.f32 " \
        "{%0,%1,%2,%3}, {%4,%5,%6,%7}, {%8,%9}, {%0,%1,%2,%3};" \
        : "+f"(c0), "+f"(c1), "+f"(c2), "+f"(c3) \
        : "r"(a0), "r"(a1), "r"(a2), "r"(a3), "r"(b0), "r"(b1))

// fp16 weight split: w = h + l with l the fp16 residual
__device__ __forceinline__ void wsplit_h(float w, __half& h, __half& l) {
    h = __float2half_rn(w);
    l = __float2half_rn(w - __half2float(h));
}
// pack a float pair into one half2 word
__device__ __forceinline__ uint32_t packh2(float v0, float v1) {
    __half2 p = __floats2half2_rn(v0, v1);
    return *(uint32_t*)&p;
}

// ---- geometry ----
__host__ __device__ constexpr int gc_kp(int F)  { return (F == 75) ? 80 : 64; }
__host__ __device__ constexpr int gc_rsw(int F) { return gc_kp(F) / 2 + 4; }   // 44 / 36
__host__ __device__ constexpr int gc_tile(int F) { return 64 * gc_rsw(F); }    // words
__host__ __device__ constexpr int gc_smem_bytes(int F) {
    return 3 * gc_tile(F) * 4 + 64 * 6 * 4 + 2 * 64 * 4;   // Wh,Wl,X + adj + sc/sh
}
// d1 fused kernel smem: Wh,Wl(128x36) + X(64x36) + adj + mem + sc/sh(128)
__host__ __device__ constexpr int d1_smem_bytes() {
    return (2 * 4608 + 2304) * 4 + 64 * 6 * 4 + 64 * 4 + 2 * 128 * 4;
}

// ================= weight prep: fp32 -> transposed fp16 hi/lo tiles =================
__global__ void prep_weights(const float* __restrict__ Ws1, const float* __restrict__ Wn1,
                             const float* __restrict__ Ws2, const float* __restrict__ Wn2,
                             const float* __restrict__ Wd)
{
    const int idx = blockIdx.x * 256 + threadIdx.x;
    constexpr int T1 = 7 * 2 * 64 * 88;   // stage1 fp16 elements (RS2=88)
    constexpr int T2 = 7 * 2 * 64 * 72;   // stage2 (RS2=72)
    constexpr int T3 = 128 * 72;          // dense1 (RS2=72)
    if (idx < T1) {
        int k = idx % 88, n = (idx / 88) & 63, part = (idx / (88 * 64)) & 1, d = idx / (88 * 128);
        float w = 0.f;
        if (k < 75) {
            if (part == 0) w = Ws1[(d * 75 + k) * 64 + n];
            else if (d > 0) w = Wn1[((d - 1) * 75 + k) * 64 + n];
        }
        __half h, l; wsplit_h(w, h, l);
        __half* th = (__half*)(g_w1 + d * 4 * 2816 + (part * 2 + 0) * 2816);
        __half* tl = (__half*)(g_w1 + d * 4 * 2816 + (part * 2 + 1) * 2816);
        th[n * 88 + k] = h;
        tl[n * 88 + k] = l;
    } else if (idx < T1 + T2) {
        int i2 = idx - T1;
        int k = i2 % 72, n = (i2 / 72) & 63, part = (i2 / (72 * 64)) & 1, d = i2 / (72 * 128);
        float w = 0.f;
        if (k < 64) {
            if (part == 0) w = Ws2[(d * 64 + k) * 64 + n];
            else if (d > 0) w = Wn2[((d - 1) * 64 + k) * 64 + n];
        }
        __half h, l; wsplit_h(w, h, l);
        __half* th = (__half*)(g_w2 + d * 4 * 2304 + (part * 2 + 0) * 2304);
        __half* tl = (__half*)(g_w2 + d * 4 * 2304 + (part * 2 + 1) * 2304);
        th[n * 72 + k] = h;
        tl[n * 72 + k] = l;
    } else if (idx < T1 + T2 + T3) {
        int i3 = idx - T1 - T2;
        int k = i3 % 72, n = i3 / 72;   // n in [0,128)
        float w = (k < 64) ? Wd[k * 128 + n] : 0.f;
        __half h, l; wsplit_h(w, h, l);
        ((__half*)g_wd)[n * 72 + k] = h;
        ((__half*)(g_wd + 4608))[n * 72 + k] = l;
    }
}

// ================= staging helpers (atom-PAIR batched, single fp16 X tile) ==========
// ---- F=75 paths (scalar loads) ----
template <int F, int D>
__device__ __forceinline__ void stage_sum(
    const float* __restrict__ feat, const int* __restrict__ s_adj,
    __half* s_xb, int warp, int lane, int nat)
{
    constexpr int KP  = gc_kp(F);
    constexpr int RS2 = 2 * gc_rsw(F);
    constexpr int NK  = (KP + 31) / 32;
    #pragma unroll 1
    for (int a0 = warp; a0 < 64; a0 += 16) {
        int as[2] = {a0, a0 + 8};
        bool act[2];
        int nb[2][D];
        #pragma unroll
        for (int p = 0; p < 2; p++) {
            act[p] = as[p] < nat;
            #pragma unroll
            for (int m = 0; m < D; m++)
                nb[p][m] = act[p] ? s_adj[as[p] * D + m] : 0;
        }
        float x[2][NK][D];
        #pragma unroll
        for (int p = 0; p < 2; p++) {
            #pragma unroll
            for (int kk = 0; kk < NK; kk++) {
                int k = lane + kk * 32;
                bool ok = act[p] && k < F;
                #pragma unroll
                for (int m = 0; m < D; m++)
                    x[p][kk][m] = ok ? feat[(size_t)nb[p][m] * F + k] : 0.f;
            }
        }
        #pragma unroll
        for (int p = 0; p < 2; p++) {
            #pragma unroll
            for (int kk = 0; kk < NK; kk++) {
                int k = lane + kk * 32;
                if (k < KP) {
                    float v = 0.f;
                    #pragma unroll
                    for (int m = 0; m < D; m++) v += x[p][kk][m];
                    s_xb[as[p] * RS2 + k] = __float2half_rn(v);
                }
            }
        }
    }
}

template <int F>
__device__ __forceinline__ void stage_self(
    const float* __restrict__ feat, __half* s_xb,
    int atom0, int abase, int warp, int lane, int nat)
{
    constexpr int KP  = gc_kp(F);
    constexpr int RS2 = 2 * gc_rsw(F);
    constexpr int NK  = (KP + 31) / 32;
    #pragma unroll 1
    for (int a0 = warp; a0 < 64; a0 += 16) {
        int as[2] = {a0, a0 + 8};
        float x[2][NK];
        #pragma unroll
        for (int p = 0; p < 2; p++) {
            const float* row = feat + (size_t)(atom0 + abase + as[p]) * F;
            const bool act = as[p] < nat;
            #pragma unroll
            for (int kk = 0; kk < NK; kk++) {
                int k = lane + kk * 32;
                x[p][kk] = (act && k < F) ? row[k] : 0.f;
            }
        }
        #pragma unroll
        for (int p = 0; p < 2; p++) {
            #pragma unroll
            for (int kk = 0; kk < NK; kk++) {
                int k = lane + kk * 32;
                if (k < KP)
                    s_xb[as[p] * RS2 + k] = __float2half_rn(x[p][kk]);
            }
        }
    }
}

// ---- F=64 paths (float2 loads, packed 32-bit stores) ----
__device__ __forceinline__ void stage_self64(
    const float* __restrict__ feat, uint32_t* s_x,
    int atom0, int abase, int warp, int lane, int nat)
{
    #pragma unroll 1
    for (int a0 = warp; a0 < 64; a0 += 16) {
        int as[2] = {a0, a0 + 8};
        float2 u[2];
        #pragma unroll
        for (int p = 0; p < 2; p++)
            u[p] = (as[p] < nat)
                 ? *(const float2*)(feat + (size_t)(atom0 + abase + as[p]) * 64 + 2 * lane)
                 : make_float2(0.f, 0.f);
        #pragma unroll
        for (int p = 0; p < 2; p++)
            s_x[as[p] * 36 + lane] = packh2(u[p].x, u[p].y);
    }
}

template <int D>
__device__ __forceinline__ void stage_sum64(
    const float* __restrict__ feat, const int* __restrict__ s_adj,
    uint32_t* s_x, int warp, int lane, int nat)
{
    #pragma unroll 1
    for (int a0 = warp; a0 < 64; a0 += 16) {
        int as[2] = {a0, a0 + 8};
        bool act[2];
        int nb[2][D];
        #pragma unroll
        for (int p = 0; p < 2; p++) {
            act[p] = as[p] < nat;
            #pragma unroll
            for (int m = 0; m < D; m++)
                nb[p][m] = act[p] ? s_adj[as[p] * D + m] : 0;
        }
        float2 x[2][D];
        #pragma unroll
        for (int p = 0; p < 2; p++)
            #pragma unroll
            for (int m = 0; m < D; m++)
                x[p][m] = act[p]
                        ? *(const float2*)(feat + (size_t)nb[p][m] * 64 + 2 * lane)
                        : make_float2(0.f, 0.f);
        #pragma unroll
        for (int p = 0; p < 2; p++) {
            float v0 = 0.f, v1 = 0.f;
            #pragma unroll
            for (int m = 0; m < D; m++) { v0 += x[p][m].x; v1 += x[p][m].y; }
            s_x[as[p] * 36 + lane] = packh2(v0, v1);
        }
    }
}

// pooled staging for dense1: X = max(self, neighbors)
template <int D>
__device__ __forceinline__ void stage_pool(
    const float* __restrict__ feat, const int* __restrict__ s_adj,
    uint32_t* s_x, int atom0, int abase, int warp, int lane, int nat)
{
    constexpr int DD = (D > 0) ? D : 1;
    #pragma unroll 1
    for (int a0 = warp; a0 < 64; a0 += 16) {
        int as[2] = {a0, a0 + 8};
        bool act[2];
        int nb[2][DD];
        #pragma unroll
        for (int p = 0; p < 2; p++) {
            act[p] = as[p] < nat;
            #pragma unroll
            for (int m = 0; m < DD; m++)
                nb[p][m] = (D > 0 && act[p]) ? s_adj[as[p] * D + m] : 0;
        }
        float2 s[2];
        #pragma unroll
        for (int p = 0; p < 2; p++)
            s[p] = act[p]
                 ? *(const float2*)(feat + (size_t)(atom0 + abase + as[p]) * 64 + 2 * lane)
                 : make_float2(0.f, 0.f);
        if (D > 0) {
            float2 x[2][DD];
            #pragma unroll
            for (int p = 0; p < 2; p++)
                #pragma unroll
                for (int m = 0; m < D; m++)
                    x[p][m] = act[p]
                            ? *(const float2*)(feat + (size_t)nb[p][m] * 64 + 2 * lane)
                            : make_float2(0.f, 0.f);
            #pragma unroll
            for (int p = 0; p < 2; p++)
                #pragma unroll
                for (int m = 0; m < D; m++) {
                    s[p].x = fmaxf(s[p].x, x[p][m].x);
                    s[p].y = fmaxf(s[p].y, x[p][m].y);
                }
        }
        #pragma unroll
        for (int p = 0; p < 2; p++)
            s_x[as[p] * 36 + lane] = packh2(s[p].x, s[p].y);
    }
}

// ================= merged graph conv (all degrees, one launch) =======================
template <int F>
__global__ __launch_bounds__(256, 6) void gc_mma_all(
    const float* __restrict__ feat,
    const int* __restrict__ a1, const int* __restrict__ a2, const int* __restrict__ a3,
    const int* __restrict__ a4, const int* __restrict__ a5, const int* __restrict__ a6,
    const float* __restrict__ gc_b,   // [7][64]
    const float* __restrict__ bn_g, const float* __restrict__ bn_b,
    const float* __restrict__ bn_m, const float* __restrict__ bn_v,
    float* __restrict__ out)
{
    constexpr int KP   = gc_kp(F);
    constexpr int RSW  = gc_rsw(F);
    constexpr int TILE = gc_tile(F);
    constexpr int OFFS[8] = {0, 20000, 100000, 250000, 400000, 475000, 495000, 500000};
    constexpr int BOFF[8] = {0, 313, 1563, 3907, 6251, 7423, 7736, 7815};

    extern __shared__ uint32_t smem[];
    uint32_t* s_wh = smem;
    uint32_t* s_wl = smem + TILE;
    uint32_t* s_x  = smem + 2 * TILE;
    int*   s_adj = (int*)(smem + 3 * TILE);
    float* s_sc  = (float*)(s_adj + 64 * 6);
    float* s_sh  = s_sc + 64;
    __half* s_xb = (__half*)s_x;

    const int t = threadIdx.x;
    const int lane = t & 31;
    const int warp = t >> 5;

    int d = 0;
    #pragma unroll
    for (int i = 1; i < 7; i++) if ((int)blockIdx.x >= BOFF[i]) d = i;
    const int lblk  = blockIdx.x - BOFF[d];
    const int atom0 = OFFS[d];
    const int cnt   = OFFS[d + 1] - OFFS[d];
    const int abase = lblk * 64;
    const int nat   = min(64, cnt - abase);
    const int* adj = (d == 1) ? a1 : (d == 2) ? a2 : (d == 3) ? a3 :
                     (d == 4) ? a4 : (d == 5) ? a5 : (d == 6) ? a6 : nullptr;
    const uint32_t* wbase = (F == 75 ? g_w1 : g_w2) + d * 4 * TILE;
    const float* bias = gc_b + d * 64;

    if (t < 64) {
        float sc = bn_g[t] * rsqrtf(bn_v[t] + 1e-3f);
        s_sc[t] = sc;
        s_sh[t] = bn_b[t] - bn_m[t] * sc;
    }
    if (d > 0)
        for (int u = t; u < nat * d; u += 256)
            s_adj[u] = adj[abase * d + u];

    // ---- pass 0: W = Ws tiles (uint4 copy), X = self ----
    {
        const uint4* src = (const uint4*)wbase;
        uint4* dh = (uint4*)s_wh;
        uint4* dl = (uint4*)s_wl;
        #pragma unroll 2
        for (int i = t; i < TILE / 4; i += 256) {
            dh[i] = src[i];
            dl[i] = src[i + TILE / 4];
        }
    }
    if constexpr (F == 64)
        stage_self64(feat, s_x, atom0, abase, warp, lane, nat);
    else
        stage_self<F>(feat, s_xb, atom0, abase, warp, lane, nat);
    __syncthreads();

    const int g   = lane >> 2;
    const int tIG = lane & 3;
    const int c0  = (warp & 1) * 32;
    const int row0 = (warp >> 1) * 16 + g;
    const int row1 = row0 + 8;

    float c[4][4];
    #pragma unroll
    for (int nt = 0; nt < 4; nt++) {
        float2 bb = *(const float2*)(bias + c0 + nt * 8 + tIG * 2);
        c[nt][0] = bb.x; c[nt][1] = bb.y; c[nt][2] = bb.x; c[nt][3] = bb.y;
    }

    #pragma unroll
    for (int ks = 0; ks < KP / 16; ks++) {
        const int koff = ks * 8 + tIG;
        uint32_t a0 = s_x[row0 * RSW + koff];
        uint32_t a1 = s_x[row1 * RSW + koff];
        uint32_t a2 = s_x[row0 * RSW + koff + 4];
        uint32_t a3 = s_x[row1 * RSW + koff + 4];
        #pragma unroll
        for (int nt = 0; nt < 4; nt++) {
            const int n = c0 + nt * 8 + g;
            uint32_t b0h = s_wh[n * RSW + koff];
            uint32_t b1h = s_wh[n * RSW + koff + 4];
            uint32_t b0l = s_wl[n * RSW + koff];
            uint32_t b1l = s_wl[n * RSW + koff + 4];
            MMA_F16(c[nt][0], c[nt][1], c[nt][2], c[nt][3],
                    a0, a1, a2, a3, b0h, b1h);
            MMA_F16(c[nt][0], c[nt][1], c[nt][2], c[nt][3],
                    a0, a1, a2, a3, b0l, b1l);
        }
    }

    // ---- pass 1: W = Wn tiles, X = neighbor sums ----
    if (d > 0) {
        __syncthreads();
        {
            const uint4* src = (const uint4*)(wbase + 2 * TILE);
            uint4* dh = (uint4*)s_wh;
            uint4* dl = (uint4*)s_wl;
            #pragma unroll 2
            for (int i = t; i < TILE / 4; i += 256) {
                dh[i] = src[i];
                dl[i] = src[i + TILE / 4];
            }
        }
        if constexpr (F == 64) {
            switch (d) {
            case 1: stage_sum64<1>(feat, s_adj, s_x, warp, lane, nat); break;
            case 2: stage_sum64<2>(feat, s_adj, s_x, warp, lane, nat); break;
            case 3: stage_sum64<3>(feat, s_adj, s_x, warp, lane, nat); break;
            case 4: stage_sum64<4>(feat, s_adj, s_x, warp, lane, nat); break;
            case 5: stage_sum64<5>(feat, s_adj, s_x, warp, lane, nat); break;
            case 6: stage_sum64<6>(feat, s_adj, s_x, warp, lane, nat); break;
            }
        } else {
            switch (d) {
            case 1: stage_sum<F,1>(feat, s_adj, s_xb, warp, lane, nat); break;
            case 2: stage_sum<F,2>(feat, s_adj, s_xb, warp, lane, nat); break;
            case 3: stage_sum<F,3>(feat, s_adj, s_xb, warp, lane, nat); break;
            case 4: stage_sum<F,4>(feat, s_adj, s_xb, warp, lane, nat); break;
            case 5: stage_sum<F,5>(feat, s_adj, s_xb, warp, lane, nat); break;
            case 6: stage_sum<F,6>(feat, s_adj, s_xb, warp, lane, nat); break;
            }
        }
        __syncthreads();

        #pragma unroll
        for (int ks = 0; ks < KP / 16; ks++) {
            const int koff = ks * 8 + tIG;
            uint32_t a0 = s_x[row0 * RSW + koff];
            uint32_t a1 = s_x[row1 * RSW + koff];
            uint32_t a2 = s_x[row0 * RSW + koff + 4];
            uint32_t a3 = s_x[row1 * RSW + koff + 4];
            #pragma unroll
            for (int nt = 0; nt < 4; nt++) {
                const int n = c0 + nt * 8 + g;
                uint32_t b0h = s_wh[n * RSW + koff];
                uint32_t b1h = s_wh[n * RSW + koff + 4];
                uint32_t b0l = s_wl[n * RSW + koff];
                uint32_t b1l = s_wl[n * RSW + koff + 4];
                MMA_F16(c[nt][0], c[nt][1], c[nt][2], c[nt][3],
                        a0, a1, a2, a3, b0h, b1h);
                MMA_F16(c[nt][0], c[nt][1], c[nt][2], c[nt][3],
                        a0, a1, a2, a3, b0l, b1l);
            }
        }
    }

    // ---- epilogue: tanh + bn + store ----
    #pragma unroll
    for (int nt = 0; nt < 4; nt++) {
        const int n = c0 + nt * 8 + tIG * 2;
        float2 sc2 = *(const float2*)(s_sc + n);
        float2 sh2 = *(const float2*)(s_sh + n);
        if (row0 < nat) {
            float2 o;
            o.x = sc2.x * tanh_fast(c[nt][0]) + sh2.x;
            o.y = sc2.y * tanh_fast(c[nt][1]) + sh2.y;
            *(float2*)(out + (size_t)(atom0 + abase + row0) * 64 + n) = o;
        }
        if (row1 < nat) {
            float2 o;
            o.x = sc2.x * tanh_fast(c[nt][2]) + sh2.x;
            o.y = sc2.y * tanh_fast(c[nt][3]) + sh2.y;
            *(float2*)(out + (size_t)(atom0 + abase + row1) * 64 + n) = o;
        }
    }
}

// ================= graph pool (float4) =================
__global__ __launch_bounds__(256) void pool_kernel(
    const float4* __restrict__ in, float4* __restrict__ out,
    const int* __restrict__ a1, const int* __restrict__ a2,
    const int* __restrict__ a3, const int* __restrict__ a4,
    const int* __restrict__ a5, const int* __restrict__ a6)
{
    int idx  = blockIdx.x * 256 + threadIdx.x;  // NA*16 total
    int atom = idx >> 4;
    int q    = idx & 15;
    float4 v = in[idx];

    if (atom >= 20000) {
        const int* ap; int d, li;
        if      (atom < 100000) { d = 1; ap = a1; li = atom - 20000;  }
        else if (atom < 250000) { d = 2; ap = a2; li = atom - 100000; }
        else if (atom < 400000) { d = 3; ap = a3; li = atom - 250000; }
        else if (atom < 475000) { d = 4; ap = a4; li = atom - 400000; }
        else if (atom < 495000) { d = 5; ap = a5; li = atom - 475000; }
        else                    { d = 6; ap = a6; li = atom - 495000; }
        for (int m = 0; m < d; m++) {
            int nb = ap[li * d + m];
            float4 u = in[nb * 16 + q];
            v.x = fmaxf(v.x, u.x); v.y = fmaxf(v.y, u.y);
            v.z = fmaxf(v.z, u.z); v.w = fmaxf(v.w, u.w);
        }
    }
    out[idx] = v;
}

// ====== fused pool2 + dense1 [64]->[128] via mma (+tanh +bn3) + segment gather ======
__global__ __launch_bounds__(256, 4) void d1_mma_all(
    const float* __restrict__ feat,   // h1 (gc2 output)
    const int* __restrict__ a1, const int* __restrict__ a2, const int* __restrict__ a3,
    const int* __restrict__ a4, const int* __restrict__ a5, const int* __restrict__ a6,
    const int* __restrict__ membership,
    const float* __restrict__ b,      // [128]
    const float* __restrict__ bn_g, const float* __restrict__ bn_b,
    const float* __restrict__ bn_m, const float* __restrict__ bn_v,
    float* __restrict__ gsum, unsigned* __restrict__ gmax)
{
    constexpr int RSW = 36;
    constexpr int XT  = 64 * RSW;     // 2304
    constexpr int WT  = 128 * RSW;    // 4608
    constexpr int OFFS[8] = {0, 20000, 100000, 250000, 400000, 475000, 495000, 500000};
    constexpr int BOFF[8] = {0, 313, 1563, 3907, 6251, 7423, 7736, 7815};

    extern __shared__ uint32_t smem[];
    uint32_t* s_wh = smem;
    uint32_t* s_wl = smem + WT;
    uint32_t* s_x  = smem + 2 * WT;
    int*   s_adj = (int*)(smem + 2 * WT + XT);
    int*   s_mem = s_adj + 64 * 6;
    float* s_sc  = (float*)(s_mem + 64);
    float* s_sh  = s_sc + 128;

    const int t = threadIdx.x;
    const int lane = t & 31;
    const int warp = t >> 5;

    int d = 0;
    #pragma unroll
    for (int i = 1; i < 7; i++) if ((int)blockIdx.x >= BOFF[i]) d = i;
    const int lblk  = blockIdx.x - BOFF[d];
    const int atom0 = OFFS[d];
    const int cnt   = OFFS[d + 1] - OFFS[d];
    const int abase = lblk * 64;
    const int nat   = min(64, cnt - abase);
    const int* adj = (d == 1) ? a1 : (d == 2) ? a2 : (d == 3) ? a3 :
                     (d == 4) ? a4 : (d == 5) ? a5 : (d == 6) ? a6 : nullptr;

    if (t < 128) {
        float sc = bn_g[t] * rsqrtf(bn_v[t] + 1e-3f);
        s_sc[t] = sc;
        s_sh[t] = bn_b[t] - bn_m[t] * sc;
    }
    if (t < nat) s_mem[t] = membership[atom0 + abase + t];
    if (d > 0)
        for (int u = t; u < nat * d; u += 256)
            s_adj[u] = adj[abase * d + u];

    // W tiles (uint4 copy from precomputed)
    {
        const uint4* src = (const uint4*)g_wd;
        uint4* dh = (uint4*)s_wh;
        uint4* dl = (uint4*)s_wl;
        #pragma unroll 2
        for (int i = t; i < WT / 4; i += 256) {
            dh[i] = src[i];
            dl[i] = src[i + WT / 4];
        }
    }

    // BARRIER: s_adj/s_mem/sc/sh fully written before stage_pool reads them.
    __syncthreads();

    switch (d) {
    case 0: stage_pool<0>(feat, s_adj, s_x, atom0, abase, warp, lane, nat); break;
    case 1: stage_pool<1>(feat, s_adj, s_x, atom0, abase, warp, lane, nat); break;
    case 2: stage_pool<2>(feat, s_adj, s_x, atom0, abase, warp, lane, nat); break;
    case 3: stage_pool<3>(feat, s_adj, s_x, atom0, abase, warp, lane, nat); break;
    case 4: stage_pool<4>(feat, s_adj, s_x, atom0, abase, warp, lane, nat); break;
    case 5: stage_pool<5>(feat, s_adj, s_x, atom0, abase, warp, lane, nat); break;
    case 6: stage_pool<6>(feat, s_adj, s_x, atom0, abase, warp, lane, nat); break;
    }
    __syncthreads();

    const int g   = lane >> 2;
    const int tIG = lane & 3;
    const int c0  = (warp & 1) * 64;
    const int row0 = (warp >> 1) * 16 + g;
    const int row1 = row0 + 8;

    float c[8][4];
    #pragma unroll
    for (int nt = 0; nt < 8; nt++) {
        float2 bb = *(const float2*)(b + c0 + nt * 8 + tIG * 2);
        c[nt][0] = bb.x; c[nt][1] = bb.y; c[nt][2] = bb.x; c[nt][3] = bb.y;
    }

    #pragma unroll
    for (int ks = 0; ks < 4; ks++) {
        const int koff = ks * 8 + tIG;
        uint32_t a0 = s_x[row0 * RSW + koff];
        uint32_t a1 = s_x[row1 * RSW + koff];
        uint32_t a2 = s_x[row0 * RSW + koff + 4];
        uint32_t a3 = s_x[row1 * RSW + koff + 4];
        #pragma unroll
        for (int nt = 0; nt < 8; nt++) {
            const int n = c0 + nt * 8 + g;
            uint32_t b0h = s_wh[n * RSW + koff];
            uint32_t b1h = s_wh[n * RSW + koff + 4];
            uint32_t b0l = s_wl[n * RSW + koff];
            uint32_t b1l = s_wl[n * RSW + koff + 4];
            MMA_F16(c[nt][0], c[nt][1], c[nt][2], c[nt][3],
                    a0, a1, a2, a3, b0h, b1h);
            MMA_F16(c[nt][0], c[nt][1], c[nt][2], c[nt][3],
                    a0, a1, a2, a3, b0l, b1l);
        }
    }

    // epilogue: tanh + bn, then atomic segment sum/max
    const int m0 = (row0 < nat) ? s_mem[row0] : 0;
    const int m1 = (row1 < nat) ? s_mem[row1] : 0;
    #pragma unroll
    for (int nt = 0; nt < 8; nt++) {
        const int n = c0 + nt * 8 + tIG * 2;
        float2 sc2 = *(const float2*)(s_sc + n);
        float2 sh2 = *(const float2*)(s_sh + n);
        if (row0 < nat) {
            float v0 = sc2.x * tanh_fast(c[nt][0]) + sh2.x;
            float v1 = sc2.y * tanh_fast(c[nt][1]) + sh2.y;
            atomicAdd(&gsum[m0 * 128 + n], v0);
            atomicAdd(&gsum[m0 * 128 + n + 1], v1);
            atomicMax(&gmax[m0 * 128 + n], enc_f(v0));
            atomicMax(&gmax[m0 * 128 + n + 1], enc_f(v1));
        }
        if (row1 < nat) {
            float v0 = sc2.x * tanh_fast(c[nt][2]) + sh2.x;
            float v1 = sc2.y * tanh_fast(c[nt][3]) + sh2.y;
            atomicAdd(&gsum[m1 * 128 + n], v0);
            atomicAdd(&gsum[m1 * 128 + n + 1], v1);
            atomicMax(&gmax[m1 * 128 + n], enc_f(v0));
            atomicMax(&gmax[m1 * 128 + n + 1], enc_f(v1));
        }
    }
}

// ================= head =================
__global__ void head_kernel(const float* __restrict__ gsum, const unsigned* __restrict__ gmax,
                            const float* __restrict__ d2W, const float* __restrict__ d2b,
                            const float* __restrict__ d3W, const float* __restrict__ d3b,
                            float* __restrict__ out)
{
    __shared__ float sg[256];
    __shared__ float sred[64];
    const int row = blockIdx.x;
    const int t   = threadIdx.x;  // 64 threads

    for (int k = t; k < 256; k += 64) {
        float v = (k < 128) ? gsum[row * 128 + k] : dec_f(gmax[row * 128 + (k - 128)]);
        sg[k] = tanh_fast(v);
    }
    __syncthreads();

    float acc = d2b[t];
    for (int k = 0; k < 256; k++)
        acc = fmaf(sg[k], d2W[k * 64 + t], acc);
    float s = 1.f / (1.f + expf(-acc));

    sred[t] = s * d3W[t];
    __syncthreads();
    if (t < 32) {
        float x = sred[t] + sred[t + 32];
        #pragma unroll
        for (int off = 16; off; off >>= 1)
            x += __shfl_down_sync(0xffffffffu, x, off);
        if (t == 0) out[row] = x + d3b[0];
    }
}

// ================= launch =================
extern "C" void kernel_launch(void* const* d_in, const int* in_sizes, int n_in,
                              void* d_out, int out_size)
{
    const float* feat       = (const float*)d_in[0];
    const int*   membership = (const int*)d_in[1];
    const int*   adj[6]     = {(const int*)d_in[2], (const int*)d_in[3], (const int*)d_in[4],
                               (const int*)d_in[5], (const int*)d_in[6], (const int*)d_in[7]};
    const float* gc1_Wn = (const float*)d_in[8];
    const float* gc1_Ws = (const float*)d_in[9];
    const float* gc1_b  = (const float*)d_in[10];
    const float* gc2_Wn = (const float*)d_in[11];
    const float* gc2_Ws = (const float*)d_in[12];
    const float* gc2_b  = (const float*)d_in[13];
    const float* bn1g = (const float*)d_in[14];
    const float* bn1b = (const float*)d_in[15];
    const float* bn1m = (const float*)d_in[16];
    const float* bn1v = (const float*)d_in[17];
    const float* bn3g = (const float*)d_in[18];
    const float* bn3b = (const float*)d_in[19];
    const float* bn3m = (const float*)d_in[20];
    const float* bn3v = (const float*)d_in[21];
    const float* d1W = (const float*)d_in[22];
    const float* d1b = (const float*)d_in[23];
    const float* d2W = (const float*)d_in[24];
    const float* d2b = (const float*)d_in[25];
    const float* d3W = (const float*)d_in[26];
    const float* d3b = (const float*)d_in[27];

    float *h1, *h2, *gsum; unsigned* gmax;
    cudaGetSymbolAddress((void**)&h1, g_h1);
    cudaGetSymbolAddress((void**)&h2, g_h2);
    cudaGetSymbolAddress((void**)&gsum, g_gsum);
    cudaGetSymbolAddress((void**)&gmax, g_gmax);

    constexpr int SZ75 = gc_smem_bytes(75);
    constexpr int SZ64 = gc_smem_bytes(64);
    constexpr int SZD1 = d1_smem_bytes();
    static bool attr_set = false;
    if (!attr_set) {
        cudaFuncSetAttribute(gc_mma_all<75>, cudaFuncAttributeMaxDynamicSharedMemorySize, SZ75);
        cudaFuncSetAttribute(gc_mma_all<64>, cudaFuncAttributeMaxDynamicSharedMemorySize, SZ64);
        cudaFuncSetAttribute(d1_mma_all, cudaFuncAttributeMaxDynamicSharedMemorySize, SZD1);
        attr_set = true;
    }

    // ---- weight prep (every call; deterministic) ----
    prep_weights<<<596, 256>>>(gc1_Ws, gc1_Wn, gc2_Ws, gc2_Wn, d1W);

    // ---- gc1 (+tanh +bn1): feat[NA,75] -> h1[NA,64]
    gc_mma_all<75><<<7815, 256, SZ75>>>(feat, adj[0], adj[1], adj[2], adj[3], adj[4], adj[5],
                                        gc1_b, bn1g, bn1b, bn1m, bn1v, h1);

    // ---- pool1: h1 -> h2
    pool_kernel<<<NA * 16 / 256, 256>>>((const float4*)h1, (float4*)h2,
                                        adj[0], adj[1], adj[2], adj[3], adj[4], adj[5]);

    // ---- gc2 (+tanh +bn1): h2[NA,64] -> h1[NA,64]
    gc_mma_all<64><<<7815, 256, SZ64>>>(h2, adj[0], adj[1], adj[2], adj[3], adj[4], adj[5],
                                        gc2_b, bn1g, bn1b, bn1m, bn1v, h1);

    // ---- zero gather accumulators, then fused pool2+dense1(mma)+segment gather
    cudaMemsetAsync(gsum, 0, 1024 * 128 * sizeof(float));
    cudaMemsetAsync(gmax, 0, 1024 * 128 * sizeof(unsigned));
    d1_mma_all<<<7815, 256, SZD1>>>(h1, adj[0], adj[1], adj[2], adj[3], adj[4], adj[5],
                                    membership, d1b, bn3g, bn3b, bn3m, bn3v, gsum, gmax);

    // ---- head
    head_kernel<<<1024, 64>>>(gsum, gmax, d2W, d2b, d3W, d3b, (float*)d_out);
}